// round 3
// baseline (speedup 1.0000x reference)
#include <cuda_runtime.h>

typedef unsigned long long ull_t;

#define N_ROWS 12288
#define Z_D 128
#define H_D 256
#define N_STEPS 8
#define DT_F 0.125f
#define P_ODE 97
#define P_DEC 65

// ---------------- global scratch (no allocations allowed) ----------------
__device__ float g_k[6][N_ROWS * Z_D];
__device__ float g_y[N_ROWS * Z_D];
__device__ float g_h[N_ROWS * H_D];
__device__ float g_s[N_ROWS * H_D];

// ---------------- dopri5 tableau ----------------
__constant__ float cA[6][5] = {
  {0.f, 0.f, 0.f, 0.f, 0.f},
  {0.2f, 0.f, 0.f, 0.f, 0.f},
  {3.f/40.f, 9.f/40.f, 0.f, 0.f, 0.f},
  {44.f/45.f, -56.f/15.f, 32.f/9.f, 0.f, 0.f},
  {19372.f/6561.f, -25360.f/2187.f, 64448.f/6561.f, -212.f/729.f, 0.f},
  {9017.f/3168.f, -355.f/33.f, 46732.f/5247.f, 49.f/176.f, -5103.f/18656.f}
};
__constant__ float cC[6]  = {0.f, 0.2f, 0.3f, 0.8f, 8.f/9.f, 1.f};
__constant__ float cBW[6] = {35.f/384.f, 0.f, 500.f/1113.f, 125.f/192.f,
                             -2187.f/6784.f, 11.f/84.f};

// ---------------- packed f32x2 helpers ----------------
__device__ __forceinline__ ull_t pack2(float x, float y) {
  ull_t r; asm("mov.b64 %0, {%1, %2};" : "=l"(r) : "f"(x), "f"(y)); return r;
}
__device__ __forceinline__ float2 unpack2(ull_t v) {
  float2 f; asm("mov.b64 {%0, %1}, %2;" : "=f"(f.x), "=f"(f.y) : "l"(v)); return f;
}
__device__ __forceinline__ void ffma2(ull_t& d, ull_t a, ull_t b) {
  asm("fma.rn.f32x2 %0, %1, %2, %0;" : "+l"(d) : "l"(a), "l"(b));
}
__device__ __forceinline__ float tanh_fast(float x) {
  float e = __expf(2.f * x);
  return 1.f - __fdividef(2.f, e + 1.f);
}

extern __shared__ float smem[];

// ---------------- register-blocked GEMM over transposed smem A ----------------
// acc[r][c] += sum_k AT[k][r0+r] * W[k][c0+c]; W streamed via 8-row smem tile.
template<int K, int KREAL, int RW, int NC, int WN, int PITCH>
__device__ __forceinline__ void gemm_acc(
    const float* __restrict__ AT, const float* __restrict__ Wg,
    float* __restrict__ Wst, ull_t* acc, int r0, int c0, int tid)
{
  constexpr int NT  = K / 8;
  constexpr int C4  = WN / 4;
  constexpr int NF4 = (8 * WN) / (4 * 256);
  float4 pf[NF4];

  // stage tile 0
  #pragma unroll
  for (int q = 0; q < NF4; q++) {
    int idx = tid + q * 256;
    int row = idx / C4, c4 = idx % C4;
    if (row < KREAL) pf[q] = *(const float4*)(Wg + (size_t)row * WN + c4 * 4);
    else             pf[q] = make_float4(0.f, 0.f, 0.f, 0.f);
  }
  #pragma unroll
  for (int q = 0; q < NF4; q++) {
    int idx = tid + q * 256;
    int row = idx / C4, c4 = idx % C4;
    *(float4*)(Wst + row * WN + c4 * 4) = pf[q];
  }
  __syncthreads();

  #pragma unroll 1
  for (int kt = 0; kt < NT; kt++) {
    if (kt + 1 < NT) {
      #pragma unroll
      for (int q = 0; q < NF4; q++) {
        int idx = tid + q * 256;
        int row = idx / C4, c4 = idx % C4;
        int gr  = (kt + 1) * 8 + row;
        if (gr < KREAL) pf[q] = *(const float4*)(Wg + (size_t)gr * WN + c4 * 4);
        else            pf[q] = make_float4(0.f, 0.f, 0.f, 0.f);
      }
    }
    #pragma unroll
    for (int kk = 0; kk < 8; kk++) {
      int k = kt * 8 + kk;
      float a[RW];
      #pragma unroll
      for (int i = 0; i < RW; i++) a[i] = AT[k * PITCH + r0 + i];
      ull_t bb[NC / 2];
      const ull_t* wr = (const ull_t*)(Wst + kk * WN + c0);
      #pragma unroll
      for (int j = 0; j < NC / 2; j++) bb[j] = wr[j];
      #pragma unroll
      for (int i = 0; i < RW; i++) {
        ull_t aa = pack2(a[i], a[i]);
        #pragma unroll
        for (int j = 0; j < NC / 2; j++) ffma2(acc[i * (NC / 2) + j], aa, bb[j]);
      }
    }
    __syncthreads();
    if (kt + 1 < NT) {
      #pragma unroll
      for (int q = 0; q < NF4; q++) {
        int idx = tid + q * 256;
        int row = idx / C4, c4 = idx % C4;
        *(float4*)(Wst + row * WN + c4 * 4) = pf[q];
      }
      __syncthreads();
    }
  }
}

template<int RW, int NC>
__device__ __forceinline__ void init_bias(ull_t* acc, const float* __restrict__ bias, int c0) {
  #pragma unroll
  for (int j = 0; j < NC / 2; j++) {
    float2 b2 = *(const float2*)(bias + c0 + 2 * j);
    ull_t v = pack2(b2.x, b2.y);
    #pragma unroll
    for (int i = 0; i < RW; i++) acc[i * (NC / 2) + j] = v;
  }
}

// ---------------- persistent ODE kernel: 8 dopri5 steps fused ----------------
__global__ void __launch_bounds__(256, 1) ode_kernel(
    const float* __restrict__ z,  const float* __restrict__ ts,
    const float* __restrict__ w_t, const float* __restrict__ b_t,
    const float* __restrict__ W1, const float* __restrict__ b1,
    const float* __restrict__ W2, const float* __restrict__ b2,
    const float* __restrict__ W3, const float* __restrict__ b3)
{
  float* AT  = smem;                    // [256][P_ODE]
  float* y_s = AT + 256 * P_ODE;        // [96][128]
  float* Wst = y_s + 96 * Z_D;          // [8][256]
  float* rat = Wst + 8 * 256;           // [96]

  const int tid = threadIdx.x;
  const int R0  = blockIdx.x * 96;
  const int rg = tid & 15, cg = tid >> 4;
  const int r0 = rg * 6;

  for (int idx = tid; idx < 96 * Z_D; idx += 256) {
    int r = idx >> 7, k = idx & 127;
    y_s[idx] = z[((R0 + r) & 63) * Z_D + k];
  }
  if (tid < 96) rat[tid] = ts[R0 + tid];
  __syncthreads();

  for (int step = 0; step < N_STEPS; step++) {
    float s0 = step * DT_F;
    for (int st = 0; st < 6; st++) {
      float tst = s0 + cC[st] * DT_F;

      // build yi^T into AT
      for (int idx = tid; idx < 96 * Z_D; idx += 256) {
        int r = idx >> 7, k = idx & 127;
        float v = y_s[idx];
        for (int j = 0; j < st; j++)
          v += (DT_F * cA[st][j]) * g_k[j][(size_t)(R0 + r) * Z_D + k];
        v += __cosf(fmaf(tst * rat[r], w_t[k], b_t[k]));
        AT[k * P_ODE + r] = v;
      }
      __syncthreads();

      {   // layer 1: [96,128]@[128,256] -> tanh -> AT^T
        ull_t acc[48];
        init_bias<6, 16>(acc, b1, cg * 16);
        gemm_acc<128, 128, 6, 16, 256, P_ODE>(AT, W1, Wst, acc, r0, cg * 16, tid);
        #pragma unroll
        for (int i = 0; i < 6; i++)
          #pragma unroll
          for (int j = 0; j < 8; j++) {
            float2 v = unpack2(acc[i * 8 + j]);
            int c = cg * 16 + 2 * j;
            AT[c * P_ODE + r0 + i]       = tanh_fast(v.x);
            AT[(c + 1) * P_ODE + r0 + i] = tanh_fast(v.y);
          }
        __syncthreads();
      }
      {   // layer 2: [96,256]@[256,256] -> tanh -> AT^T
        ull_t acc[48];
        init_bias<6, 16>(acc, b2, cg * 16);
        gemm_acc<256, 256, 6, 16, 256, P_ODE>(AT, W2, Wst, acc, r0, cg * 16, tid);
        #pragma unroll
        for (int i = 0; i < 6; i++)
          #pragma unroll
          for (int j = 0; j < 8; j++) {
            float2 v = unpack2(acc[i * 8 + j]);
            int c = cg * 16 + 2 * j;
            AT[c * P_ODE + r0 + i]       = tanh_fast(v.x);
            AT[(c + 1) * P_ODE + r0 + i] = tanh_fast(v.y);
          }
        __syncthreads();
      }
      {   // layer 3: [96,256]@[256,128] * ratio -> g_k[st]
        ull_t acc[24];
        init_bias<6, 8>(acc, b3, cg * 8);
        gemm_acc<256, 256, 6, 8, 128, P_ODE>(AT, W3, Wst, acc, r0, cg * 8, tid);
        #pragma unroll
        for (int i = 0; i < 6; i++) {
          int r = r0 + i;
          float rr = rat[r];
          size_t base = (size_t)(R0 + r) * Z_D + cg * 8;
          #pragma unroll
          for (int j = 0; j < 4; j++) {
            float2 v = unpack2(acc[i * 4 + j]);
            v.x *= rr; v.y *= rr;
            *(float2*)(&g_k[st][base + 2 * j]) = v;
          }
        }
        __syncthreads();
      }
    }
    // y += dt * sum bw_j k_j
    for (int idx = tid; idx < 96 * Z_D; idx += 256) {
      int r = idx >> 7, k = idx & 127;
      size_t gi = (size_t)(R0 + r) * Z_D + k;
      float v = y_s[idx];
      v += DT_F * (cBW[0] * g_k[0][gi] + cBW[2] * g_k[2][gi] + cBW[3] * g_k[3][gi]
                 + cBW[4] * g_k[4][gi] + cBW[5] * g_k[5][gi]);
      y_s[idx] = v;
    }
    __syncthreads();
  }

  for (int idx = tid; idx < 96 * Z_D; idx += 256) {
    int r = idx >> 7, k = idx & 127;
    g_y[(size_t)(R0 + r) * Z_D + k] = y_s[idx];
  }
}

// ---------------- decode_fc: [x | y_final] @ Wd + bd ----------------
__global__ void __launch_bounds__(256, 1) dec_kernel(
    const float* __restrict__ x, const float* __restrict__ Wd, const float* __restrict__ bd)
{
  float* AT  = smem;                   // [304][P_DEC]
  float* Wst = AT + 304 * P_DEC;
  const int tid = threadIdx.x;
  const int R0  = blockIdx.x * 64;
  const int rg = tid & 15, cg = tid >> 4;
  const float* xr = x + (size_t)blockIdx.x * 172;

  for (int idx = tid; idx < 304 * 64; idx += 256) {
    int c = idx >> 6, r = idx & 63;
    float v = 0.f;
    if (c < 172) v = xr[c];
    else if (c < 300) v = g_y[(size_t)(R0 + r) * Z_D + (c - 172)];
    AT[c * P_DEC + r] = v;
  }
  __syncthreads();

  ull_t acc[32];
  init_bias<4, 16>(acc, bd, cg * 16);
  gemm_acc<304, 300, 4, 16, 256, P_DEC>(AT, Wd, Wst, acc, rg * 4, cg * 16, tid);
  #pragma unroll
  for (int i = 0; i < 4; i++) {
    size_t base = (size_t)(R0 + rg * 4 + i) * H_D + cg * 16;
    #pragma unroll
    for (int j = 0; j < 8; j++) {
      float2 v = unpack2(acc[i * 8 + j]);
      *(float2*)(&g_h[base + 2 * j]) = v;
    }
  }
}

// ---------------- src/dst fc ----------------
__global__ void __launch_bounds__(256, 1) sd_kernel(
    const float* __restrict__ Ws, const float* __restrict__ bs,
    const float* __restrict__ Wdst, const float* __restrict__ bdst)
{
  float* AT  = smem;                   // [256][P_DEC]
  float* Wst = AT + 256 * P_DEC;
  const int tid = threadIdx.x;
  const int R0  = blockIdx.x * 64;
  const int rg = tid & 15, cg = tid >> 4;
  const float* W = (R0 < 4096) ? Ws : Wdst;
  const float* bb = (R0 < 4096) ? bs : bdst;

  for (int idx = tid; idx < 256 * 64; idx += 256) {
    int c = idx >> 6, r = idx & 63;
    AT[c * P_DEC + r] = g_h[(size_t)(R0 + r) * H_D + c];
  }
  __syncthreads();

  ull_t acc[32];
  init_bias<4, 16>(acc, bb, cg * 16);
  gemm_acc<256, 256, 4, 16, 256, P_DEC>(AT, W, Wst, acc, rg * 4, cg * 16, tid);
  #pragma unroll
  for (int i = 0; i < 4; i++) {
    size_t base = (size_t)(R0 + rg * 4 + i) * H_D + cg * 16;
    #pragma unroll
    for (int j = 0; j < 8; j++) {
      float2 v = unpack2(acc[i * 8 + j]);
      *(float2*)(&g_s[base + 2 * j]) = v;
    }
  }
}

// ---------------- edge out + mean over L ----------------
__global__ void __launch_bounds__(256) edge_kernel(
    const float* __restrict__ Wo, const float* __restrict__ bo, float* __restrict__ out)
{
  __shared__ float red[8];
  const int tid = threadIdx.x;
  const int o = blockIdx.x;
  const int b = (o < 64) ? o : (o - 64);
  const size_t off2 = (o < 64) ? (size_t)4096 * H_D : (size_t)8192 * H_D;
  const float wcol = Wo[tid];

  float sum = 0.f;
  for (int l = 0; l < 64; l++) {
    size_t r1 = (size_t)(b * 64 + l) * H_D + tid;
    float v = g_s[r1] + g_s[off2 + r1];
    sum += fmaxf(v, 0.f) * wcol;
  }
  #pragma unroll
  for (int d = 16; d > 0; d >>= 1) sum += __shfl_xor_sync(0xFFFFFFFFu, sum, d);
  if ((tid & 31) == 0) red[tid >> 5] = sum;
  __syncthreads();
  if (tid == 0) {
    float t = 0.f;
    #pragma unroll
    for (int w = 0; w < 8; w++) t += red[w];
    out[o] = t * (1.f / 64.f) + bo[0];
  }
}

extern "C" void kernel_launch(void* const* d_in, const int* in_sizes, int n_in,
                              void* d_out, int out_size) {
  const float* x    = (const float*)d_in[0];
  const float* z    = (const float*)d_in[1];
  const float* ts   = (const float*)d_in[2];
  const float* w_t  = (const float*)d_in[3];
  const float* b_t  = (const float*)d_in[4];
  const float* W1   = (const float*)d_in[5];
  const float* b1   = (const float*)d_in[6];
  const float* W2   = (const float*)d_in[7];
  const float* b2   = (const float*)d_in[8];
  const float* W3   = (const float*)d_in[9];
  const float* b3   = (const float*)d_in[10];
  const float* Wd   = (const float*)d_in[11];
  const float* bd   = (const float*)d_in[12];
  const float* Ws   = (const float*)d_in[13];
  const float* bs   = (const float*)d_in[14];
  const float* Wdst = (const float*)d_in[15];
  const float* bdst = (const float*)d_in[16];
  const float* Wo   = (const float*)d_in[17];
  const float* bo   = (const float*)d_in[18];
  float* out = (float*)d_out;

  const int SM_ODE = (256 * P_ODE + 96 * Z_D + 8 * 256 + 96) * 4;
  const int SM_D1  = (304 * P_DEC + 8 * 256) * 4;
  const int SM_D2  = (256 * P_DEC + 8 * 256) * 4;

  cudaFuncSetAttribute(ode_kernel, cudaFuncAttributeMaxDynamicSharedMemorySize, SM_ODE);
  cudaFuncSetAttribute(dec_kernel, cudaFuncAttributeMaxDynamicSharedMemorySize, SM_D1);
  cudaFuncSetAttribute(sd_kernel,  cudaFuncAttributeMaxDynamicSharedMemorySize, SM_D2);

  ode_kernel<<<128, 256, SM_ODE>>>(z, ts, w_t, b_t, W1, b1, W2, b2, W3, b3);
  dec_kernel<<<192, 256, SM_D1>>>(x, Wd, bd);
  sd_kernel<<<192, 256, SM_D2>>>(Ws, bs, Wdst, bdst);
  edge_kernel<<<128, 256>>>(Wo, bo, out);
}

// round 6
// speedup vs baseline: 1.6879x; 1.6879x over previous
#include <cuda_runtime.h>
#include <cuda_bf16.h>
#include <cstdint>

#define N_ROWS 12288
#define Z_D 128
#define H_D 256
#define N_STEPS 8
#define DT_F 0.125f

__device__ float g_k[6][N_ROWS * Z_D];
__device__ float g_y[N_ROWS * Z_D];
__device__ float g_h[N_ROWS * H_D];
__device__ float g_s[N_ROWS * H_D];
__device__ __nv_bfloat16 g_ws0[131072];
__device__ __nv_bfloat16 g_ws1[131072];
#define OFF_W1 0
#define OFF_W2 32768
#define OFF_W3 98304

__constant__ float cA[6][5] = {
  {0.f,0.f,0.f,0.f,0.f},
  {0.2f,0.f,0.f,0.f,0.f},
  {3.f/40.f,9.f/40.f,0.f,0.f,0.f},
  {44.f/45.f,-56.f/15.f,32.f/9.f,0.f,0.f},
  {19372.f/6561.f,-25360.f/2187.f,64448.f/6561.f,-212.f/729.f,0.f},
  {9017.f/3168.f,-355.f/33.f,46732.f/5247.f,49.f/176.f,-5103.f/18656.f}
};
__constant__ float cC[6] = {0.f,0.2f,0.3f,0.8f,8.f/9.f,1.f};

// ---------------- helpers ----------------
__device__ __forceinline__ uint32_t smem_u32(const void* p) {
  uint32_t a;
  asm("{ .reg .u64 t; cvta.to.shared.u64 t, %1; cvt.u32.u64 %0, t; }" : "=r"(a) : "l"(p));
  return a;
}
#define CVT_BF2(res, lo, hi) \
  asm("cvt.rn.satfinite.bf16x2.f32 %0, %1, %2;" : "=r"(res) : "f"(hi), "f"(lo))
#define CP16(dst, src) \
  asm volatile("cp.async.cg.shared.global [%0], [%1], 16;" :: "r"(dst), "l"(src) : "memory")
#define CP_COMMIT() asm volatile("cp.async.commit_group;" ::: "memory")
#define CP_WAIT0()  asm volatile("cp.async.wait_group 0;" ::: "memory")

__device__ __forceinline__ void mma_bf16(float* c, const uint32_t* a, const uint32_t* b) {
  asm volatile(
    "mma.sync.aligned.m16n8k16.row.col.f32.bf16.bf16.f32 "
    "{%0,%1,%2,%3}, {%4,%5,%6,%7}, {%8,%9}, {%0,%1,%2,%3};"
    : "+f"(c[0]), "+f"(c[1]), "+f"(c[2]), "+f"(c[3])
    : "r"(a[0]), "r"(a[1]), "r"(a[2]), "r"(a[3]), "r"(b[0]), "r"(b[1]));
}
__device__ __forceinline__ void ldm4(uint32_t* r, uint32_t addr) {
  asm volatile("ldmatrix.sync.aligned.m8n8.x4.shared.b16 {%0,%1,%2,%3}, [%4];"
    : "=r"(r[0]), "=r"(r[1]), "=r"(r[2]), "=r"(r[3]) : "r"(addr));
}
__device__ __forceinline__ float tanh_fast(float x) {
  float e = __expf(2.f * x);
  return 1.f - __fdividef(2.f, e + 1.f);
}

// smem byte offsets: A stride 264 bf16 (528B), W chunk stride 72 bf16 (144B)
#define SO_A0   0
#define SO_A1   67584
#define SO_W0   135168
#define SO_W1   172032
#define SO_B1S  208896
#define SO_B2S  209920
#define SO_B3S  210944
#define SO_WTS  211456
#define SO_BTS  211968
#define SO_RAT  212480
#define SM_ODE  212992

// ---------------- weight prep: split fp32 -> bf16 hi/lo, transpose to [N][K] ----------------
__global__ void prep_kernel(const float* __restrict__ W1, const float* __restrict__ W2,
                            const float* __restrict__ W3) {
  int i = blockIdx.x * 256 + threadIdx.x;
  float w; int dst;
  if (i < 32768)      { int n = i >> 7, k = i & 127;                w = W1[k * 256 + n]; dst = OFF_W1 + i; }
  else if (i < 98304) { int e = i - 32768; int n = e >> 8, k = e & 255; w = W2[k * 256 + n]; dst = OFF_W2 + e; }
  else                { int e = i - 98304; int n = e >> 8, k = e & 255; w = W3[k * 128 + n]; dst = OFF_W3 + e; }
  __nv_bfloat16 h = __float2bfloat16(w);
  g_ws0[dst] = h;
  g_ws1[dst] = __float2bfloat16(w - __bfloat162float(h));
}

// ---------------- one MLP layer via split HMMA ----------------
// C[128, N] += A[128, Kfull] * W[N, Kfull]^T ; warp (mg, ng): rows 32*mg.., cols per ncb/NT.
// c: [2*NT][4] accumulators (bias pre-initialized).
template<int NT, int KCH, int NW>
__device__ __forceinline__ void layer_mma(
    const __nv_bfloat16* __restrict__ w0, const __nv_bfloat16* __restrict__ w1, int Kfull,
    uint32_t a0b, uint32_t a1b, uint32_t wb0, uint32_t wb1,
    int ncb, int mg, int lane, int tid, float (*c)[4]) {
  #pragma unroll 1
  for (int kc = 0; kc < KCH; kc++) {
    __syncthreads();   // previous chunk's B reads done
    for (int i = tid; i < NW * 8; i += 256) {
      int n = i >> 3, kk = i & 7;
      uint32_t d = (uint32_t)(n * 144 + kk * 16);
      size_t src = (size_t)n * Kfull + kc * 64 + kk * 8;
      CP16(wb0 + d, w0 + src);
      CP16(wb1 + d, w1 + src);
    }
    CP_COMMIT();
    CP_WAIT0();
    __syncthreads();
    #pragma unroll
    for (int ks = 0; ks < 4; ks++) {
      int k0 = kc * 64 + ks * 16;
      int m = lane >> 3, ri = lane & 7;
      int rbase = 32 * mg + (m & 1) * 8 + ri;
      int kcol = k0 + (m >> 1) * 8;
      uint32_t a0f[2][4], a1f[2][4];
      #pragma unroll
      for (int mt = 0; mt < 2; mt++) {
        uint32_t off = (uint32_t)(((rbase + 16 * mt) * 264 + kcol) * 2);
        ldm4(a0f[mt], a0b + off);
        ldm4(a1f[mt], a1b + off);
      }
      #pragma unroll
      for (int nt = 0; nt < NT; nt++) {
        int n = ncb + nt * 8 + (lane >> 2);
        uint32_t boff = (uint32_t)(n * 144 + (ks * 16 + (lane & 3) * 2) * 2);
        uint32_t b0[2], b1[2];
        asm volatile("ld.shared.b32 %0, [%1];" : "=r"(b0[0]) : "r"(wb0 + boff));
        asm volatile("ld.shared.b32 %0, [%1];" : "=r"(b0[1]) : "r"(wb0 + boff + 16));
        asm volatile("ld.shared.b32 %0, [%1];" : "=r"(b1[0]) : "r"(wb1 + boff));
        asm volatile("ld.shared.b32 %0, [%1];" : "=r"(b1[1]) : "r"(wb1 + boff + 16));
        #pragma unroll
        for (int mt = 0; mt < 2; mt++) {
          mma_bf16(c[mt * NT + nt], a0f[mt], b0);
          mma_bf16(c[mt * NT + nt], a0f[mt], b1);
          mma_bf16(c[mt * NT + nt], a1f[mt], b0);
        }
      }
    }
  }
  __syncthreads();   // all A reads done before epilogue overwrites A
}

template<int NT>
__device__ __forceinline__ void init_bias_frag(float (*c)[4], const float* bias, int ncb, int lane) {
  #pragma unroll
  for (int nt = 0; nt < NT; nt++) {
    int cc = ncb + nt * 8 + (lane & 3) * 2;
    float b0 = bias[cc], b1 = bias[cc + 1];
    #pragma unroll
    for (int mt = 0; mt < 2; mt++) {
      c[mt * NT + nt][0] = b0; c[mt * NT + nt][1] = b1;
      c[mt * NT + nt][2] = b0; c[mt * NT + nt][3] = b1;
    }
  }
}

// tanh epilogue: C -> split bf16 into A0/A1 smem
template<int NT>
__device__ __forceinline__ void epi_tanh(float (*c)[4], uint32_t a0b, uint32_t a1b,
                                         int ncb, int mg, int lane) {
  #pragma unroll
  for (int mt = 0; mt < 2; mt++) {
    int row = 32 * mg + 16 * mt + (lane >> 2);
    #pragma unroll
    for (int nt = 0; nt < NT; nt++) {
      int col = ncb + nt * 8 + (lane & 3) * 2;
      float* cf = c[mt * NT + nt];
      #pragma unroll
      for (int h = 0; h < 2; h++) {   // h=0: row, h=1: row+8
        float t0 = tanh_fast(cf[2 * h]);
        float t1 = tanh_fast(cf[2 * h + 1]);
        uint32_t hp; CVT_BF2(hp, t0, t1);
        __nv_bfloat162 hb = *reinterpret_cast<__nv_bfloat162*>(&hp);
        uint32_t lp; CVT_BF2(lp, t0 - __bfloat162float(hb.x), t1 - __bfloat162float(hb.y));
        uint32_t off = (uint32_t)(((row + 8 * h) * 264 + col) * 2);
        asm volatile("st.shared.b32 [%0], %1;" :: "r"(a0b + off), "r"(hp) : "memory");
        asm volatile("st.shared.b32 [%0], %1;" :: "r"(a1b + off), "r"(lp) : "memory");
      }
    }
  }
}

extern __shared__ char smem_raw[];

__global__ void __launch_bounds__(256, 1) ode_kernel(
    const float* __restrict__ z, const float* __restrict__ ts,
    const float* __restrict__ w_t, const float* __restrict__ b_t,
    const float* __restrict__ b1, const float* __restrict__ b2, const float* __restrict__ b3) {
  const uint32_t base = smem_u32(smem_raw);
  float* b1s = (float*)(smem_raw + SO_B1S);
  float* b2s = (float*)(smem_raw + SO_B2S);
  float* b3s = (float*)(smem_raw + SO_B3S);
  float* wts = (float*)(smem_raw + SO_WTS);
  float* bts = (float*)(smem_raw + SO_BTS);
  float* rat = (float*)(smem_raw + SO_RAT);
  const uint32_t a0b = base + SO_A0, a1b = base + SO_A1;
  const uint32_t wb0 = base + SO_W0, wb1 = base + SO_W1;
  const int tid = threadIdx.x;
  const int lane = tid & 31, w = tid >> 5;
  const int mg = w >> 1, ng = w & 1;
  const int R0 = blockIdx.x * 128;

  if (tid < 128) {
    rat[tid] = ts[R0 + tid];
    wts[tid] = w_t[tid];
    bts[tid] = b_t[tid];
    b3s[tid] = b3[tid];
  }
  b1s[tid] = b1[tid];
  b2s[tid] = b2[tid];
  for (int p = tid; p < 128 * 64; p += 256) {
    int r = p >> 6, k2 = (p & 63) * 2;
    float2 zz = *(const float2*)(z + ((R0 + r) & 63) * Z_D + k2);
    *(float2*)(g_y + (size_t)(R0 + r) * Z_D + k2) = zz;
  }
  __syncthreads();

  for (int step = 0; step < N_STEPS; step++) {
    float s0 = step * DT_F;
    for (int st = 0; st < 6; st++) {
      float tst = s0 + cC[st] * DT_F;
      // ---- build stage input into split A (K=128) ----
      for (int p = tid; p < 128 * 64; p += 256) {
        int r = p >> 6, k2 = (p & 63) * 2;
        size_t gi = (size_t)(R0 + r) * Z_D + k2;
        float2 v = *(const float2*)(g_y + gi);
        #pragma unroll 1
        for (int j = 0; j < st; j++) {
          float2 kk = *(const float2*)(&g_k[j][gi]);
          float cj = DT_F * cA[st][j];
          v.x += cj * kk.x; v.y += cj * kk.y;
        }
        float tr = tst * rat[r];
        v.x += __cosf(fmaf(tr, wts[k2], bts[k2]));
        v.y += __cosf(fmaf(tr, wts[k2 + 1], bts[k2 + 1]));
        uint32_t hp; CVT_BF2(hp, v.x, v.y);
        __nv_bfloat162 hb = *reinterpret_cast<__nv_bfloat162*>(&hp);
        uint32_t lp; CVT_BF2(lp, v.x - __bfloat162float(hb.x), v.y - __bfloat162float(hb.y));
        uint32_t off = (uint32_t)((r * 264 + k2) * 2);
        asm volatile("st.shared.b32 [%0], %1;" :: "r"(a0b + off), "r"(hp) : "memory");
        asm volatile("st.shared.b32 [%0], %1;" :: "r"(a1b + off), "r"(lp) : "memory");
      }
      __syncthreads();
      {   // layer 1: K=128 -> N=256, tanh
        float c[32][4];
        init_bias_frag<16>(c, b1s, ng * 128, lane);
        layer_mma<16, 2, 256>(g_ws0 + OFF_W1, g_ws1 + OFF_W1, 128,
                              a0b, a1b, wb0, wb1, ng * 128, mg, lane, tid, c);
        epi_tanh<16>(c, a0b, a1b, ng * 128, mg, lane);
      }
      __syncthreads();
      {   // layer 2: K=256 -> N=256, tanh
        float c[32][4];
        init_bias_frag<16>(c, b2s, ng * 128, lane);
        layer_mma<16, 4, 256>(g_ws0 + OFF_W2, g_ws1 + OFF_W2, 256,
                              a0b, a1b, wb0, wb1, ng * 128, mg, lane, tid, c);
        epi_tanh<16>(c, a0b, a1b, ng * 128, mg, lane);
      }
      __syncthreads();
      {   // layer 3: K=256 -> N=128, * ratio -> g_k[st]
        float c[16][4];
        init_bias_frag<8>(c, b3s, ng * 64, lane);
        layer_mma<8, 4, 128>(g_ws0 + OFF_W3, g_ws1 + OFF_W3, 256,
                             a0b, a1b, wb0, wb1, ng * 64, mg, lane, tid, c);
        #pragma unroll
        for (int mt = 0; mt < 2; mt++) {
          int row = 32 * mg + 16 * mt + (lane >> 2);
          #pragma unroll
          for (int nt = 0; nt < 8; nt++) {
            int col = ng * 64 + nt * 8 + (lane & 3) * 2;
            float* cf = c[mt * 8 + nt];
            #pragma unroll
            for (int h = 0; h < 2; h++) {
              int rr = row + 8 * h;
              float sc = rat[rr];
              float2 v = make_float2(cf[2 * h] * sc, cf[2 * h + 1] * sc);
              *(float2*)(&g_k[st][(size_t)(R0 + rr) * Z_D + col]) = v;
            }
          }
        }
      }
      __syncthreads();
    }
    // ---- y += dt * sum bw_j k_j ----
    for (int p = tid; p < 128 * 64; p += 256) {
      int r = p >> 6, k2 = (p & 63) * 2;
      size_t gi = (size_t)(R0 + r) * Z_D + k2;
      float2 y = *(float2*)(g_y + gi);
      float2 k0 = *(const float2*)(&g_k[0][gi]);
      float2 q2 = *(const float2*)(&g_k[2][gi]);
      float2 q3 = *(const float2*)(&g_k[3][gi]);
      float2 q4 = *(const float2*)(&g_k[4][gi]);
      float2 q5 = *(const float2*)(&g_k[5][gi]);
      const float w0 = 35.f/384.f, w2 = 500.f/1113.f, w3 = 125.f/192.f,
                  w4 = -2187.f/6784.f, w5 = 11.f/84.f;
      y.x += DT_F * (w0*k0.x + w2*q2.x + w3*q3.x + w4*q4.x + w5*q5.x);
      y.y += DT_F * (w0*k0.y + w2*q2.y + w3*q3.y + w4*q4.y + w5*q5.y);
      *(float2*)(g_y + gi) = y;
    }
    __syncthreads();
  }
}

// ---------------- decode_fc ----------------
__global__ void __launch_bounds__(256) dec_kernel(
    const float* __restrict__ x, const float* __restrict__ Wd, const float* __restrict__ bd) {
  __shared__ float xs[172];
  __shared__ float ys[64 * 128];
  const int tid = threadIdx.x;
  const int b = blockIdx.x, R0 = b * 64;
  for (int i = tid; i < 172; i += 256) xs[i] = x[(size_t)b * 172 + i];
  for (int i = tid; i < 64 * 128; i += 256) ys[i] = g_y[(size_t)R0 * 128 + i];
  __syncthreads();
  float acc0 = bd[tid];
  #pragma unroll 4
  for (int k = 0; k < 172; k++) acc0 = fmaf(xs[k], Wd[(size_t)k * 256 + tid], acc0);
  float acc[64];
  #pragma unroll
  for (int r = 0; r < 64; r++) acc[r] = acc0;
  #pragma unroll 2
  for (int k = 0; k < 128; k++) {
    float w = Wd[(size_t)(172 + k) * 256 + tid];
    #pragma unroll
    for (int r = 0; r < 64; r++) acc[r] = fmaf(ys[r * 128 + k], w, acc[r]);
  }
  #pragma unroll
  for (int r = 0; r < 64; r++) g_h[(size_t)(R0 + r) * 256 + tid] = acc[r];
}

// ---------------- src/dst fc ----------------
__global__ void __launch_bounds__(256) sd_kernel(
    const float* __restrict__ Ws, const float* __restrict__ bs,
    const float* __restrict__ Wdst, const float* __restrict__ bdst) {
  __shared__ float hs[32 * 256];
  const int tid = threadIdx.x;
  const int R0 = blockIdx.x * 32;
  const float* W = (R0 < 4096) ? Ws : Wdst;
  const float* bb = (R0 < 4096) ? bs : bdst;
  for (int i = tid; i < 32 * 256; i += 256) hs[i] = g_h[(size_t)R0 * 256 + i];
  __syncthreads();
  float acc[32];
  float b0 = bb[tid];
  #pragma unroll
  for (int r = 0; r < 32; r++) acc[r] = b0;
  #pragma unroll 2
  for (int k = 0; k < 256; k++) {
    float w = W[(size_t)k * 256 + tid];
    #pragma unroll
    for (int r = 0; r < 32; r++) acc[r] = fmaf(hs[r * 256 + k], w, acc[r]);
  }
  #pragma unroll
  for (int r = 0; r < 32; r++) g_s[(size_t)(R0 + r) * 256 + tid] = acc[r];
}

// ---------------- edge out + mean over L ----------------
__global__ void __launch_bounds__(256) edge_kernel(
    const float* __restrict__ Wo, const float* __restrict__ bo, float* __restrict__ out) {
  __shared__ float red[8];
  const int tid = threadIdx.x;
  const int o = blockIdx.x;
  const int b = (o < 64) ? o : (o - 64);
  const size_t off2 = (o < 64) ? (size_t)4096 * H_D : (size_t)8192 * H_D;
  const float wcol = Wo[tid];
  float sum = 0.f;
  for (int l = 0; l < 64; l++) {
    size_t r1 = (size_t)(b * 64 + l) * H_D + tid;
    float v = g_s[r1] + g_s[off2 + r1];
    sum += fmaxf(v, 0.f) * wcol;
  }
  #pragma unroll
  for (int d = 16; d > 0; d >>= 1) sum += __shfl_xor_sync(0xFFFFFFFFu, sum, d);
  if ((tid & 31) == 0) red[tid >> 5] = sum;
  __syncthreads();
  if (tid == 0) {
    float t = 0.f;
    #pragma unroll
    for (int w = 0; w < 8; w++) t += red[w];
    out[o] = t * (1.f / 64.f) + bo[0];
  }
}

extern "C" void kernel_launch(void* const* d_in, const int* in_sizes, int n_in,
                              void* d_out, int out_size) {
  const float* x    = (const float*)d_in[0];
  const float* z    = (const float*)d_in[1];
  const float* ts   = (const float*)d_in[2];
  const float* w_t  = (const float*)d_in[3];
  const float* b_t  = (const float*)d_in[4];
  const float* W1   = (const float*)d_in[5];
  const float* b1   = (const float*)d_in[6];
  const float* W2   = (const float*)d_in[7];
  const float* b2   = (const float*)d_in[8];
  const float* W3   = (const float*)d_in[9];
  const float* b3   = (const float*)d_in[10];
  const float* Wd   = (const float*)d_in[11];
  const float* bd   = (const float*)d_in[12];
  const float* Ws   = (const float*)d_in[13];
  const float* bs   = (const float*)d_in[14];
  const float* Wdst = (const float*)d_in[15];
  const float* bdst = (const float*)d_in[16];
  const float* Wo   = (const float*)d_in[17];
  const float* bo   = (const float*)d_in[18];
  float* out = (float*)d_out;

  cudaFuncSetAttribute(ode_kernel, cudaFuncAttributeMaxDynamicSharedMemorySize, SM_ODE);

  prep_kernel<<<512, 256>>>(W1, W2, W3);
  ode_kernel<<<96, 256, SM_ODE>>>(z, ts, w_t, b_t, b1, b2, b3);
  dec_kernel<<<192, 256>>>(x, Wd, bd);
  sd_kernel<<<384, 256>>>(Ws, bs, Wdst, bdst);
  edge_kernel<<<128, 256>>>(Wo, bo, out);
}

// round 7
// speedup vs baseline: 2.1118x; 1.2512x over previous
#include <cuda_runtime.h>
#include <cuda_bf16.h>
#include <cstdint>

#define N_ROWS 12288
#define Z_D 128
#define H_D 256
#define N_STEPS 8
#define DT_F 0.125f

__device__ float g_k[6][N_ROWS * Z_D];
__device__ float g_y[N_ROWS * Z_D];
__device__ float g_h[N_ROWS * H_D];
__device__ float g_s[N_ROWS * H_D];
__device__ __nv_bfloat16 g_ws0[131072];
__device__ __nv_bfloat16 g_ws1[131072];
#define OFF_W1 0
#define OFF_W2 32768
#define OFF_W3 98304

__constant__ float cA[6][5] = {
  {0.f,0.f,0.f,0.f,0.f},
  {0.2f,0.f,0.f,0.f,0.f},
  {3.f/40.f,9.f/40.f,0.f,0.f,0.f},
  {44.f/45.f,-56.f/15.f,32.f/9.f,0.f,0.f},
  {19372.f/6561.f,-25360.f/2187.f,64448.f/6561.f,-212.f/729.f,0.f},
  {9017.f/3168.f,-355.f/33.f,46732.f/5247.f,49.f/176.f,-5103.f/18656.f}
};
__constant__ float cC[6] = {0.f,0.2f,0.3f,0.8f,8.f/9.f,1.f};

// ---------------- helpers ----------------
__device__ __forceinline__ uint32_t smem_u32(const void* p) {
  uint32_t a;
  asm("{ .reg .u64 t; cvta.to.shared.u64 t, %1; cvt.u32.u64 %0, t; }" : "=r"(a) : "l"(p));
  return a;
}
#define CVT_BF2(res, lo, hi) \
  asm("cvt.rn.satfinite.bf16x2.f32 %0, %1, %2;" : "=r"(res) : "f"(hi), "f"(lo))
#define CP16(dst, src) \
  asm volatile("cp.async.cg.shared.global [%0], [%1], 16;" :: "r"(dst), "l"(src) : "memory")
#define CP_COMMIT() asm volatile("cp.async.commit_group;" ::: "memory")

__device__ __forceinline__ void mma_bf16(float* c, const uint32_t* a, const uint32_t* b) {
  asm volatile(
    "mma.sync.aligned.m16n8k16.row.col.f32.bf16.bf16.f32 "
    "{%0,%1,%2,%3}, {%4,%5,%6,%7}, {%8,%9}, {%0,%1,%2,%3};"
    : "+f"(c[0]), "+f"(c[1]), "+f"(c[2]), "+f"(c[3])
    : "r"(a[0]), "r"(a[1]), "r"(a[2]), "r"(a[3]), "r"(b[0]), "r"(b[1]));
}
__device__ __forceinline__ void ldm4(uint32_t* r, uint32_t addr) {
  asm volatile("ldmatrix.sync.aligned.m8n8.x4.shared.b16 {%0,%1,%2,%3}, [%4];"
    : "=r"(r[0]), "=r"(r[1]), "=r"(r[2]), "=r"(r[3]) : "r"(addr));
}
__device__ __forceinline__ float tanh_fast(float x) {
  float e = __expf(2.f * x);
  return 1.f - __fdividef(2.f, e + 1.f);
}

// ---- smem layout (bytes). A stride 264 bf16 = 528 B; W chunk row stride 80 B.
#define SO_A0   0
#define SO_A1   50688
#define SO_W00  101376
#define SO_W10  121856
#define SO_W01  142336
#define SO_W11  162816
#define SO_B1S  183296
#define SO_B2S  184320
#define SO_B3S  185344
#define SO_WTS  185856
#define SO_BTS  186368
#define SO_RAT  186880
#define SM_ODE  187264

// ---------------- weight prep: split fp32 -> bf16 hi/lo, transpose to [N][K] ----------------
__global__ void prep_kernel(const float* __restrict__ W1, const float* __restrict__ W2,
                            const float* __restrict__ W3) {
  int i = blockIdx.x * 256 + threadIdx.x;
  float w; int dst;
  if (i < 32768)      { int n = i >> 7, k = i & 127;                w = W1[k * 256 + n]; dst = OFF_W1 + i; }
  else if (i < 98304) { int e = i - 32768; int n = e >> 8, k = e & 255; w = W2[k * 256 + n]; dst = OFF_W2 + e; }
  else                { int e = i - 98304; int n = e >> 8, k = e & 255; w = W3[k * 128 + n]; dst = OFF_W3 + e; }
  __nv_bfloat16 h = __float2bfloat16(w);
  g_ws0[dst] = h;
  g_ws1[dst] = __float2bfloat16(w - __bfloat162float(h));
}

// ---------------- one MLP layer: split HMMA, double-buffered 32-K chunks, ldmatrix B ----------------
// Warp (mg, ng): rows 16*mg..+15, cols ncb..ncb+8*NT-1. c[NT][4] bias-preloaded.
template<int NT, int NCH, int NW>
__device__ __forceinline__ void layer_mma(
    const __nv_bfloat16* __restrict__ w0, const __nv_bfloat16* __restrict__ w1, int Kfull,
    uint32_t a0b, uint32_t a1b, const uint32_t* wbuf,
    int ncb, int mg, int lane, int tid, float (*c)[4]) {
  auto issue = [&](int cidx) {
    uint32_t w0b = wbuf[(cidx & 1) * 2], w1b = wbuf[(cidx & 1) * 2 + 1];
    for (int i = tid; i < NW * 4; i += 384) {
      int n = i >> 2, q = i & 3;
      uint32_t d = (uint32_t)(n * 80 + q * 16);
      size_t src = (size_t)n * Kfull + cidx * 32 + q * 8;
      CP16(w0b + d, w0 + src);
      CP16(w1b + d, w1 + src);
    }
    CP_COMMIT();
  };
  issue(0);
  #pragma unroll 1
  for (int ck = 0; ck < NCH; ck++) {
    if (ck + 1 < NCH) {
      issue(ck + 1);
      asm volatile("cp.async.wait_group 1;" ::: "memory");
    } else {
      asm volatile("cp.async.wait_group 0;" ::: "memory");
    }
    __syncthreads();
    uint32_t w0b = wbuf[(ck & 1) * 2], w1b = wbuf[(ck & 1) * 2 + 1];
    #pragma unroll
    for (int ks = 0; ks < 2; ks++) {
      int m = lane >> 3, ri = lane & 7;
      int row = 16 * mg + (m & 1) * 8 + ri;
      int kcol = ck * 32 + ks * 16 + (m >> 1) * 8;
      uint32_t aoff = (uint32_t)(row * 528 + kcol * 2);
      uint32_t a0f[4], a1f[4];
      ldm4(a0f, a0b + aoff);
      ldm4(a1f, a1b + aoff);
      int g = lane >> 3, rr = lane & 7;
      #pragma unroll
      for (int nt2 = 0; nt2 < NT / 2; nt2++) {
        int n = ncb + nt2 * 16 + (g >> 1) * 8 + rr;
        uint32_t boff = (uint32_t)(n * 80 + (ks * 16 + (g & 1) * 8) * 2);
        uint32_t rb0[4], rb1[4];
        ldm4(rb0, w0b + boff);
        ldm4(rb1, w1b + boff);
        mma_bf16(c[nt2 * 2],     a0f, rb0);
        mma_bf16(c[nt2 * 2],     a0f, rb1);
        mma_bf16(c[nt2 * 2],     a1f, rb0);
        mma_bf16(c[nt2 * 2 + 1], a0f, rb0 + 2);
        mma_bf16(c[nt2 * 2 + 1], a0f, rb1 + 2);
        mma_bf16(c[nt2 * 2 + 1], a1f, rb0 + 2);
      }
    }
    __syncthreads();
  }
}

template<int NT>
__device__ __forceinline__ void init_bias_frag(float (*c)[4], const float* bias, int ncb, int lane) {
  #pragma unroll
  for (int nt = 0; nt < NT; nt++) {
    int cc = ncb + nt * 8 + (lane & 3) * 2;
    float b0 = bias[cc], b1 = bias[cc + 1];
    c[nt][0] = b0; c[nt][1] = b1; c[nt][2] = b0; c[nt][3] = b1;
  }
}

// tanh epilogue: C -> split bf16 into A0/A1 smem
template<int NT>
__device__ __forceinline__ void epi_tanh(float (*c)[4], uint32_t a0b, uint32_t a1b,
                                         int ncb, int mg, int lane) {
  int row = 16 * mg + (lane >> 2);
  #pragma unroll
  for (int nt = 0; nt < NT; nt++) {
    int col = ncb + nt * 8 + (lane & 3) * 2;
    #pragma unroll
    for (int h = 0; h < 2; h++) {
      float t0 = tanh_fast(c[nt][2 * h]);
      float t1 = tanh_fast(c[nt][2 * h + 1]);
      uint32_t hp; CVT_BF2(hp, t0, t1);
      __nv_bfloat162 hb = *reinterpret_cast<__nv_bfloat162*>(&hp);
      uint32_t lp; CVT_BF2(lp, t0 - __bfloat162float(hb.x), t1 - __bfloat162float(hb.y));
      uint32_t off = (uint32_t)(((row + 8 * h) * 264 + col) * 2);
      asm volatile("st.shared.b32 [%0], %1;" :: "r"(a0b + off), "r"(hp) : "memory");
      asm volatile("st.shared.b32 [%0], %1;" :: "r"(a1b + off), "r"(lp) : "memory");
    }
  }
}

extern __shared__ char smem_raw[];

__global__ void __launch_bounds__(384, 1) ode_kernel(
    const float* __restrict__ z, const float* __restrict__ ts,
    const float* __restrict__ w_t, const float* __restrict__ b_t,
    const float* __restrict__ b1, const float* __restrict__ b2, const float* __restrict__ b3) {
  const uint32_t base = smem_u32(smem_raw);
  float* b1s = (float*)(smem_raw + SO_B1S);
  float* b2s = (float*)(smem_raw + SO_B2S);
  float* b3s = (float*)(smem_raw + SO_B3S);
  float* wts = (float*)(smem_raw + SO_WTS);
  float* bts = (float*)(smem_raw + SO_BTS);
  float* rat = (float*)(smem_raw + SO_RAT);
  const uint32_t a0b = base + SO_A0, a1b = base + SO_A1;
  const uint32_t wbuf[4] = {base + SO_W00, base + SO_W10, base + SO_W01, base + SO_W11};
  const int tid = threadIdx.x;
  const int lane = tid & 31, w = tid >> 5;
  const int mg = w >> 1, ng = w & 1;   // mg 0..5 (16 rows), ng 0..1
  const int R0 = blockIdx.x * 96;

  if (tid < 96) rat[tid] = ts[R0 + tid];
  if (tid < 128) {
    wts[tid] = w_t[tid];
    bts[tid] = b_t[tid];
    b3s[tid] = b3[tid];
  }
  if (tid < 256) { b1s[tid] = b1[tid]; b2s[tid] = b2[tid]; }
  for (int p = tid; p < 96 * 64; p += 384) {
    int r = p >> 6, k2 = (p & 63) * 2;
    float2 zz = *(const float2*)(z + ((R0 + r) & 63) * Z_D + k2);
    *(float2*)(g_y + (size_t)(R0 + r) * Z_D + k2) = zz;
  }
  __syncthreads();

  for (int step = 0; step < N_STEPS; step++) {
    float s0 = step * DT_F;
    for (int st = 0; st < 6; st++) {
      float tst = s0 + cC[st] * DT_F;
      // ---- build stage input into split A (96 x 128) ----
      for (int p = tid; p < 96 * 64; p += 384) {
        int r = p >> 6, k2 = (p & 63) * 2;
        size_t gi = (size_t)(R0 + r) * Z_D + k2;
        float2 v = *(const float2*)(g_y + gi);
        #pragma unroll 1
        for (int j = 0; j < st; j++) {
          float2 kk = *(const float2*)(&g_k[j][gi]);
          float cj = DT_F * cA[st][j];
          v.x += cj * kk.x; v.y += cj * kk.y;
        }
        float tr = tst * rat[r];
        v.x += __cosf(fmaf(tr, wts[k2], bts[k2]));
        v.y += __cosf(fmaf(tr, wts[k2 + 1], bts[k2 + 1]));
        uint32_t hp; CVT_BF2(hp, v.x, v.y);
        __nv_bfloat162 hb = *reinterpret_cast<__nv_bfloat162*>(&hp);
        uint32_t lp; CVT_BF2(lp, v.x - __bfloat162float(hb.x), v.y - __bfloat162float(hb.y));
        uint32_t off = (uint32_t)((r * 264 + k2) * 2);
        asm volatile("st.shared.b32 [%0], %1;" :: "r"(a0b + off), "r"(hp) : "memory");
        asm volatile("st.shared.b32 [%0], %1;" :: "r"(a1b + off), "r"(lp) : "memory");
      }
      __syncthreads();
      {   // layer 1: K=128 -> N=256, tanh
        float c[16][4];
        init_bias_frag<16>(c, b1s, ng * 128, lane);
        layer_mma<16, 4, 256>(g_ws0 + OFF_W1, g_ws1 + OFF_W1, 128,
                              a0b, a1b, wbuf, ng * 128, mg, lane, tid, c);
        epi_tanh<16>(c, a0b, a1b, ng * 128, mg, lane);
      }
      __syncthreads();
      {   // layer 2: K=256 -> N=256, tanh
        float c[16][4];
        init_bias_frag<16>(c, b2s, ng * 128, lane);
        layer_mma<16, 8, 256>(g_ws0 + OFF_W2, g_ws1 + OFF_W2, 256,
                              a0b, a1b, wbuf, ng * 128, mg, lane, tid, c);
        epi_tanh<16>(c, a0b, a1b, ng * 128, mg, lane);
      }
      __syncthreads();
      {   // layer 3: K=256 -> N=128, * ratio -> g_k[st]
        float c[8][4];
        init_bias_frag<8>(c, b3s, ng * 64, lane);
        layer_mma<8, 8, 128>(g_ws0 + OFF_W3, g_ws1 + OFF_W3, 256,
                             a0b, a1b, wbuf, ng * 64, mg, lane, tid, c);
        int row = 16 * mg + (lane >> 2);
        #pragma unroll
        for (int nt = 0; nt < 8; nt++) {
          int col = ng * 64 + nt * 8 + (lane & 3) * 2;
          #pragma unroll
          for (int h = 0; h < 2; h++) {
            int rr = row + 8 * h;
            float sc = rat[rr];
            float2 v = make_float2(c[nt][2 * h] * sc, c[nt][2 * h + 1] * sc);
            *(float2*)(&g_k[st][(size_t)(R0 + rr) * Z_D + col]) = v;
          }
        }
      }
      __syncthreads();
    }
    // ---- y += dt * sum bw_j k_j ----
    for (int p = tid; p < 96 * 64; p += 384) {
      int r = p >> 6, k2 = (p & 63) * 2;
      size_t gi = (size_t)(R0 + r) * Z_D + k2;
      float2 y = *(float2*)(g_y + gi);
      float2 k0 = *(const float2*)(&g_k[0][gi]);
      float2 q2 = *(const float2*)(&g_k[2][gi]);
      float2 q3 = *(const float2*)(&g_k[3][gi]);
      float2 q4 = *(const float2*)(&g_k[4][gi]);
      float2 q5 = *(const float2*)(&g_k[5][gi]);
      const float w0 = 35.f/384.f, w2 = 500.f/1113.f, w3 = 125.f/192.f,
                  w4 = -2187.f/6784.f, w5 = 11.f/84.f;
      y.x += DT_F * (w0*k0.x + w2*q2.x + w3*q3.x + w4*q4.x + w5*q5.x);
      y.y += DT_F * (w0*k0.y + w2*q2.y + w3*q3.y + w4*q4.y + w5*q5.y);
      *(float2*)(g_y + gi) = y;
    }
    __syncthreads();
  }
}

// ---------------- decode_fc ----------------
__global__ void __launch_bounds__(256) dec_kernel(
    const float* __restrict__ x, const float* __restrict__ Wd, const float* __restrict__ bd) {
  __shared__ float xs[172];
  __shared__ float ys[64 * 128];
  const int tid = threadIdx.x;
  const int b = blockIdx.x, R0 = b * 64;
  for (int i = tid; i < 172; i += 256) xs[i] = x[(size_t)b * 172 + i];
  for (int i = tid; i < 64 * 128; i += 256) ys[i] = g_y[(size_t)R0 * 128 + i];
  __syncthreads();
  float acc0 = bd[tid];
  #pragma unroll 4
  for (int k = 0; k < 172; k++) acc0 = fmaf(xs[k], Wd[(size_t)k * 256 + tid], acc0);
  float acc[64];
  #pragma unroll
  for (int r = 0; r < 64; r++) acc[r] = acc0;
  #pragma unroll 2
  for (int k = 0; k < 128; k++) {
    float w = Wd[(size_t)(172 + k) * 256 + tid];
    #pragma unroll
    for (int r = 0; r < 64; r++) acc[r] = fmaf(ys[r * 128 + k], w, acc[r]);
  }
  #pragma unroll
  for (int r = 0; r < 64; r++) g_h[(size_t)(R0 + r) * 256 + tid] = acc[r];
}

// ---------------- src/dst fc ----------------
__global__ void __launch_bounds__(256) sd_kernel(
    const float* __restrict__ Ws, const float* __restrict__ bs,
    const float* __restrict__ Wdst, const float* __restrict__ bdst) {
  __shared__ float hs[32 * 256];
  const int tid = threadIdx.x;
  const int R0 = blockIdx.x * 32;
  const float* W = (R0 < 4096) ? Ws : Wdst;
  const float* bb = (R0 < 4096) ? bs : bdst;
  for (int i = tid; i < 32 * 256; i += 256) hs[i] = g_h[(size_t)R0 * 256 + i];
  __syncthreads();
  float acc[32];
  float b0 = bb[tid];
  #pragma unroll
  for (int r = 0; r < 32; r++) acc[r] = b0;
  #pragma unroll 2
  for (int k = 0; k < 256; k++) {
    float w = W[(size_t)k * 256 + tid];
    #pragma unroll
    for (int r = 0; r < 32; r++) acc[r] = fmaf(hs[r * 256 + k], w, acc[r]);
  }
  #pragma unroll
  for (int r = 0; r < 32; r++) g_s[(size_t)(R0 + r) * 256 + tid] = acc[r];
}

// ---------------- edge out + mean over L ----------------
__global__ void __launch_bounds__(256) edge_kernel(
    const float* __restrict__ Wo, const float* __restrict__ bo, float* __restrict__ out) {
  __shared__ float red[8];
  const int tid = threadIdx.x;
  const int o = blockIdx.x;
  const int b = (o < 64) ? o : (o - 64);
  const size_t off2 = (o < 64) ? (size_t)4096 * H_D : (size_t)8192 * H_D;
  const float wcol = Wo[tid];
  float sum = 0.f;
  for (int l = 0; l < 64; l++) {
    size_t r1 = (size_t)(b * 64 + l) * H_D + tid;
    float v = g_s[r1] + g_s[off2 + r1];
    sum += fmaxf(v, 0.f) * wcol;
  }
  #pragma unroll
  for (int d = 16; d > 0; d >>= 1) sum += __shfl_xor_sync(0xFFFFFFFFu, sum, d);
  if ((tid & 31) == 0) red[tid >> 5] = sum;
  __syncthreads();
  if (tid == 0) {
    float t = 0.f;
    #pragma unroll
    for (int w = 0; w < 8; w++) t += red[w];
    out[o] = t * (1.f / 64.f) + bo[0];
  }
}

extern "C" void kernel_launch(void* const* d_in, const int* in_sizes, int n_in,
                              void* d_out, int out_size) {
  const float* x    = (const float*)d_in[0];
  const float* z    = (const float*)d_in[1];
  const float* ts   = (const float*)d_in[2];
  const float* w_t  = (const float*)d_in[3];
  const float* b_t  = (const float*)d_in[4];
  const float* W1   = (const float*)d_in[5];
  const float* b1   = (const float*)d_in[6];
  const float* W2   = (const float*)d_in[7];
  const float* b2   = (const float*)d_in[8];
  const float* W3   = (const float*)d_in[9];
  const float* b3   = (const float*)d_in[10];
  const float* Wd   = (const float*)d_in[11];
  const float* bd   = (const float*)d_in[12];
  const float* Ws   = (const float*)d_in[13];
  const float* bs   = (const float*)d_in[14];
  const float* Wdst = (const float*)d_in[15];
  const float* bdst = (const float*)d_in[16];
  const float* Wo   = (const float*)d_in[17];
  const float* bo   = (const float*)d_in[18];
  float* out = (float*)d_out;

  cudaFuncSetAttribute(ode_kernel, cudaFuncAttributeMaxDynamicSharedMemorySize, SM_ODE);

  prep_kernel<<<512, 256>>>(W1, W2, W3);
  ode_kernel<<<128, 384, SM_ODE>>>(z, ts, w_t, b_t, b1, b2, b3);
  dec_kernel<<<192, 256>>>(x, Wd, bd);
  sd_kernel<<<384, 256>>>(Ws, bs, Wdst, bdst);
  edge_kernel<<<128, 256>>>(Wo, bo, out);
}

// round 8
// speedup vs baseline: 3.7313x; 1.7669x over previous
#include <cuda_runtime.h>
#include <cuda_fp16.h>
#include <cstdint>

#define N_ROWS 12288
#define Z_D 128
#define H_D 256
#define N_STEPS 8
#define DT_F 0.125f

__device__ float g_k[6][N_ROWS * Z_D];
__device__ float g_y[N_ROWS * Z_D];
__device__ float g_h[N_ROWS * H_D];
__device__ float g_s[N_ROWS * H_D];
__device__ __half g_wh[131072];
#define OFF_W1 0
#define OFF_W2 32768
#define OFF_W3 98304

__constant__ float cA[6][5] = {
  {0.f,0.f,0.f,0.f,0.f},
  {0.2f,0.f,0.f,0.f,0.f},
  {3.f/40.f,9.f/40.f,0.f,0.f,0.f},
  {44.f/45.f,-56.f/15.f,32.f/9.f,0.f,0.f},
  {19372.f/6561.f,-25360.f/2187.f,64448.f/6561.f,-212.f/729.f,0.f},
  {9017.f/3168.f,-355.f/33.f,46732.f/5247.f,49.f/176.f,-5103.f/18656.f}
};
__constant__ float cC[6] = {0.f,0.2f,0.3f,0.8f,8.f/9.f,1.f};

// ---------------- helpers ----------------
__device__ __forceinline__ uint32_t smem_u32(const void* p) {
  uint32_t a;
  asm("{ .reg .u64 t; cvta.to.shared.u64 t, %1; cvt.u32.u64 %0, t; }" : "=r"(a) : "l"(p));
  return a;
}
#define CVT_H2(res, lo, hi) \
  asm("cvt.rn.f16x2.f32 %0, %1, %2;" : "=r"(res) : "f"(hi), "f"(lo))
#define CP16(dst, src) \
  asm volatile("cp.async.cg.shared.global [%0], [%1], 16;" :: "r"(dst), "l"(src) : "memory")
#define CP_COMMIT() asm volatile("cp.async.commit_group;" ::: "memory")

__device__ __forceinline__ void mma_f16(float* c, const uint32_t* a, const uint32_t* b) {
  asm volatile(
    "mma.sync.aligned.m16n8k16.row.col.f32.f16.f16.f32 "
    "{%0,%1,%2,%3}, {%4,%5,%6,%7}, {%8,%9}, {%0,%1,%2,%3};"
    : "+f"(c[0]), "+f"(c[1]), "+f"(c[2]), "+f"(c[3])
    : "r"(a[0]), "r"(a[1]), "r"(a[2]), "r"(a[3]), "r"(b[0]), "r"(b[1]));
}
__device__ __forceinline__ void ldm4(uint32_t* r, uint32_t addr) {
  asm volatile("ldmatrix.sync.aligned.m8n8.x4.shared.b16 {%0,%1,%2,%3}, [%4];"
    : "=r"(r[0]), "=r"(r[1]), "=r"(r[2]), "=r"(r[3]) : "r"(addr));
}
__device__ __forceinline__ float tanh_fast(float x) {
  float e = __expf(2.f * x);
  return 1.f - __fdividef(2.f, e + 1.f);
}

// ---- smem layout (bytes). A: 96 rows x 264 halves (528 B stride) = 50688.
//      W chunk buffers: 256 rows x 72 halves (144 B stride) = 36864 each, x2.
#define SO_A0   0
#define SO_W0   50688
#define SO_W1   87552
#define SO_B1S  124416
#define SO_B2S  125440
#define SO_B3S  126464
#define SO_WTS  126976
#define SO_BTS  127488
#define SO_RAT  128000
#define SM_ODE  128384

// ---------------- weight prep: fp32 -> fp16, transpose to [N][K] ----------------
__global__ void prep_kernel(const float* __restrict__ W1, const float* __restrict__ W2,
                            const float* __restrict__ W3) {
  int i = blockIdx.x * 256 + threadIdx.x;
  float w; int dst;
  if (i < 32768)      { int n = i >> 7, k = i & 127;                w = W1[k * 256 + n]; dst = OFF_W1 + i; }
  else if (i < 98304) { int e = i - 32768; int n = e >> 8, k = e & 255; w = W2[k * 256 + n]; dst = OFF_W2 + e; }
  else                { int e = i - 98304; int n = e >> 8, k = e & 255; w = W3[k * 128 + n]; dst = OFF_W3 + e; }
  g_wh[dst] = __float2half_rn(w);
}

// ---------------- one MLP layer: fp16 HMMA, double-buffered 64-K chunks ----------------
// Warp (mg, ng): rows 16*mg..+15, cols ncb..ncb+8*NT-1. c[NT][4] bias-preloaded.
template<int NT, int NCH, int NW>
__device__ __forceinline__ void layer_mma(
    const __half* __restrict__ w0, int Kfull,
    uint32_t a0b, const uint32_t* wbuf,
    int ncb, int mg, int lane, int tid, float (*c)[4]) {
  auto issue = [&](int cidx) {
    uint32_t wb = wbuf[cidx & 1];
    for (int i = tid; i < NW * 8; i += 384) {
      int n = i >> 3, q = i & 7;
      CP16(wb + (uint32_t)(n * 144 + q * 16), w0 + (size_t)n * Kfull + cidx * 64 + q * 8);
    }
    CP_COMMIT();
  };
  issue(0);
  #pragma unroll 1
  for (int ck = 0; ck < NCH; ck++) {
    if (ck + 1 < NCH) {
      issue(ck + 1);
      asm volatile("cp.async.wait_group 1;" ::: "memory");
    } else {
      asm volatile("cp.async.wait_group 0;" ::: "memory");
    }
    __syncthreads();
    uint32_t wb = wbuf[ck & 1];
    #pragma unroll
    for (int ks = 0; ks < 4; ks++) {
      int m = lane >> 3, ri = lane & 7;
      int row = 16 * mg + (m & 1) * 8 + ri;
      int kcol = ck * 64 + ks * 16 + (m >> 1) * 8;
      uint32_t aoff = (uint32_t)(row * 528 + kcol * 2);
      uint32_t a0f[4];
      ldm4(a0f, a0b + aoff);
      int g = lane >> 3, rr = lane & 7;
      #pragma unroll
      for (int nt2 = 0; nt2 < NT / 2; nt2++) {
        int n = ncb + nt2 * 16 + (g >> 1) * 8 + rr;
        uint32_t boff = (uint32_t)(n * 144 + (ks * 16 + (g & 1) * 8) * 2);
        uint32_t rb[4];
        ldm4(rb, wb + boff);
        mma_f16(c[nt2 * 2],     a0f, rb);
        mma_f16(c[nt2 * 2 + 1], a0f, rb + 2);
      }
    }
    __syncthreads();
  }
}

template<int NT>
__device__ __forceinline__ void init_bias_frag(float (*c)[4], const float* bias, int ncb, int lane) {
  #pragma unroll
  for (int nt = 0; nt < NT; nt++) {
    int cc = ncb + nt * 8 + (lane & 3) * 2;
    float b0 = bias[cc], b1 = bias[cc + 1];
    c[nt][0] = b0; c[nt][1] = b1; c[nt][2] = b0; c[nt][3] = b1;
  }
}

// tanh epilogue: C -> fp16 into A smem
template<int NT>
__device__ __forceinline__ void epi_tanh(float (*c)[4], uint32_t a0b,
                                         int ncb, int mg, int lane) {
  int row = 16 * mg + (lane >> 2);
  #pragma unroll
  for (int nt = 0; nt < NT; nt++) {
    int col = ncb + nt * 8 + (lane & 3) * 2;
    #pragma unroll
    for (int h = 0; h < 2; h++) {
      float t0 = tanh_fast(c[nt][2 * h]);
      float t1 = tanh_fast(c[nt][2 * h + 1]);
      uint32_t hp; CVT_H2(hp, t0, t1);
      uint32_t off = (uint32_t)(((row + 8 * h) * 264 + col) * 2);
      asm volatile("st.shared.b32 [%0], %1;" :: "r"(a0b + off), "r"(hp) : "memory");
    }
  }
}

extern __shared__ char smem_raw[];

__global__ void __launch_bounds__(384, 1) ode_kernel(
    const float* __restrict__ z, const float* __restrict__ ts,
    const float* __restrict__ w_t, const float* __restrict__ b_t,
    const float* __restrict__ b1, const float* __restrict__ b2, const float* __restrict__ b3) {
  const uint32_t base = smem_u32(smem_raw);
  float* b1s = (float*)(smem_raw + SO_B1S);
  float* b2s = (float*)(smem_raw + SO_B2S);
  float* b3s = (float*)(smem_raw + SO_B3S);
  float* wts = (float*)(smem_raw + SO_WTS);
  float* bts = (float*)(smem_raw + SO_BTS);
  float* rat = (float*)(smem_raw + SO_RAT);
  const uint32_t a0b = base + SO_A0;
  const uint32_t wbuf[2] = {base + SO_W0, base + SO_W1};
  const int tid = threadIdx.x;
  const int lane = tid & 31, w = tid >> 5;
  const int mg = w >> 1, ng = w & 1;   // mg 0..5 (16 rows), ng 0..1
  const int R0 = blockIdx.x * 96;

  if (tid < 96) rat[tid] = ts[R0 + tid];
  if (tid < 128) {
    wts[tid] = w_t[tid];
    bts[tid] = b_t[tid];
    b3s[tid] = b3[tid];
  }
  if (tid < 256) { b1s[tid] = b1[tid]; b2s[tid] = b2[tid]; }
  for (int p = tid; p < 96 * 64; p += 384) {
    int r = p >> 6, k2 = (p & 63) * 2;
    float2 zz = *(const float2*)(z + ((R0 + r) & 63) * Z_D + k2);
    *(float2*)(g_y + (size_t)(R0 + r) * Z_D + k2) = zz;
  }
  __syncthreads();

  for (int step = 0; step < N_STEPS; step++) {
    float s0 = step * DT_F;
    for (int st = 0; st < 6; st++) {
      float tst = s0 + cC[st] * DT_F;
      // ---- build stage input into fp16 A (96 x 128) ----
      for (int p = tid; p < 96 * 64; p += 384) {
        int r = p >> 6, k2 = (p & 63) * 2;
        size_t gi = (size_t)(R0 + r) * Z_D + k2;
        float2 v = *(const float2*)(g_y + gi);
        #pragma unroll 1
        for (int j = 0; j < st; j++) {
          float2 kk = *(const float2*)(&g_k[j][gi]);
          float cj = DT_F * cA[st][j];
          v.x += cj * kk.x; v.y += cj * kk.y;
        }
        float tr = tst * rat[r];
        v.x += __cosf(fmaf(tr, wts[k2], bts[k2]));
        v.y += __cosf(fmaf(tr, wts[k2 + 1], bts[k2 + 1]));
        uint32_t hp; CVT_H2(hp, v.x, v.y);
        uint32_t off = (uint32_t)((r * 264 + k2) * 2);
        asm volatile("st.shared.b32 [%0], %1;" :: "r"(a0b + off), "r"(hp) : "memory");
      }
      __syncthreads();
      {   // layer 1: K=128 -> N=256, tanh
        float c[16][4];
        init_bias_frag<16>(c, b1s, ng * 128, lane);
        layer_mma<16, 2, 256>(g_wh + OFF_W1, 128, a0b, wbuf, ng * 128, mg, lane, tid, c);
        epi_tanh<16>(c, a0b, ng * 128, mg, lane);
      }
      __syncthreads();
      {   // layer 2: K=256 -> N=256, tanh
        float c[16][4];
        init_bias_frag<16>(c, b2s, ng * 128, lane);
        layer_mma<16, 4, 256>(g_wh + OFF_W2, 256, a0b, wbuf, ng * 128, mg, lane, tid, c);
        epi_tanh<16>(c, a0b, ng * 128, mg, lane);
      }
      __syncthreads();
      {   // layer 3: K=256 -> N=128, * ratio -> g_k[st]
        float c[8][4];
        init_bias_frag<8>(c, b3s, ng * 64, lane);
        layer_mma<8, 4, 128>(g_wh + OFF_W3, 256, a0b, wbuf, ng * 64, mg, lane, tid, c);
        int row = 16 * mg + (lane >> 2);
        #pragma unroll
        for (int nt = 0; nt < 8; nt++) {
          int col = ng * 64 + nt * 8 + (lane & 3) * 2;
          #pragma unroll
          for (int h = 0; h < 2; h++) {
            int rr = row + 8 * h;
            float sc = rat[rr];
            float2 v = make_float2(c[nt][2 * h] * sc, c[nt][2 * h + 1] * sc);
            *(float2*)(&g_k[st][(size_t)(R0 + rr) * Z_D + col]) = v;
          }
        }
      }
      __syncthreads();
    }
    // ---- y += dt * sum bw_j k_j ----
    for (int p = tid; p < 96 * 64; p += 384) {
      int r = p >> 6, k2 = (p & 63) * 2;
      size_t gi = (size_t)(R0 + r) * Z_D + k2;
      float2 y = *(float2*)(g_y + gi);
      float2 k0 = *(const float2*)(&g_k[0][gi]);
      float2 q2 = *(const float2*)(&g_k[2][gi]);
      float2 q3 = *(const float2*)(&g_k[3][gi]);
      float2 q4 = *(const float2*)(&g_k[4][gi]);
      float2 q5 = *(const float2*)(&g_k[5][gi]);
      const float w0 = 35.f/384.f, w2 = 500.f/1113.f, w3 = 125.f/192.f,
                  w4 = -2187.f/6784.f, w5 = 11.f/84.f;
      y.x += DT_F * (w0*k0.x + w2*q2.x + w3*q3.x + w4*q4.x + w5*q5.x);
      y.y += DT_F * (w0*k0.y + w2*q2.y + w3*q3.y + w4*q4.y + w5*q5.y);
      *(float2*)(g_y + gi) = y;
    }
    __syncthreads();
  }
}

// ---------------- decode_fc ----------------
__global__ void __launch_bounds__(256) dec_kernel(
    const float* __restrict__ x, const float* __restrict__ Wd, const float* __restrict__ bd) {
  __shared__ float xs[172];
  __shared__ float ys[64 * 128];
  const int tid = threadIdx.x;
  const int b = blockIdx.x, R0 = b * 64;
  for (int i = tid; i < 172; i += 256) xs[i] = x[(size_t)b * 172 + i];
  for (int i = tid; i < 64 * 128; i += 256) ys[i] = g_y[(size_t)R0 * 128 + i];
  __syncthreads();
  float acc0 = bd[tid];
  #pragma unroll 4
  for (int k = 0; k < 172; k++) acc0 = fmaf(xs[k], Wd[(size_t)k * 256 + tid], acc0);
  float acc[64];
  #pragma unroll
  for (int r = 0; r < 64; r++) acc[r] = acc0;
  #pragma unroll 2
  for (int k = 0; k < 128; k++) {
    float w = Wd[(size_t)(172 + k) * 256 + tid];
    #pragma unroll
    for (int r = 0; r < 64; r++) acc[r] = fmaf(ys[r * 128 + k], w, acc[r]);
  }
  #pragma unroll
  for (int r = 0; r < 64; r++) g_h[(size_t)(R0 + r) * 256 + tid] = acc[r];
}

// ---------------- src/dst fc ----------------
__global__ void __launch_bounds__(256) sd_kernel(
    const float* __restrict__ Ws, const float* __restrict__ bs,
    const float* __restrict__ Wdst, const float* __restrict__ bdst) {
  __shared__ float hs[32 * 256];
  const int tid = threadIdx.x;
  const int R0 = blockIdx.x * 32;
  const float* W = (R0 < 4096) ? Ws : Wdst;
  const float* bb = (R0 < 4096) ? bs : bdst;
  for (int i = tid; i < 32 * 256; i += 256) hs[i] = g_h[(size_t)R0 * 256 + i];
  __syncthreads();
  float acc[32];
  float b0 = bb[tid];
  #pragma unroll
  for (int r = 0; r < 32; r++) acc[r] = b0;
  #pragma unroll 2
  for (int k = 0; k < 256; k++) {
    float w = W[(size_t)k * 256 + tid];
    #pragma unroll
    for (int r = 0; r < 32; r++) acc[r] = fmaf(hs[r * 256 + k], w, acc[r]);
  }
  #pragma unroll
  for (int r = 0; r < 32; r++) g_s[(size_t)(R0 + r) * 256 + tid] = acc[r];
}

// ---------------- edge out + mean over L ----------------
__global__ void __launch_bounds__(256) edge_kernel(
    const float* __restrict__ Wo, const float* __restrict__ bo, float* __restrict__ out) {
  __shared__ float red[8];
  const int tid = threadIdx.x;
  const int o = blockIdx.x;
  const int b = (o < 64) ? o : (o - 64);
  const size_t off2 = (o < 64) ? (size_t)4096 * H_D : (size_t)8192 * H_D;
  const float wcol = Wo[tid];
  float sum = 0.f;
  for (int l = 0; l < 64; l++) {
    size_t r1 = (size_t)(b * 64 + l) * H_D + tid;
    float v = g_s[r1] + g_s[off2 + r1];
    sum += fmaxf(v, 0.f) * wcol;
  }
  #pragma unroll
  for (int d = 16; d > 0; d >>= 1) sum += __shfl_xor_sync(0xFFFFFFFFu, sum, d);
  if ((tid & 31) == 0) red[tid >> 5] = sum;
  __syncthreads();
  if (tid == 0) {
    float t = 0.f;
    #pragma unroll
    for (int w = 0; w < 8; w++) t += red[w];
    out[o] = t * (1.f / 64.f) + bo[0];
  }
}

extern "C" void kernel_launch(void* const* d_in, const int* in_sizes, int n_in,
                              void* d_out, int out_size) {
  const float* x    = (const float*)d_in[0];
  const float* z    = (const float*)d_in[1];
  const float* ts   = (const float*)d_in[2];
  const float* w_t  = (const float*)d_in[3];
  const float* b_t  = (const float*)d_in[4];
  const float* W1   = (const float*)d_in[5];
  const float* b1   = (const float*)d_in[6];
  const float* W2   = (const float*)d_in[7];
  const float* b2   = (const float*)d_in[8];
  const float* W3   = (const float*)d_in[9];
  const float* b3   = (const float*)d_in[10];
  const float* Wd   = (const float*)d_in[11];
  const float* bd   = (const float*)d_in[12];
  const float* Ws   = (const float*)d_in[13];
  const float* bs   = (const float*)d_in[14];
  const float* Wdst = (const float*)d_in[15];
  const float* bdst = (const float*)d_in[16];
  const float* Wo   = (const float*)d_in[17];
  const float* bo   = (const float*)d_in[18];
  float* out = (float*)d_out;

  cudaFuncSetAttribute(ode_kernel, cudaFuncAttributeMaxDynamicSharedMemorySize, SM_ODE);

  prep_kernel<<<512, 256>>>(W1, W2, W3);
  ode_kernel<<<128, 384, SM_ODE>>>(z, ts, w_t, b_t, b1, b2, b3);
  dec_kernel<<<192, 256>>>(x, Wd, bd);
  sd_kernel<<<384, 256>>>(Ws, bs, Wdst, bdst);
  edge_kernel<<<128, 256>>>(Wo, bo, out);
}

// round 9
// speedup vs baseline: 4.2247x; 1.1322x over previous
#include <cuda_runtime.h>
#include <cuda_fp16.h>
#include <cstdint>

#define N_ROWS 12288
#define Z_D 128
#define H_D 256
#define N_STEPS 8
#define DT_F 0.125f

__device__ float g_k[6][N_ROWS * Z_D];
__device__ float g_y[N_ROWS * Z_D];
__device__ float g_h[N_ROWS * H_D];
__device__ float g_s[N_ROWS * H_D];
// chunk-major swizzled fp16 weights: W1 | W2c0 | W2c1 | W3 (4 x 32768 halves = 4 x 64 KB)
__device__ __half g_wh[131072];
#define HW1  0
#define HW2A 32768
#define HW2B 65536
#define HW3  98304

__constant__ float cA[6][5] = {
  {0.f,0.f,0.f,0.f,0.f},
  {0.2f,0.f,0.f,0.f,0.f},
  {3.f/40.f,9.f/40.f,0.f,0.f,0.f},
  {44.f/45.f,-56.f/15.f,32.f/9.f,0.f,0.f},
  {19372.f/6561.f,-25360.f/2187.f,64448.f/6561.f,-212.f/729.f,0.f},
  {9017.f/3168.f,-355.f/33.f,46732.f/5247.f,49.f/176.f,-5103.f/18656.f}
};
__constant__ float cC[6] = {0.f,0.2f,0.3f,0.8f,8.f/9.f,1.f};

// ---------------- helpers ----------------
__device__ __forceinline__ uint32_t smem_u32(const void* p) {
  uint32_t a;
  asm("{ .reg .u64 t; cvta.to.shared.u64 t, %1; cvt.u32.u64 %0, t; }" : "=r"(a) : "l"(p));
  return a;
}
#define CVT_H2(res, lo, hi) \
  asm("cvt.rn.f16x2.f32 %0, %1, %2;" : "=r"(res) : "f"(hi), "f"(lo))

__device__ __forceinline__ void mma_f16(float* c, const uint32_t* a, const uint32_t* b) {
  asm volatile(
    "mma.sync.aligned.m16n8k16.row.col.f32.f16.f16.f32 "
    "{%0,%1,%2,%3}, {%4,%5,%6,%7}, {%8,%9}, {%0,%1,%2,%3};"
    : "+f"(c[0]), "+f"(c[1]), "+f"(c[2]), "+f"(c[3])
    : "r"(a[0]), "r"(a[1]), "r"(a[2]), "r"(a[3]), "r"(b[0]), "r"(b[1]));
}
__device__ __forceinline__ void ldm4(uint32_t* r, uint32_t addr) {
  asm volatile("ldmatrix.sync.aligned.m8n8.x4.shared.b16 {%0,%1,%2,%3}, [%4];"
    : "=r"(r[0]), "=r"(r[1]), "=r"(r[2]), "=r"(r[3]) : "r"(addr));
}
__device__ __forceinline__ float tanh_fast(float x) {
  float e = __expf(2.f * x);
  return 1.f - __fdividef(2.f, e + 1.f);
}

#define MBAR_INIT(mbar, cnt) \
  asm volatile("mbarrier.init.shared.b64 [%0], %1;" :: "r"(mbar), "r"(cnt) : "memory")
#define MBAR_EXPECT(mbar, bytes) \
  asm volatile("mbarrier.arrive.expect_tx.shared.b64 _, [%0], %1;" :: "r"(mbar), "r"(bytes) : "memory")
#define MBAR_WAIT(mbar, par) do { \
  uint32_t _m = (mbar), _p = (par), _d; \
  asm volatile("{\n\t.reg .pred p;\n\tmbarrier.try_wait.parity.acquire.cta.shared::cta.b64 p, [%1], %2;\n\tselp.b32 %0, 1, 0, p;\n\t}" \
    : "=r"(_d) : "r"(_m), "r"(_p) : "memory"); \
  if (!_d) { \
    asm volatile("{\n\t.reg .pred P1;\n\tWL_%=:\n\tmbarrier.try_wait.parity.acquire.cta.shared::cta.b64 P1, [%0], %1, 0x989680;\n\t@P1 bra.uni WD_%=;\n\tbra.uni WL_%=;\n\tWD_%=:\n\t}" \
      :: "r"(_m), "r"(_p) : "memory"); \
  } \
} while (0)
#define BULK_LOAD(dst, src, bytes, mbar) \
  asm volatile("cp.async.bulk.shared::cluster.global.mbarrier::complete_tx::bytes [%0], [%1], %2, [%3];" \
    :: "r"(dst), "l"(src), "r"(bytes), "r"(mbar) : "memory")

// ---- smem layout (bytes): A swizzled 96x512B; two 64KB weight buffers.
#define SO_A    0
#define SO_B0   49152
#define SO_B1   114688
#define SO_B1S  180224
#define SO_B2S  181248
#define SO_B3S  182272
#define SO_WTS  182784
#define SO_BTS  183296
#define SO_RAT  183808
#define SO_MB   184192
#define SM_ODE  184320

// ---------------- weight prep: fp32 -> fp16, chunk-major + XOR-granule swizzle ----------------
__global__ void prep_kernel(const float* __restrict__ W1, const float* __restrict__ W2,
                            const float* __restrict__ W3) {
  int i = blockIdx.x * 256 + threadIdx.x;
  if (i < 32768) {                       // W1 [N=256][K=128], row 256B (16 granules)
    int n = i >> 7, k = i & 127;
    int dst = HW1 + n * 128 + (((k >> 3) ^ (n & 7)) << 3) + (k & 7);
    g_wh[dst] = __float2half_rn(W1[k * 256 + n]);
  } else if (i < 98304) {                // W2 [N=256][K=256] split in two 128-K chunks
    int e = i - 32768; int n = e >> 8, k = e & 255;
    int c = k >> 7, kl = k & 127;
    int dst = HW2A + c * 32768 + n * 128 + (((kl >> 3) ^ (n & 7)) << 3) + (k & 7);
    g_wh[dst] = __float2half_rn(W2[k * 256 + n]);
  } else {                               // W3 [N=128][K=256], row 512B (32 granules)
    int e = i - 98304; int n = e >> 8, k = e & 255;
    int dst = HW3 + n * 256 + (((k >> 3) ^ (n & 7)) << 3) + (k & 7);
    g_wh[dst] = __float2half_rn(W3[k * 128 + n]);
  }
}

// ---------------- MMA span over a resident B buffer ----------------
// rbshift: 8 for 256B B-rows (K=128 chunk), 9 for 512B (W3 K=256).
template<int NT, int NKS>
__device__ __forceinline__ void mma_span(
    uint32_t ab, uint32_t bb, int kbaseA, int rbshift,
    int ncb, int mg, int lane, float (*c)[4]) {
  int m = lane >> 3;
  int row = 16 * mg + (m & 1) * 8 + (lane & 7);
  int g = lane >> 3, rr = lane & 7;
  #pragma unroll
  for (int ks = 0; ks < NKS; ks++) {
    int kcolA = kbaseA + ks * 16 + (m >> 1) * 8;
    uint32_t aoff = (uint32_t)((row << 9) + ((((kcolA >> 3) ^ (row & 7))) << 4));
    uint32_t af[4];
    ldm4(af, ab + aoff);
    int kcolB = ks * 16 + (g & 1) * 8;
    #pragma unroll
    for (int nt2 = 0; nt2 < NT / 2; nt2++) {
      int n = ncb + nt2 * 16 + (g >> 1) * 8 + rr;
      uint32_t boff = (uint32_t)((n << rbshift) + ((((kcolB >> 3) ^ (n & 7))) << 4));
      uint32_t rb[4];
      ldm4(rb, bb + boff);
      mma_f16(c[nt2 * 2],     af, rb);
      mma_f16(c[nt2 * 2 + 1], af, rb + 2);
    }
  }
}

template<int NT>
__device__ __forceinline__ void init_bias_frag(float (*c)[4], const float* bias, int ncb, int lane) {
  #pragma unroll
  for (int nt = 0; nt < NT; nt++) {
    int cc = ncb + nt * 8 + (lane & 3) * 2;
    float b0 = bias[cc], b1 = bias[cc + 1];
    c[nt][0] = b0; c[nt][1] = b1; c[nt][2] = b0; c[nt][3] = b1;
  }
}

// tanh epilogue: C -> fp16 into swizzled A
template<int NT>
__device__ __forceinline__ void epi_tanh(float (*c)[4], uint32_t ab,
                                         int ncb, int mg, int lane) {
  int row = 16 * mg + (lane >> 2);
  #pragma unroll
  for (int nt = 0; nt < NT; nt++) {
    int col = ncb + nt * 8 + (lane & 3) * 2;
    #pragma unroll
    for (int h = 0; h < 2; h++) {
      int rh = row + 8 * h;
      float t0 = tanh_fast(c[nt][2 * h]);
      float t1 = tanh_fast(c[nt][2 * h + 1]);
      uint32_t hp; CVT_H2(hp, t0, t1);
      uint32_t off = (uint32_t)((rh << 9) + ((((col >> 3) ^ (rh & 7))) << 4) + ((col & 7) << 1));
      asm volatile("st.shared.b32 [%0], %1;" :: "r"(ab + off), "r"(hp) : "memory");
    }
  }
}

extern __shared__ char smem_raw[];

__global__ void __launch_bounds__(384, 1) ode_kernel(
    const float* __restrict__ z, const float* __restrict__ ts,
    const float* __restrict__ w_t, const float* __restrict__ b_t,
    const float* __restrict__ b1, const float* __restrict__ b2, const float* __restrict__ b3) {
  const uint32_t base = smem_u32(smem_raw);
  float* b1s = (float*)(smem_raw + SO_B1S);
  float* b2s = (float*)(smem_raw + SO_B2S);
  float* b3s = (float*)(smem_raw + SO_B3S);
  float* wts = (float*)(smem_raw + SO_WTS);
  float* bts = (float*)(smem_raw + SO_BTS);
  float* rat = (float*)(smem_raw + SO_RAT);
  const uint32_t ab = base + SO_A;
  const uint32_t wb0 = base + SO_B0, wb1 = base + SO_B1;
  const uint32_t mb0 = base + SO_MB, mb1 = base + SO_MB + 8;
  const int tid = threadIdx.x;
  const int lane = tid & 31, w = tid >> 5;
  const int mg = w >> 1, ng = w & 1;   // mg 0..5 (16 rows), ng 0..1
  const int R0 = blockIdx.x * 96;

  if (tid < 96) rat[tid] = ts[R0 + tid];
  if (tid < 128) {
    wts[tid] = w_t[tid];
    bts[tid] = b_t[tid];
    b3s[tid] = b3[tid];
  }
  if (tid < 256) { b1s[tid] = b1[tid]; b2s[tid] = b2[tid]; }
  if (tid == 0) { MBAR_INIT(mb0, 1); MBAR_INIT(mb1, 1); }
  for (int p = tid; p < 96 * 64; p += 384) {
    int r = p >> 6, k2 = (p & 63) * 2;
    float2 zz = *(const float2*)(z + ((R0 + r) & 63) * Z_D + k2);
    *(float2*)(g_y + (size_t)(R0 + r) * Z_D + k2) = zz;
  }
  __syncthreads();
  // bootstrap loads: b0 <- W1, b1 <- W2c0
  if (tid == 0) {
    MBAR_EXPECT(mb0, 65536);
    BULK_LOAD(wb0, (const void*)(g_wh + HW1), 65536, mb0);
    MBAR_EXPECT(mb1, 65536);
    BULK_LOAD(wb1, (const void*)(g_wh + HW2A), 65536, mb1);
  }

  for (int step = 0; step < N_STEPS; step++) {
    float s0 = step * DT_F;
    for (int st = 0; st < 6; st++) {
      bool last = (step == N_STEPS - 1) && (st == 5);
      float tst = s0 + cC[st] * DT_F;
      // ---- build stage input into fp16 A[*, 0:128] ----
      for (int p = tid; p < 96 * 64; p += 384) {
        int r = p >> 6, k2 = (p & 63) * 2;
        size_t gi = (size_t)(R0 + r) * Z_D + k2;
        float2 v = *(const float2*)(g_y + gi);
        #pragma unroll 1
        for (int j = 0; j < st; j++) {
          float2 kk = *(const float2*)(&g_k[j][gi]);
          float cj = DT_F * cA[st][j];
          v.x += cj * kk.x; v.y += cj * kk.y;
        }
        float tr = tst * rat[r];
        v.x += __cosf(fmaf(tr, wts[k2], bts[k2]));
        v.y += __cosf(fmaf(tr, wts[k2 + 1], bts[k2 + 1]));
        uint32_t hp; CVT_H2(hp, v.x, v.y);
        uint32_t off = (uint32_t)((r << 9) + ((((k2 >> 3) ^ (r & 7))) << 4) + ((k2 & 7) << 1));
        asm volatile("st.shared.b32 [%0], %1;" :: "r"(ab + off), "r"(hp) : "memory");
      }
      MBAR_WAIT(mb0, 0);                 // W1 arrived
      __syncthreads();                   // A ready
      {   // layer 1: K=128 -> N=256, tanh
        float c[16][4];
        init_bias_frag<16>(c, b1s, ng * 128, lane);
        mma_span<16, 8>(ab, wb0, 0, 8, ng * 128, mg, lane, c);
        __syncthreads();                 // b0 + A reads done
        if (tid == 0) {
          MBAR_EXPECT(mb0, 65536);
          BULK_LOAD(wb0, (const void*)(g_wh + HW2B), 65536, mb0);
        }
        epi_tanh<16>(c, ab, ng * 128, mg, lane);
      }
      MBAR_WAIT(mb1, 0);                 // W2c0 arrived
      __syncthreads();                   // A epilogue done
      {   // layer 2: K=256 -> N=256 (two 128-K chunks), tanh
        float c[16][4];
        init_bias_frag<16>(c, b2s, ng * 128, lane);
        mma_span<16, 8>(ab, wb1, 0, 8, ng * 128, mg, lane, c);
        __syncthreads();                 // b1 reads done
        if (tid == 0) {
          MBAR_EXPECT(mb1, 65536);
          BULK_LOAD(wb1, (const void*)(g_wh + HW3), 65536, mb1);
        }
        MBAR_WAIT(mb0, 1);               // W2c1 arrived
        mma_span<16, 8>(ab, wb0, 128, 8, ng * 128, mg, lane, c);
        __syncthreads();                 // b0 reads done
        if (tid == 0 && !last) {
          MBAR_EXPECT(mb0, 65536);
          BULK_LOAD(wb0, (const void*)(g_wh + HW1), 65536, mb0);
        }
        epi_tanh<16>(c, ab, ng * 128, mg, lane);
      }
      MBAR_WAIT(mb1, 1);                 // W3 arrived
      __syncthreads();                   // A epilogue done
      {   // layer 3: K=256 -> N=128, * ratio -> g_k[st]
        float c[8][4];
        init_bias_frag<8>(c, b3s, ng * 64, lane);
        mma_span<8, 16>(ab, wb1, 0, 9, ng * 64, mg, lane, c);
        __syncthreads();                 // b1 + A reads done
        if (tid == 0 && !last) {
          MBAR_EXPECT(mb1, 65536);
          BULK_LOAD(wb1, (const void*)(g_wh + HW2A), 65536, mb1);
        }
        int row = 16 * mg + (lane >> 2);
        #pragma unroll
        for (int nt = 0; nt < 8; nt++) {
          int col = ng * 64 + nt * 8 + (lane & 3) * 2;
          #pragma unroll
          for (int h = 0; h < 2; h++) {
            int rr = row + 8 * h;
            float sc = rat[rr];
            float2 v = make_float2(c[nt][2 * h] * sc, c[nt][2 * h + 1] * sc);
            *(float2*)(&g_k[st][(size_t)(R0 + rr) * Z_D + col]) = v;
          }
        }
      }
      __syncthreads();                   // g_k visible for next build / y-update
    }
    // ---- y += dt * sum bw_j k_j ----
    for (int p = tid; p < 96 * 64; p += 384) {
      int r = p >> 6, k2 = (p & 63) * 2;
      size_t gi = (size_t)(R0 + r) * Z_D + k2;
      float2 y = *(float2*)(g_y + gi);
      float2 k0 = *(const float2*)(&g_k[0][gi]);
      float2 q2 = *(const float2*)(&g_k[2][gi]);
      float2 q3 = *(const float2*)(&g_k[3][gi]);
      float2 q4 = *(const float2*)(&g_k[4][gi]);
      float2 q5 = *(const float2*)(&g_k[5][gi]);
      const float w0 = 35.f/384.f, w2 = 500.f/1113.f, w3 = 125.f/192.f,
                  w4 = -2187.f/6784.f, w5 = 11.f/84.f;
      y.x += DT_F * (w0*k0.x + w2*q2.x + w3*q3.x + w4*q4.x + w5*q5.x);
      y.y += DT_F * (w0*k0.y + w2*q2.y + w3*q3.y + w4*q4.y + w5*q5.y);
      *(float2*)(g_y + gi) = y;
    }
    __syncthreads();
  }
}

// ---------------- decode_fc: 32 rows/block ----------------
__global__ void __launch_bounds__(256) dec_kernel(
    const float* __restrict__ x, const float* __restrict__ Wd, const float* __restrict__ bd) {
  __shared__ float xs[172];
  __shared__ float ys[32 * 128];
  const int tid = threadIdx.x;
  const int R0 = blockIdx.x * 32;
  const int b = R0 / 64;
  for (int i = tid; i < 172; i += 256) xs[i] = x[(size_t)b * 172 + i];
  for (int i = tid; i < 32 * 128; i += 256) ys[i] = g_y[(size_t)R0 * 128 + i];
  __syncthreads();
  float acc0 = bd[tid];
  #pragma unroll 4
  for (int k = 0; k < 172; k++) acc0 = fmaf(xs[k], Wd[(size_t)k * 256 + tid], acc0);
  float acc[32];
  #pragma unroll
  for (int r = 0; r < 32; r++) acc[r] = acc0;
  #pragma unroll 2
  for (int k = 0; k < 128; k++) {
    float w = Wd[(size_t)(172 + k) * 256 + tid];
    #pragma unroll
    for (int r = 0; r < 32; r++) acc[r] = fmaf(ys[r * 128 + k], w, acc[r]);
  }
  #pragma unroll
  for (int r = 0; r < 32; r++) g_h[(size_t)(R0 + r) * 256 + tid] = acc[r];
}

// ---------------- src/dst fc: 16 rows/block ----------------
__global__ void __launch_bounds__(256) sd_kernel(
    const float* __restrict__ Ws, const float* __restrict__ bs,
    const float* __restrict__ Wdst, const float* __restrict__ bdst) {
  __shared__ float hs[16 * 256];
  const int tid = threadIdx.x;
  const int R0 = blockIdx.x * 16;
  const float* W = (R0 < 4096) ? Ws : Wdst;
  const float* bb = (R0 < 4096) ? bs : bdst;
  for (int i = tid; i < 16 * 256; i += 256) hs[i] = g_h[(size_t)R0 * 256 + i];
  __syncthreads();
  float acc[16];
  float b0 = bb[tid];
  #pragma unroll
  for (int r = 0; r < 16; r++) acc[r] = b0;
  #pragma unroll 4
  for (int k = 0; k < 256; k++) {
    float w = W[(size_t)k * 256 + tid];
    #pragma unroll
    for (int r = 0; r < 16; r++) acc[r] = fmaf(hs[r * 256 + k], w, acc[r]);
  }
  #pragma unroll
  for (int r = 0; r < 16; r++) g_s[(size_t)(R0 + r) * 256 + tid] = acc[r];
}

// ---------------- edge out + mean over L ----------------
__global__ void __launch_bounds__(256) edge_kernel(
    const float* __restrict__ Wo, const float* __restrict__ bo, float* __restrict__ out) {
  __shared__ float red[8];
  const int tid = threadIdx.x;
  const int o = blockIdx.x;
  const int b = (o < 64) ? o : (o - 64);
  const size_t off2 = (o < 64) ? (size_t)4096 * H_D : (size_t)8192 * H_D;
  const float wcol = Wo[tid];
  float sum = 0.f;
  for (int l = 0; l < 64; l++) {
    size_t r1 = (size_t)(b * 64 + l) * H_D + tid;
    float v = g_s[r1] + g_s[off2 + r1];
    sum += fmaxf(v, 0.f) * wcol;
  }
  #pragma unroll
  for (int d = 16; d > 0; d >>= 1) sum += __shfl_xor_sync(0xFFFFFFFFu, sum, d);
  if ((tid & 31) == 0) red[tid >> 5] = sum;
  __syncthreads();
  if (tid == 0) {
    float t = 0.f;
    #pragma unroll
    for (int w = 0; w < 8; w++) t += red[w];
    out[o] = t * (1.f / 64.f) + bo[0];
  }
}

extern "C" void kernel_launch(void* const* d_in, const int* in_sizes, int n_in,
                              void* d_out, int out_size) {
  const float* x    = (const float*)d_in[0];
  const float* z    = (const float*)d_in[1];
  const float* ts   = (const float*)d_in[2];
  const float* w_t  = (const float*)d_in[3];
  const float* b_t  = (const float*)d_in[4];
  const float* W1   = (const float*)d_in[5];
  const float* b1   = (const float*)d_in[6];
  const float* W2   = (const float*)d_in[7];
  const float* b2   = (const float*)d_in[8];
  const float* W3   = (const float*)d_in[9];
  const float* b3   = (const float*)d_in[10];
  const float* Wd   = (const float*)d_in[11];
  const float* bd   = (const float*)d_in[12];
  const float* Ws   = (const float*)d_in[13];
  const float* bs   = (const float*)d_in[14];
  const float* Wdst = (const float*)d_in[15];
  const float* bdst = (const float*)d_in[16];
  const float* Wo   = (const float*)d_in[17];
  const float* bo   = (const float*)d_in[18];
  float* out = (float*)d_out;

  cudaFuncSetAttribute(ode_kernel, cudaFuncAttributeMaxDynamicSharedMemorySize, SM_ODE);

  prep_kernel<<<512, 256>>>(W1, W2, W3);
  ode_kernel<<<128, 384, SM_ODE>>>(z, ts, w_t, b_t, b1, b2, b3);
  dec_kernel<<<384, 256>>>(x, Wd, bd);
  sd_kernel<<<768, 256>>>(Ws, bs, Wdst, bdst);
  edge_kernel<<<128, 256>>>(Wo, bo, out);
}

// round 10
// speedup vs baseline: 4.2382x; 1.0032x over previous
#include <cuda_runtime.h>
#include <cuda_fp16.h>
#include <cstdint>

#define N_ROWS 12288
#define Z_D 128
#define H_D 256
#define N_STEPS 8
#define DT_F 0.125f

__device__ float g_k[6][N_ROWS * Z_D];
__device__ float g_y[N_ROWS * Z_D];
__device__ float g_h[N_ROWS * H_D];
__device__ float g_s[N_ROWS * H_D];
// chunk-major swizzled fp16 weights: W1 | W2c0 | W2c1 | W3 (4 x 32768 halves = 4 x 64 KB)
__device__ __half g_wh[131072];
#define HW1  0
#define HW2A 32768
#define HW2B 65536
#define HW3  98304

__constant__ float cA[6][5] = {
  {0.f,0.f,0.f,0.f,0.f},
  {0.2f,0.f,0.f,0.f,0.f},
  {3.f/40.f,9.f/40.f,0.f,0.f,0.f},
  {44.f/45.f,-56.f/15.f,32.f/9.f,0.f,0.f},
  {19372.f/6561.f,-25360.f/2187.f,64448.f/6561.f,-212.f/729.f,0.f},
  {9017.f/3168.f,-355.f/33.f,46732.f/5247.f,49.f/176.f,-5103.f/18656.f}
};
__constant__ float cC[6] = {0.f,0.2f,0.3f,0.8f,8.f/9.f,1.f};

// ---------------- helpers ----------------
__device__ __forceinline__ uint32_t smem_u32(const void* p) {
  uint32_t a;
  asm("{ .reg .u64 t; cvta.to.shared.u64 t, %1; cvt.u32.u64 %0, t; }" : "=r"(a) : "l"(p));
  return a;
}
#define CVT_H2(res, lo, hi) \
  asm("cvt.rn.f16x2.f32 %0, %1, %2;" : "=r"(res) : "f"(hi), "f"(lo))

// fp16-accumulator HMMA: 2x rate vs f32-acc on legacy mma path
__device__ __forceinline__ void mma_f16h(uint32_t* c, const uint32_t* a, const uint32_t* b) {
  asm volatile(
    "mma.sync.aligned.m16n8k16.row.col.f16.f16.f16.f16 "
    "{%0,%1}, {%2,%3,%4,%5}, {%6,%7}, {%0,%1};"
    : "+r"(c[0]), "+r"(c[1])
    : "r"(a[0]), "r"(a[1]), "r"(a[2]), "r"(a[3]), "r"(b[0]), "r"(b[1]));
}
__device__ __forceinline__ void ldm4(uint32_t* r, uint32_t addr) {
  asm volatile("ldmatrix.sync.aligned.m8n8.x4.shared.b16 {%0,%1,%2,%3}, [%4];"
    : "=r"(r[0]), "=r"(r[1]), "=r"(r[2]), "=r"(r[3]) : "r"(addr));
}
__device__ __forceinline__ float tanh_fast(float x) {
  float e = __expf(2.f * x);
  return 1.f - __fdividef(2.f, e + 1.f);
}

#define MBAR_INIT(mbar, cnt) \
  asm volatile("mbarrier.init.shared.b64 [%0], %1;" :: "r"(mbar), "r"(cnt) : "memory")
#define MBAR_EXPECT(mbar, bytes) \
  asm volatile("mbarrier.arrive.expect_tx.shared.b64 _, [%0], %1;" :: "r"(mbar), "r"(bytes) : "memory")
#define MBAR_WAIT(mbar, par) do { \
  uint32_t _m = (mbar), _p = (par), _d; \
  asm volatile("{\n\t.reg .pred p;\n\tmbarrier.try_wait.parity.acquire.cta.shared::cta.b64 p, [%1], %2;\n\tselp.b32 %0, 1, 0, p;\n\t}" \
    : "=r"(_d) : "r"(_m), "r"(_p) : "memory"); \
  if (!_d) { \
    asm volatile("{\n\t.reg .pred P1;\n\tWL_%=:\n\tmbarrier.try_wait.parity.acquire.cta.shared::cta.b64 P1, [%0], %1, 0x989680;\n\t@P1 bra.uni WD_%=;\n\tbra.uni WL_%=;\n\tWD_%=:\n\t}" \
      :: "r"(_m), "r"(_p) : "memory"); \
  } \
} while (0)
#define BULK_LOAD(dst, src, bytes, mbar) \
  asm volatile("cp.async.bulk.shared::cluster.global.mbarrier::complete_tx::bytes [%0], [%1], %2, [%3];" \
    :: "r"(dst), "l"(src), "r"(bytes), "r"(mbar) : "memory")

// ---- smem layout (bytes): A swizzled 96x512B; two 64KB weight buffers.
#define SO_A    0
#define SO_B0   49152
#define SO_B1   114688
#define SO_B1S  180224
#define SO_B2S  181248
#define SO_B3S  182272
#define SO_WTS  182784
#define SO_BTS  183296
#define SO_RAT  183808
#define SO_MB   184192
#define SM_ODE  184320

// ---------------- weight prep: fp32 -> fp16, chunk-major + XOR-granule swizzle ----------------
__global__ void prep_kernel(const float* __restrict__ W1, const float* __restrict__ W2,
                            const float* __restrict__ W3) {
  int i = blockIdx.x * 256 + threadIdx.x;
  if (i < 32768) {                       // W1 [N=256][K=128], row 256B (16 granules)
    int n = i >> 7, k = i & 127;
    int dst = HW1 + n * 128 + (((k >> 3) ^ (n & 7)) << 3) + (k & 7);
    g_wh[dst] = __float2half_rn(W1[k * 256 + n]);
  } else if (i < 98304) {                // W2 [N=256][K=256] split in two 128-K chunks
    int e = i - 32768; int n = e >> 8, k = e & 255;
    int c = k >> 7, kl = k & 127;
    int dst = HW2A + c * 32768 + n * 128 + (((kl >> 3) ^ (n & 7)) << 3) + (k & 7);
    g_wh[dst] = __float2half_rn(W2[k * 256 + n]);
  } else {                               // W3 [N=128][K=256], row 512B (32 granules)
    int e = i - 98304; int n = e >> 8, k = e & 255;
    int dst = HW3 + n * 256 + (((k >> 3) ^ (n & 7)) << 3) + (k & 7);
    g_wh[dst] = __float2half_rn(W3[k * 128 + n]);
  }
}

// ---------------- MMA span over a resident B buffer (fp16 accumulators) ----------------
// rbshift: 8 for 256B B-rows (K=128 chunk), 9 for 512B (W3 K=256).
template<int NT, int NKS>
__device__ __forceinline__ void mma_span(
    uint32_t ab, uint32_t bb, int kbaseA, int rbshift,
    int ncb, int mg, int lane, uint32_t (*c)[2]) {
  int m = lane >> 3;
  int row = 16 * mg + (m & 1) * 8 + (lane & 7);
  int g = lane >> 3, rr = lane & 7;
  #pragma unroll
  for (int ks = 0; ks < NKS; ks++) {
    int kcolA = kbaseA + ks * 16 + (m >> 1) * 8;
    uint32_t aoff = (uint32_t)((row << 9) + ((((kcolA >> 3) ^ (row & 7))) << 4));
    uint32_t af[4];
    ldm4(af, ab + aoff);
    int kcolB = ks * 16 + (g & 1) * 8;
    #pragma unroll
    for (int nt2 = 0; nt2 < NT / 2; nt2++) {
      int n = ncb + nt2 * 16 + (g >> 1) * 8 + rr;
      uint32_t boff = (uint32_t)((n << rbshift) + ((((kcolB >> 3) ^ (n & 7))) << 4));
      uint32_t rb[4];
      ldm4(rb, bb + boff);
      mma_f16h(c[nt2 * 2],     af, rb);
      mma_f16h(c[nt2 * 2 + 1], af, rb + 2);
    }
  }
}

template<int NT>
__device__ __forceinline__ void init_bias_frag(uint32_t (*c)[2], const float* bias, int ncb, int lane) {
  #pragma unroll
  for (int nt = 0; nt < NT; nt++) {
    int cc = ncb + nt * 8 + (lane & 3) * 2;
    uint32_t hp; CVT_H2(hp, bias[cc], bias[cc + 1]);
    c[nt][0] = hp; c[nt][1] = hp;
  }
}

// tanh epilogue: C(f16x2) -> fp16 into swizzled A
template<int NT>
__device__ __forceinline__ void epi_tanh(uint32_t (*c)[2], uint32_t ab,
                                         int ncb, int mg, int lane) {
  int row = 16 * mg + (lane >> 2);
  #pragma unroll
  for (int nt = 0; nt < NT; nt++) {
    int col = ncb + nt * 8 + (lane & 3) * 2;
    #pragma unroll
    for (int h = 0; h < 2; h++) {
      int rh = row + 8 * h;
      float2 f = __half22float2(*reinterpret_cast<__half2*>(&c[nt][h]));
      float t0 = tanh_fast(f.x);
      float t1 = tanh_fast(f.y);
      uint32_t hp; CVT_H2(hp, t0, t1);
      uint32_t off = (uint32_t)((rh << 9) + ((((col >> 3) ^ (rh & 7))) << 4) + ((col & 7) << 1));
      asm volatile("st.shared.b32 [%0], %1;" :: "r"(ab + off), "r"(hp) : "memory");
    }
  }
}

extern __shared__ char smem_raw[];

__global__ void __launch_bounds__(384, 1) ode_kernel(
    const float* __restrict__ z, const float* __restrict__ ts,
    const float* __restrict__ w_t, const float* __restrict__ b_t,
    const float* __restrict__ b1, const float* __restrict__ b2, const float* __restrict__ b3) {
  const uint32_t base = smem_u32(smem_raw);
  float* b1s = (float*)(smem_raw + SO_B1S);
  float* b2s = (float*)(smem_raw + SO_B2S);
  float* b3s = (float*)(smem_raw + SO_B3S);
  float* wts = (float*)(smem_raw + SO_WTS);
  float* bts = (float*)(smem_raw + SO_BTS);
  float* rat = (float*)(smem_raw + SO_RAT);
  const uint32_t ab = base + SO_A;
  const uint32_t wb0 = base + SO_B0, wb1 = base + SO_B1;
  const uint32_t mb0 = base + SO_MB, mb1 = base + SO_MB + 8;
  const int tid = threadIdx.x;
  const int lane = tid & 31, w = tid >> 5;
  const int mg = w >> 1, ng = w & 1;   // mg 0..5 (16 rows), ng 0..1
  const int R0 = blockIdx.x * 96;

  if (tid < 96) rat[tid] = ts[R0 + tid];
  if (tid < 128) {
    wts[tid] = w_t[tid];
    bts[tid] = b_t[tid];
    b3s[tid] = b3[tid];
  }
  if (tid < 256) { b1s[tid] = b1[tid]; b2s[tid] = b2[tid]; }
  if (tid == 0) { MBAR_INIT(mb0, 1); MBAR_INIT(mb1, 1); }
  for (int p = tid; p < 96 * 64; p += 384) {
    int r = p >> 6, k2 = (p & 63) * 2;
    float2 zz = *(const float2*)(z + ((R0 + r) & 63) * Z_D + k2);
    *(float2*)(g_y + (size_t)(R0 + r) * Z_D + k2) = zz;
  }
  __syncthreads();
  // bootstrap loads: b0 <- W1, b1 <- W2c0
  if (tid == 0) {
    MBAR_EXPECT(mb0, 65536);
    BULK_LOAD(wb0, (const void*)(g_wh + HW1), 65536, mb0);
    MBAR_EXPECT(mb1, 65536);
    BULK_LOAD(wb1, (const void*)(g_wh + HW2A), 65536, mb1);
  }

  for (int step = 0; step < N_STEPS; step++) {
    float s0 = step * DT_F;
    for (int st = 0; st < 6; st++) {
      bool last = (step == N_STEPS - 1) && (st == 5);
      float tst = s0 + cC[st] * DT_F;
      // ---- build stage input into fp16 A[*, 0:128] ----
      for (int p = tid; p < 96 * 64; p += 384) {
        int r = p >> 6, k2 = (p & 63) * 2;
        size_t gi = (size_t)(R0 + r) * Z_D + k2;
        float2 v = *(const float2*)(g_y + gi);
        #pragma unroll 1
        for (int j = 0; j < st; j++) {
          float2 kk = *(const float2*)(&g_k[j][gi]);
          float cj = DT_F * cA[st][j];
          v.x += cj * kk.x; v.y += cj * kk.y;
        }
        float tr = tst * rat[r];
        v.x += __cosf(fmaf(tr, wts[k2], bts[k2]));
        v.y += __cosf(fmaf(tr, wts[k2 + 1], bts[k2 + 1]));
        uint32_t hp; CVT_H2(hp, v.x, v.y);
        uint32_t off = (uint32_t)((r << 9) + ((((k2 >> 3) ^ (r & 7))) << 4) + ((k2 & 7) << 1));
        asm volatile("st.shared.b32 [%0], %1;" :: "r"(ab + off), "r"(hp) : "memory");
      }
      MBAR_WAIT(mb0, 0);                 // W1 arrived
      __syncthreads();                   // A ready
      {   // layer 1: K=128 -> N=256, tanh
        uint32_t c[16][2];
        init_bias_frag<16>(c, b1s, ng * 128, lane);
        mma_span<16, 8>(ab, wb0, 0, 8, ng * 128, mg, lane, c);
        __syncthreads();                 // b0 + A reads done
        if (tid == 0) {
          MBAR_EXPECT(mb0, 65536);
          BULK_LOAD(wb0, (const void*)(g_wh + HW2B), 65536, mb0);
        }
        epi_tanh<16>(c, ab, ng * 128, mg, lane);
      }
      MBAR_WAIT(mb1, 0);                 // W2c0 arrived
      __syncthreads();                   // A epilogue done
      {   // layer 2: K=256 -> N=256 (two 128-K chunks), tanh
        uint32_t c[16][2];
        init_bias_frag<16>(c, b2s, ng * 128, lane);
        mma_span<16, 8>(ab, wb1, 0, 8, ng * 128, mg, lane, c);
        __syncthreads();                 // b1 reads done
        if (tid == 0) {
          MBAR_EXPECT(mb1, 65536);
          BULK_LOAD(wb1, (const void*)(g_wh + HW3), 65536, mb1);
        }
        MBAR_WAIT(mb0, 1);               // W2c1 arrived
        mma_span<16, 8>(ab, wb0, 128, 8, ng * 128, mg, lane, c);
        __syncthreads();                 // b0 reads done
        if (tid == 0 && !last) {
          MBAR_EXPECT(mb0, 65536);
          BULK_LOAD(wb0, (const void*)(g_wh + HW1), 65536, mb0);
        }
        epi_tanh<16>(c, ab, ng * 128, mg, lane);
      }
      MBAR_WAIT(mb1, 1);                 // W3 arrived
      __syncthreads();                   // A epilogue done
      {   // layer 3: K=256 -> N=128, * ratio -> g_k[st]
        uint32_t c[8][2];
        init_bias_frag<8>(c, b3s, ng * 64, lane);
        mma_span<8, 16>(ab, wb1, 0, 9, ng * 64, mg, lane, c);
        __syncthreads();                 // b1 + A reads done
        if (tid == 0 && !last) {
          MBAR_EXPECT(mb1, 65536);
          BULK_LOAD(wb1, (const void*)(g_wh + HW2A), 65536, mb1);
        }
        int row = 16 * mg + (lane >> 2);
        #pragma unroll
        for (int nt = 0; nt < 8; nt++) {
          int col = ng * 64 + nt * 8 + (lane & 3) * 2;
          #pragma unroll
          for (int h = 0; h < 2; h++) {
            int rr = row + 8 * h;
            float sc = rat[rr];
            float2 f = __half22float2(*reinterpret_cast<__half2*>(&c[nt][h]));
            float2 v = make_float2(f.x * sc, f.y * sc);
            *(float2*)(&g_k[st][(size_t)(R0 + rr) * Z_D + col]) = v;
          }
        }
      }
      __syncthreads();                   // g_k visible for next build / y-update
    }
    // ---- y += dt * sum bw_j k_j ----
    for (int p = tid; p < 96 * 64; p += 384) {
      int r = p >> 6, k2 = (p & 63) * 2;
      size_t gi = (size_t)(R0 + r) * Z_D + k2;
      float2 y = *(float2*)(g_y + gi);
      float2 k0 = *(const float2*)(&g_k[0][gi]);
      float2 q2 = *(const float2*)(&g_k[2][gi]);
      float2 q3 = *(const float2*)(&g_k[3][gi]);
      float2 q4 = *(const float2*)(&g_k[4][gi]);
      float2 q5 = *(const float2*)(&g_k[5][gi]);
      const float w0 = 35.f/384.f, w2 = 500.f/1113.f, w3 = 125.f/192.f,
                  w4 = -2187.f/6784.f, w5 = 11.f/84.f;
      y.x += DT_F * (w0*k0.x + w2*q2.x + w3*q3.x + w4*q4.x + w5*q5.x);
      y.y += DT_F * (w0*k0.y + w2*q2.y + w3*q3.y + w4*q4.y + w5*q5.y);
      *(float2*)(g_y + gi) = y;
    }
    __syncthreads();
  }
}

// ---------------- decode_fc: 64 rows/block (R8 geometry) ----------------
__global__ void __launch_bounds__(256) dec_kernel(
    const float* __restrict__ x, const float* __restrict__ Wd, const float* __restrict__ bd) {
  __shared__ float xs[172];
  __shared__ float ys[64 * 128];
  const int tid = threadIdx.x;
  const int b = blockIdx.x, R0 = b * 64;
  for (int i = tid; i < 172; i += 256) xs[i] = x[(size_t)b * 172 + i];
  for (int i = tid; i < 64 * 128; i += 256) ys[i] = g_y[(size_t)R0 * 128 + i];
  __syncthreads();
  float acc0 = bd[tid];
  #pragma unroll 4
  for (int k = 0; k < 172; k++) acc0 = fmaf(xs[k], Wd[(size_t)k * 256 + tid], acc0);
  float acc[64];
  #pragma unroll
  for (int r = 0; r < 64; r++) acc[r] = acc0;
  #pragma unroll 2
  for (int k = 0; k < 128; k++) {
    float w = Wd[(size_t)(172 + k) * 256 + tid];
    #pragma unroll
    for (int r = 0; r < 64; r++) acc[r] = fmaf(ys[r * 128 + k], w, acc[r]);
  }
  #pragma unroll
  for (int r = 0; r < 64; r++) g_h[(size_t)(R0 + r) * 256 + tid] = acc[r];
}

// ---------------- src/dst fc: 32 rows/block (R8 geometry) ----------------
__global__ void __launch_bounds__(256) sd_kernel(
    const float* __restrict__ Ws, const float* __restrict__ bs,
    const float* __restrict__ Wdst, const float* __restrict__ bdst) {
  __shared__ float hs[32 * 256];
  const int tid = threadIdx.x;
  const int R0 = blockIdx.x * 32;
  const float* W = (R0 < 4096) ? Ws : Wdst;
  const float* bb = (R0 < 4096) ? bs : bdst;
  for (int i = tid; i < 32 * 256; i += 256) hs[i] = g_h[(size_t)R0 * 256 + i];
  __syncthreads();
  float acc[32];
  float b0 = bb[tid];
  #pragma unroll
  for (int r = 0; r < 32; r++) acc[r] = b0;
  #pragma unroll 2
  for (int k = 0; k < 256; k++) {
    float w = W[(size_t)k * 256 + tid];
    #pragma unroll
    for (int r = 0; r < 32; r++) acc[r] = fmaf(hs[r * 256 + k], w, acc[r]);
  }
  #pragma unroll
  for (int r = 0; r < 32; r++) g_s[(size_t)(R0 + r) * 256 + tid] = acc[r];
}

// ---------------- edge out + mean over L ----------------
__global__ void __launch_bounds__(256) edge_kernel(
    const float* __restrict__ Wo, const float* __restrict__ bo, float* __restrict__ out) {
  __shared__ float red[8];
  const int tid = threadIdx.x;
  const int o = blockIdx.x;
  const int b = (o < 64) ? o : (o - 64);
  const size_t off2 = (o < 64) ? (size_t)4096 * H_D : (size_t)8192 * H_D;
  const float wcol = Wo[tid];
  float sum = 0.f;
  for (int l = 0; l < 64; l++) {
    size_t r1 = (size_t)(b * 64 + l) * H_D + tid;
    float v = g_s[r1] + g_s[off2 + r1];
    sum += fmaxf(v, 0.f) * wcol;
  }
  #pragma unroll
  for (int d = 16; d > 0; d >>= 1) sum += __shfl_xor_sync(0xFFFFFFFFu, sum, d);
  if ((tid & 31) == 0) red[tid >> 5] = sum;
  __syncthreads();
  if (tid == 0) {
    float t = 0.f;
    #pragma unroll
    for (int w = 0; w < 8; w++) t += red[w];
    out[o] = t * (1.f / 64.f) + bo[0];
  }
}

extern "C" void kernel_launch(void* const* d_in, const int* in_sizes, int n_in,
                              void* d_out, int out_size) {
  const float* x    = (const float*)d_in[0];
  const float* z    = (const float*)d_in[1];
  const float* ts   = (const float*)d_in[2];
  const float* w_t  = (const float*)d_in[3];
  const float* b_t  = (const float*)d_in[4];
  const float* W1   = (const float*)d_in[5];
  const float* b1   = (const float*)d_in[6];
  const float* W2   = (const float*)d_in[7];
  const float* b2   = (const float*)d_in[8];
  const float* W3   = (const float*)d_in[9];
  const float* b3   = (const float*)d_in[10];
  const float* Wd   = (const float*)d_in[11];
  const float* bd   = (const float*)d_in[12];
  const float* Ws   = (const float*)d_in[13];
  const float* bs   = (const float*)d_in[14];
  const float* Wdst = (const float*)d_in[15];
  const float* bdst = (const float*)d_in[16];
  const float* Wo   = (const float*)d_in[17];
  const float* bo   = (const float*)d_in[18];
  float* out = (float*)d_out;

  cudaFuncSetAttribute(ode_kernel, cudaFuncAttributeMaxDynamicSharedMemorySize, SM_ODE);

  prep_kernel<<<512, 256>>>(W1, W2, W3);
  ode_kernel<<<128, 384, SM_ODE>>>(z, ts, w_t, b_t, b1, b2, b3);
  dec_kernel<<<192, 256>>>(x, Wd, bd);
  sd_kernel<<<384, 256>>>(Ws, bs, Wdst, bdst);
  edge_kernel<<<128, 256>>>(Wo, bo, out);
}

// round 11
// speedup vs baseline: 4.4968x; 1.0610x over previous
#include <cuda_runtime.h>
#include <cuda_fp16.h>
#include <cstdint>

#define N_ROWS 12288
#define Z_D 128
#define H_D 256
#define N_STEPS 8
#define DT_F 0.125f

__device__ float g_k[6][N_ROWS * Z_D];
__device__ float g_y[N_ROWS * Z_D];
__device__ float g_h[N_ROWS * H_D];
__device__ float g_s[N_ROWS * H_D];
// 8 sequential 32KB blocks (16384 halves each):
// B0=W1[k0:64] B1=W1[k64:128] B2..B5=W2[k*64 quarters] B6=W3[k0:128] B7=W3[k128:256]
__device__ __half g_wh[131072];

__constant__ float cA[6][5] = {
  {0.f,0.f,0.f,0.f,0.f},
  {0.2f,0.f,0.f,0.f,0.f},
  {3.f/40.f,9.f/40.f,0.f,0.f,0.f},
  {44.f/45.f,-56.f/15.f,32.f/9.f,0.f,0.f},
  {19372.f/6561.f,-25360.f/2187.f,64448.f/6561.f,-212.f/729.f,0.f},
  {9017.f/3168.f,-355.f/33.f,46732.f/5247.f,49.f/176.f,-5103.f/18656.f}
};
__constant__ float cC[6] = {0.f,0.2f,0.3f,0.8f,8.f/9.f,1.f};

// ---------------- helpers ----------------
__device__ __forceinline__ uint32_t smem_u32(const void* p) {
  uint32_t a;
  asm("{ .reg .u64 t; cvta.to.shared.u64 t, %1; cvt.u32.u64 %0, t; }" : "=r"(a) : "l"(p));
  return a;
}
#define CVT_H2(res, lo, hi) \
  asm("cvt.rn.f16x2.f32 %0, %1, %2;" : "=r"(res) : "f"(hi), "f"(lo))

__device__ __forceinline__ void mma_f16h(uint32_t* c, const uint32_t* a, const uint32_t* b) {
  asm volatile(
    "mma.sync.aligned.m16n8k16.row.col.f16.f16.f16.f16 "
    "{%0,%1}, {%2,%3,%4,%5}, {%6,%7}, {%0,%1};"
    : "+r"(c[0]), "+r"(c[1])
    : "r"(a[0]), "r"(a[1]), "r"(a[2]), "r"(a[3]), "r"(b[0]), "r"(b[1]));
}
__device__ __forceinline__ void ldm4(uint32_t* r, uint32_t addr) {
  asm volatile("ldmatrix.sync.aligned.m8n8.x4.shared.b16 {%0,%1,%2,%3}, [%4];"
    : "=r"(r[0]), "=r"(r[1]), "=r"(r[2]), "=r"(r[3]) : "r"(addr));
}
__device__ __forceinline__ float tanh_fast(float x) {
  float e = __expf(2.f * x);
  return 1.f - __fdividef(2.f, e + 1.f);
}

#define MBAR_INIT(mbar, cnt) \
  asm volatile("mbarrier.init.shared.b64 [%0], %1;" :: "r"(mbar), "r"(cnt) : "memory")
#define MBAR_EXPECT(mbar, bytes) \
  asm volatile("mbarrier.arrive.expect_tx.shared.b64 _, [%0], %1;" :: "r"(mbar), "r"(bytes) : "memory")
#define MBAR_WAIT(mbar, par) do { \
  uint32_t _m = (mbar), _p = (par), _d; \
  asm volatile("{\n\t.reg .pred p;\n\tmbarrier.try_wait.parity.acquire.cta.shared::cta.b64 p, [%1], %2;\n\tselp.b32 %0, 1, 0, p;\n\t}" \
    : "=r"(_d) : "r"(_m), "r"(_p) : "memory"); \
  if (!_d) { \
    asm volatile("{\n\t.reg .pred P1;\n\tWL_%=:\n\tmbarrier.try_wait.parity.acquire.cta.shared::cta.b64 P1, [%0], %1, 0x989680;\n\t@P1 bra.uni WD_%=;\n\tbra.uni WL_%=;\n\tWD_%=:\n\t}" \
      :: "r"(_m), "r"(_p) : "memory"); \
  } \
} while (0)
#define BULK_LOAD(dst, src, bytes, mbar) \
  asm volatile("cp.async.bulk.shared::cluster.global.mbarrier::complete_tx::bytes [%0], [%1], %2, [%3];" \
    :: "r"(dst), "l"(src), "r"(bytes), "r"(mbar) : "memory")

// ---- smem layout (bytes), per 48-row CTA ----
#define SO_A    0
#define SO_B0   24576
#define SO_B1   57344
#define SO_B1S  90112
#define SO_B2S  91136
#define SO_B3S  92160
#define SO_WTS  92672
#define SO_BTS  93184
#define SO_RAT  93696
#define SO_MB   93952
#define SM_ODE  94208

// ---------------- weight prep: fp32 -> fp16, 32KB-block layout + XOR-granule swizzle ----------------
__global__ void prep_kernel(const float* __restrict__ W1, const float* __restrict__ W2,
                            const float* __restrict__ W3) {
  int i = blockIdx.x * 256 + threadIdx.x;
  if (i < 32768) {                       // W1 [N=256][K=128] -> blocks 0,1 (row 64 halves)
    int n = i >> 7, k = i & 127;
    int blk = k >> 6, kl = k & 63;
    int dst = blk * 16384 + n * 64 + (((kl >> 3) ^ (n & 7)) << 3) + (kl & 7);
    g_wh[dst] = __float2half_rn(W1[k * 256 + n]);
  } else if (i < 98304) {                // W2 [N=256][K=256] -> blocks 2..5
    int e = i - 32768; int n = e >> 8, k = e & 255;
    int blk = 2 + (k >> 6), kl = k & 63;
    int dst = blk * 16384 + n * 64 + (((kl >> 3) ^ (n & 7)) << 3) + (kl & 7);
    g_wh[dst] = __float2half_rn(W2[k * 256 + n]);
  } else {                               // W3 [N=128][K=256] -> blocks 6,7 (row 128 halves)
    int e = i - 98304; int n = e >> 8, k = e & 255;
    int blk = 6 + (k >> 7), kl = k & 127;
    int dst = blk * 16384 + n * 128 + (((kl >> 3) ^ (n & 7)) << 3) + (kl & 7);
    g_wh[dst] = __float2half_rn(W3[k * 128 + n]);
  }
}

// ---------------- MMA span over a resident 32KB B block ----------------
// RBS: 7 for 128B B rows (64-K blocks), 8 for 256B rows (W3 128-K blocks).
template<int NT, int NKS, int RBS>
__device__ __forceinline__ void mma_span(
    uint32_t ab, uint32_t bb, int kbaseA,
    int ncb, int mg, int lane, uint32_t (*c)[2]) {
  int m = lane >> 3;
  int row = 16 * mg + (m & 1) * 8 + (lane & 7);
  int g = lane >> 3, rr = lane & 7;
  #pragma unroll
  for (int ks = 0; ks < NKS; ks++) {
    int kcolA = kbaseA + ks * 16 + (m >> 1) * 8;
    uint32_t aoff = (uint32_t)((row << 9) + ((((kcolA >> 3) ^ (row & 7))) << 4));
    uint32_t af[4];
    ldm4(af, ab + aoff);
    int kcolB = ks * 16 + (g & 1) * 8;
    #pragma unroll
    for (int nt2 = 0; nt2 < NT / 2; nt2++) {
      int n = ncb + nt2 * 16 + (g >> 1) * 8 + rr;
      uint32_t boff = (uint32_t)((n << RBS) + ((((kcolB >> 3) ^ (n & 7))) << 4));
      uint32_t rb[4];
      ldm4(rb, bb + boff);
      mma_f16h(c[nt2 * 2],     af, rb);
      mma_f16h(c[nt2 * 2 + 1], af, rb + 2);
    }
  }
}

template<int NT>
__device__ __forceinline__ void init_bias_frag(uint32_t (*c)[2], const float* bias, int ncb, int lane) {
  #pragma unroll
  for (int nt = 0; nt < NT; nt++) {
    int cc = ncb + nt * 8 + (lane & 3) * 2;
    uint32_t hp; CVT_H2(hp, bias[cc], bias[cc + 1]);
    c[nt][0] = hp; c[nt][1] = hp;
  }
}

template<int NT>
__device__ __forceinline__ void epi_tanh(uint32_t (*c)[2], uint32_t ab,
                                         int ncb, int mg, int lane) {
  int row = 16 * mg + (lane >> 2);
  #pragma unroll
  for (int nt = 0; nt < NT; nt++) {
    int col = ncb + nt * 8 + (lane & 3) * 2;
    #pragma unroll
    for (int h = 0; h < 2; h++) {
      int rh = row + 8 * h;
      float2 f = __half22float2(*reinterpret_cast<__half2*>(&c[nt][h]));
      float t0 = tanh_fast(f.x);
      float t1 = tanh_fast(f.y);
      uint32_t hp; CVT_H2(hp, t0, t1);
      uint32_t off = (uint32_t)((rh << 9) + ((((col >> 3) ^ (rh & 7))) << 4) + ((col & 7) << 1));
      asm volatile("st.shared.b32 [%0], %1;" :: "r"(ab + off), "r"(hp) : "memory");
    }
  }
}

extern __shared__ char smem_raw[];

// one pipelined weight block: wait data, MMA, retire-sync, reissue this buffer 2 blocks ahead
#define DO_BLOCK(NT_, NKS_, RBS_, KBASE_, NCB_, CARR_) do { \
  uint32_t bb_ = (blk & 1) ? wb1 : wb0; \
  uint32_t mb_ = (blk & 1) ? mb1 : mb0; \
  if (blk & 1) { MBAR_WAIT(mb1, ph1); ph1 ^= 1; } \
  else         { MBAR_WAIT(mb0, ph0); ph0 ^= 1; } \
  mma_span<NT_, NKS_, RBS_>(ab, bb_, KBASE_, NCB_, mg, lane, CARR_); \
  __syncthreads(); \
  if (tid == 0 && blk + 2 < 384) { \
    MBAR_EXPECT(mb_, 32768); \
    BULK_LOAD(bb_, (const void*)(g_wh + (((blk + 2) & 7) * 16384)), 32768, mb_); \
  } \
  blk++; \
} while (0)

__global__ void __launch_bounds__(192, 2) ode_kernel(
    const float* __restrict__ z, const float* __restrict__ ts,
    const float* __restrict__ w_t, const float* __restrict__ b_t,
    const float* __restrict__ b1, const float* __restrict__ b2, const float* __restrict__ b3) {
  const uint32_t base = smem_u32(smem_raw);
  float* b1s = (float*)(smem_raw + SO_B1S);
  float* b2s = (float*)(smem_raw + SO_B2S);
  float* b3s = (float*)(smem_raw + SO_B3S);
  float* wts = (float*)(smem_raw + SO_WTS);
  float* bts = (float*)(smem_raw + SO_BTS);
  float* rat = (float*)(smem_raw + SO_RAT);
  const uint32_t ab = base + SO_A;
  const uint32_t wb0 = base + SO_B0, wb1 = base + SO_B1;
  const uint32_t mb0 = base + SO_MB, mb1 = base + SO_MB + 8;
  const int tid = threadIdx.x;
  const int lane = tid & 31, w = tid >> 5;
  const int mg = w >> 1, ng = w & 1;   // mg 0..2 (16 rows), ng 0..1
  const int R0 = blockIdx.x * 48;

  if (tid < 48) rat[tid] = ts[R0 + tid];
  if (tid < 128) {
    wts[tid] = w_t[tid];
    bts[tid] = b_t[tid];
    b3s[tid] = b3[tid];
  }
  for (int i = tid; i < 256; i += 192) { b1s[i] = b1[i]; b2s[i] = b2[i]; }
  if (tid == 0) { MBAR_INIT(mb0, 1); MBAR_INIT(mb1, 1); }
  for (int p = tid; p < 48 * 64; p += 192) {
    int r = p >> 6, k2 = (p & 63) * 2;
    float2 zz = *(const float2*)(z + ((R0 + r) & 63) * Z_D + k2);
    *(float2*)(g_y + (size_t)(R0 + r) * Z_D + k2) = zz;
  }
  __syncthreads();
  if (tid == 0) {                        // bootstrap: blocks 0,1
    MBAR_EXPECT(mb0, 32768);
    BULK_LOAD(wb0, (const void*)(g_wh + 0), 32768, mb0);
    MBAR_EXPECT(mb1, 32768);
    BULK_LOAD(wb1, (const void*)(g_wh + 16384), 32768, mb1);
  }

  int blk = 0, ph0 = 0, ph1 = 0;
  for (int step = 0; step < N_STEPS; step++) {
    float s0 = step * DT_F;
    for (int st = 0; st < 6; st++) {
      float tst = s0 + cC[st] * DT_F;
      // ---- build stage input into fp16 A (48 x 128) ----
      for (int p = tid; p < 48 * 64; p += 192) {
        int r = p >> 6, k2 = (p & 63) * 2;
        size_t gi = (size_t)(R0 + r) * Z_D + k2;
        float2 v = *(const float2*)(g_y + gi);
        #pragma unroll 1
        for (int j = 0; j < st; j++) {
          float2 kk = *(const float2*)(&g_k[j][gi]);
          float cj = DT_F * cA[st][j];
          v.x += cj * kk.x; v.y += cj * kk.y;
        }
        float tr = tst * rat[r];
        v.x += __cosf(fmaf(tr, wts[k2], bts[k2]));
        v.y += __cosf(fmaf(tr, wts[k2 + 1], bts[k2 + 1]));
        uint32_t hp; CVT_H2(hp, v.x, v.y);
        uint32_t off = (uint32_t)((r << 9) + ((((k2 >> 3) ^ (r & 7))) << 4) + ((k2 & 7) << 1));
        asm volatile("st.shared.b32 [%0], %1;" :: "r"(ab + off), "r"(hp) : "memory");
      }
      __syncthreads();                   // A ready
      {   // layer 1: K=128 (blocks 0,1) -> N=256, tanh
        uint32_t c[16][2];
        init_bias_frag<16>(c, b1s, ng * 128, lane);
        DO_BLOCK(16, 4, 7, 0,  ng * 128, c);
        DO_BLOCK(16, 4, 7, 64, ng * 128, c);
        epi_tanh<16>(c, ab, ng * 128, mg, lane);
      }
      __syncthreads();                   // A rewritten
      {   // layer 2: K=256 (blocks 2..5) -> N=256, tanh
        uint32_t c[16][2];
        init_bias_frag<16>(c, b2s, ng * 128, lane);
        DO_BLOCK(16, 4, 7, 0,   ng * 128, c);
        DO_BLOCK(16, 4, 7, 64,  ng * 128, c);
        DO_BLOCK(16, 4, 7, 128, ng * 128, c);
        DO_BLOCK(16, 4, 7, 192, ng * 128, c);
        epi_tanh<16>(c, ab, ng * 128, mg, lane);
      }
      __syncthreads();                   // A rewritten
      {   // layer 3: K=256 (blocks 6,7) -> N=128, * ratio -> g_k[st]
        uint32_t c[8][2];
        init_bias_frag<8>(c, b3s, ng * 64, lane);
        DO_BLOCK(8, 8, 8, 0,   ng * 64, c);
        DO_BLOCK(8, 8, 8, 128, ng * 64, c);
        int row = 16 * mg + (lane >> 2);
        #pragma unroll
        for (int nt = 0; nt < 8; nt++) {
          int col = ng * 64 + nt * 8 + (lane & 3) * 2;
          #pragma unroll
          for (int h = 0; h < 2; h++) {
            int rr = row + 8 * h;
            float sc = rat[rr];
            float2 f = __half22float2(*reinterpret_cast<__half2*>(&c[nt][h]));
            float2 v = make_float2(f.x * sc, f.y * sc);
            *(float2*)(&g_k[st][(size_t)(R0 + rr) * Z_D + col]) = v;
          }
        }
      }
      __syncthreads();                   // g_k visible
    }
    // ---- y += dt * sum bw_j k_j ----
    for (int p = tid; p < 48 * 64; p += 192) {
      int r = p >> 6, k2 = (p & 63) * 2;
      size_t gi = (size_t)(R0 + r) * Z_D + k2;
      float2 y = *(float2*)(g_y + gi);
      float2 k0 = *(const float2*)(&g_k[0][gi]);
      float2 q2 = *(const float2*)(&g_k[2][gi]);
      float2 q3 = *(const float2*)(&g_k[3][gi]);
      float2 q4 = *(const float2*)(&g_k[4][gi]);
      float2 q5 = *(const float2*)(&g_k[5][gi]);
      const float w0 = 35.f/384.f, w2 = 500.f/1113.f, w3 = 125.f/192.f,
                  w4 = -2187.f/6784.f, w5 = 11.f/84.f;
      y.x += DT_F * (w0*k0.x + w2*q2.x + w3*q3.x + w4*q4.x + w5*q5.x);
      y.y += DT_F * (w0*k0.y + w2*q2.y + w3*q3.y + w4*q4.y + w5*q5.y);
      *(float2*)(g_y + gi) = y;
    }
    __syncthreads();
  }
}

// ---------------- decode_fc: 64 rows/block ----------------
__global__ void __launch_bounds__(256) dec_kernel(
    const float* __restrict__ x, const float* __restrict__ Wd, const float* __restrict__ bd) {
  __shared__ float xs[172];
  __shared__ float ys[64 * 128];
  const int tid = threadIdx.x;
  const int b = blockIdx.x, R0 = b * 64;
  for (int i = tid; i < 172; i += 256) xs[i] = x[(size_t)b * 172 + i];
  for (int i = tid; i < 64 * 128; i += 256) ys[i] = g_y[(size_t)R0 * 128 + i];
  __syncthreads();
  float acc0 = bd[tid];
  #pragma unroll 4
  for (int k = 0; k < 172; k++) acc0 = fmaf(xs[k], Wd[(size_t)k * 256 + tid], acc0);
  float acc[64];
  #pragma unroll
  for (int r = 0; r < 64; r++) acc[r] = acc0;
  #pragma unroll 2
  for (int k = 0; k < 128; k++) {
    float w = Wd[(size_t)(172 + k) * 256 + tid];
    #pragma unroll
    for (int r = 0; r < 64; r++) acc[r] = fmaf(ys[r * 128 + k], w, acc[r]);
  }
  #pragma unroll
  for (int r = 0; r < 64; r++) g_h[(size_t)(R0 + r) * 256 + tid] = acc[r];
}

// ---------------- src/dst fc: 32 rows/block ----------------
__global__ void __launch_bounds__(256) sd_kernel(
    const float* __restrict__ Ws, const float* __restrict__ bs,
    const float* __restrict__ Wdst, const float* __restrict__ bdst) {
  __shared__ float hs[32 * 256];
  const int tid = threadIdx.x;
  const int R0 = blockIdx.x * 32;
  const float* W = (R0 < 4096) ? Ws : Wdst;
  const float* bb = (R0 < 4096) ? bs : bdst;
  for (int i = tid; i < 32 * 256; i += 256) hs[i] = g_h[(size_t)R0 * 256 + i];
  __syncthreads();
  float acc[32];
  float b0 = bb[tid];
  #pragma unroll
  for (int r = 0; r < 32; r++) acc[r] = b0;
  #pragma unroll 2
  for (int k = 0; k < 256; k++) {
    float w = W[(size_t)k * 256 + tid];
    #pragma unroll
    for (int r = 0; r < 32; r++) acc[r] = fmaf(hs[r * 256 + k], w, acc[r]);
  }
  #pragma unroll
  for (int r = 0; r < 32; r++) g_s[(size_t)(R0 + r) * 256 + tid] = acc[r];
}

// ---------------- edge out + mean over L ----------------
__global__ void __launch_bounds__(256) edge_kernel(
    const float* __restrict__ Wo, const float* __restrict__ bo, float* __restrict__ out) {
  __shared__ float red[8];
  const int tid = threadIdx.x;
  const int o = blockIdx.x;
  const int b = (o < 64) ? o : (o - 64);
  const size_t off2 = (o < 64) ? (size_t)4096 * H_D : (size_t)8192 * H_D;
  const float wcol = Wo[tid];
  float sum = 0.f;
  for (int l = 0; l < 64; l++) {
    size_t r1 = (size_t)(b * 64 + l) * H_D + tid;
    float v = g_s[r1] + g_s[off2 + r1];
    sum += fmaxf(v, 0.f) * wcol;
  }
  #pragma unroll
  for (int d = 16; d > 0; d >>= 1) sum += __shfl_xor_sync(0xFFFFFFFFu, sum, d);
  if ((tid & 31) == 0) red[tid >> 5] = sum;
  __syncthreads();
  if (tid == 0) {
    float t = 0.f;
    #pragma unroll
    for (int w = 0; w < 8; w++) t += red[w];
    out[o] = t * (1.f / 64.f) + bo[0];
  }
}

extern "C" void kernel_launch(void* const* d_in, const int* in_sizes, int n_in,
                              void* d_out, int out_size) {
  const float* x    = (const float*)d_in[0];
  const float* z    = (const float*)d_in[1];
  const float* ts   = (const float*)d_in[2];
  const float* w_t  = (const float*)d_in[3];
  const float* b_t  = (const float*)d_in[4];
  const float* W1   = (const float*)d_in[5];
  const float* b1   = (const float*)d_in[6];
  const float* W2   = (const float*)d_in[7];
  const float* b2   = (const float*)d_in[8];
  const float* W3   = (const float*)d_in[9];
  const float* b3   = (const float*)d_in[10];
  const float* Wd   = (const float*)d_in[11];
  const float* bd   = (const float*)d_in[12];
  const float* Ws   = (const float*)d_in[13];
  const float* bs   = (const float*)d_in[14];
  const float* Wdst = (const float*)d_in[15];
  const float* bdst = (const float*)d_in[16];
  const float* Wo   = (const float*)d_in[17];
  const float* bo   = (const float*)d_in[18];
  float* out = (float*)d_out;

  cudaFuncSetAttribute(ode_kernel, cudaFuncAttributeMaxDynamicSharedMemorySize, SM_ODE);

  prep_kernel<<<512, 256>>>(W1, W2, W3);
  ode_kernel<<<256, 192, SM_ODE>>>(z, ts, w_t, b_t, b1, b2, b3);
  dec_kernel<<<192, 256>>>(x, Wd, bd);
  sd_kernel<<<384, 256>>>(Ws, bs, Wdst, bdst);
  edge_kernel<<<128, 256>>>(Wo, bo, out);
}

// round 12
// speedup vs baseline: 4.6347x; 1.0307x over previous
#include <cuda_runtime.h>
#include <cuda_fp16.h>
#include <cstdint>

#define N_ROWS 12288
#define Z_D 128
#define H_D 256
#define N_STEPS 8
#define DT_F 0.125f

__device__ __half g_k[6][N_ROWS * Z_D];
__device__ float g_y[N_ROWS * Z_D];
__device__ float g_h[N_ROWS * H_D];
__device__ float g_s[N_ROWS * H_D];
// 8 sequential 32KB blocks (16384 halves each):
// B0=W1[k0:64] B1=W1[k64:128] B2..B5=W2[k*64 quarters] B6=W3[k0:128] B7=W3[k128:256]
__device__ __half g_wh[131072];

__constant__ float cA[6][5] = {
  {0.f,0.f,0.f,0.f,0.f},
  {0.2f,0.f,0.f,0.f,0.f},
  {3.f/40.f,9.f/40.f,0.f,0.f,0.f},
  {44.f/45.f,-56.f/15.f,32.f/9.f,0.f,0.f},
  {19372.f/6561.f,-25360.f/2187.f,64448.f/6561.f,-212.f/729.f,0.f},
  {9017.f/3168.f,-355.f/33.f,46732.f/5247.f,49.f/176.f,-5103.f/18656.f}
};
__constant__ float cC[6] = {0.f,0.2f,0.3f,0.8f,8.f/9.f,1.f};

// ---------------- helpers ----------------
__device__ __forceinline__ uint32_t smem_u32(const void* p) {
  uint32_t a;
  asm("{ .reg .u64 t; cvta.to.shared.u64 t, %1; cvt.u32.u64 %0, t; }" : "=r"(a) : "l"(p));
  return a;
}
#define CVT_H2(res, lo, hi) \
  asm("cvt.rn.f16x2.f32 %0, %1, %2;" : "=r"(res) : "f"(hi), "f"(lo))

__device__ __forceinline__ void mma_f16h(uint32_t* c, const uint32_t* a, const uint32_t* b) {
  asm volatile(
    "mma.sync.aligned.m16n8k16.row.col.f16.f16.f16.f16 "
    "{%0,%1}, {%2,%3,%4,%5}, {%6,%7}, {%0,%1};"
    : "+r"(c[0]), "+r"(c[1])
    : "r"(a[0]), "r"(a[1]), "r"(a[2]), "r"(a[3]), "r"(b[0]), "r"(b[1]));
}
__device__ __forceinline__ void ldm4(uint32_t* r, uint32_t addr) {
  asm volatile("ldmatrix.sync.aligned.m8n8.x4.shared.b16 {%0,%1,%2,%3}, [%4];"
    : "=r"(r[0]), "=r"(r[1]), "=r"(r[2]), "=r"(r[3]) : "r"(addr));
}

#define MBAR_INIT(mbar, cnt) \
  asm volatile("mbarrier.init.shared.b64 [%0], %1;" :: "r"(mbar), "r"(cnt) : "memory")
#define MBAR_EXPECT(mbar, bytes) \
  asm volatile("mbarrier.arrive.expect_tx.shared.b64 _, [%0], %1;" :: "r"(mbar), "r"(bytes) : "memory")
#define MBAR_WAIT(mbar, par) do { \
  uint32_t _m = (mbar), _p = (par), _d; \
  asm volatile("{\n\t.reg .pred p;\n\tmbarrier.try_wait.parity.acquire.cta.shared::cta.b64 p, [%1], %2;\n\tselp.b32 %0, 1, 0, p;\n\t}" \
    : "=r"(_d) : "r"(_m), "r"(_p) : "memory"); \
  if (!_d) { \
    asm volatile("{\n\t.reg .pred P1;\n\tWL_%=:\n\tmbarrier.try_wait.parity.acquire.cta.shared::cta.b64 P1, [%0], %1, 0x989680;\n\t@P1 bra.uni WD_%=;\n\tbra.uni WL_%=;\n\tWD_%=:\n\t}" \
      :: "r"(_m), "r"(_p) : "memory"); \
  } \
} while (0)
#define BULK_LOAD(dst, src, bytes, mbar) \
  asm volatile("cp.async.bulk.shared::cluster.global.mbarrier::complete_tx::bytes [%0], [%1], %2, [%3];" \
    :: "r"(dst), "l"(src), "r"(bytes), "r"(mbar) : "memory")

// ---- smem layout (bytes), per 48-row CTA ----
#define SO_A    0
#define SO_B0   24576
#define SO_B1   57344
#define SO_B1S  90112
#define SO_B2S  91136
#define SO_B3S  92160
#define SO_WTS  92672
#define SO_BTS  93184
#define SO_RAT  93696
#define SO_MB   93952
#define SM_ODE  94208

// ---------------- weight prep: fp32 -> fp16, 32KB-block layout + XOR-granule swizzle ----------------
__global__ void prep_kernel(const float* __restrict__ W1, const float* __restrict__ W2,
                            const float* __restrict__ W3) {
  int i = blockIdx.x * 256 + threadIdx.x;
  if (i < 32768) {                       // W1 [N=256][K=128] -> blocks 0,1 (row 64 halves)
    int n = i >> 7, k = i & 127;
    int blk = k >> 6, kl = k & 63;
    int dst = blk * 16384 + n * 64 + (((kl >> 3) ^ (n & 7)) << 3) + (kl & 7);
    g_wh[dst] = __float2half_rn(W1[k * 256 + n]);
  } else if (i < 98304) {                // W2 [N=256][K=256] -> blocks 2..5
    int e = i - 32768; int n = e >> 8, k = e & 255;
    int blk = 2 + (k >> 6), kl = k & 63;
    int dst = blk * 16384 + n * 64 + (((kl >> 3) ^ (n & 7)) << 3) + (kl & 7);
    g_wh[dst] = __float2half_rn(W2[k * 256 + n]);
  } else {                               // W3 [N=128][K=256] -> blocks 6,7 (row 128 halves)
    int e = i - 98304; int n = e >> 8, k = e & 255;
    int blk = 6 + (k >> 7), kl = k & 127;
    int dst = blk * 16384 + n * 128 + (((kl >> 3) ^ (n & 7)) << 3) + (kl & 7);
    g_wh[dst] = __float2half_rn(W3[k * 128 + n]);
  }
}

// ---------------- MMA span over a resident 32KB B block ----------------
// RBS: 7 for 128B B rows (64-K blocks), 8 for 256B rows (W3 128-K blocks).
template<int NT, int NKS, int RBS>
__device__ __forceinline__ void mma_span(
    uint32_t ab, uint32_t bb, int kbaseA,
    int ncb, int mg, int lane, uint32_t (*c)[2]) {
  int m = lane >> 3;
  int row = 16 * mg + (m & 1) * 8 + (lane & 7);
  int g = lane >> 3, rr = lane & 7;
  #pragma unroll
  for (int ks = 0; ks < NKS; ks++) {
    int kcolA = kbaseA + ks * 16 + (m >> 1) * 8;
    uint32_t aoff = (uint32_t)((row << 9) + ((((kcolA >> 3) ^ (row & 7))) << 4));
    uint32_t af[4];
    ldm4(af, ab + aoff);
    int kcolB = ks * 16 + (g & 1) * 8;
    #pragma unroll
    for (int nt2 = 0; nt2 < NT / 2; nt2++) {
      int n = ncb + nt2 * 16 + (g >> 1) * 8 + rr;
      uint32_t boff = (uint32_t)((n << RBS) + ((((kcolB >> 3) ^ (n & 7))) << 4));
      uint32_t rb[4];
      ldm4(rb, bb + boff);
      mma_f16h(c[nt2 * 2],     af, rb);
      mma_f16h(c[nt2 * 2 + 1], af, rb + 2);
    }
  }
}

template<int NT>
__device__ __forceinline__ void init_bias_frag(uint32_t (*c)[2], const float* bias, int ncb, int lane) {
  #pragma unroll
  for (int nt = 0; nt < NT; nt++) {
    int cc = ncb + nt * 8 + (lane & 3) * 2;
    uint32_t hp; CVT_H2(hp, bias[cc], bias[cc + 1]);
    c[nt][0] = hp; c[nt][1] = hp;
  }
}

// tanh epilogue: single tanh.approx.f16x2 per packed pair (bias pre-added in acc)
template<int NT>
__device__ __forceinline__ void epi_tanh(uint32_t (*c)[2], uint32_t ab,
                                         int ncb, int mg, int lane) {
  int row = 16 * mg + (lane >> 2);
  #pragma unroll
  for (int nt = 0; nt < NT; nt++) {
    int col = ncb + nt * 8 + (lane & 3) * 2;
    #pragma unroll
    for (int h = 0; h < 2; h++) {
      int rh = row + 8 * h;
      uint32_t t;
      asm("tanh.approx.f16x2 %0, %1;" : "=r"(t) : "r"(c[nt][h]));
      uint32_t off = (uint32_t)((rh << 9) + ((((col >> 3) ^ (rh & 7))) << 4) + ((col & 7) << 1));
      asm volatile("st.shared.b32 [%0], %1;" :: "r"(ab + off), "r"(t) : "memory");
    }
  }
}

extern __shared__ char smem_raw[];

// one pipelined weight block: wait data, MMA, retire-sync, reissue this buffer 2 blocks ahead
#define DO_BLOCK(NT_, NKS_, RBS_, KBASE_, NCB_, CARR_) do { \
  uint32_t bb_ = (blk & 1) ? wb1 : wb0; \
  uint32_t mb_ = (blk & 1) ? mb1 : mb0; \
  if (blk & 1) { MBAR_WAIT(mb1, ph1); ph1 ^= 1; } \
  else         { MBAR_WAIT(mb0, ph0); ph0 ^= 1; } \
  mma_span<NT_, NKS_, RBS_>(ab, bb_, KBASE_, NCB_, mg, lane, CARR_); \
  __syncthreads(); \
  if (tid == 0 && blk + 2 < 384) { \
    MBAR_EXPECT(mb_, 32768); \
    BULK_LOAD(bb_, (const void*)(g_wh + (((blk + 2) & 7) * 16384)), 32768, mb_); \
  } \
  blk++; \
} while (0)

__global__ void __launch_bounds__(192, 2) ode_kernel(
    const float* __restrict__ z, const float* __restrict__ ts,
    const float* __restrict__ w_t, const float* __restrict__ b_t,
    const float* __restrict__ b1, const float* __restrict__ b2, const float* __restrict__ b3) {
  const uint32_t base = smem_u32(smem_raw);
  float* b1s = (float*)(smem_raw + SO_B1S);
  float* b2s = (float*)(smem_raw + SO_B2S);
  float* b3s = (float*)(smem_raw + SO_B3S);
  float* wts = (float*)(smem_raw + SO_WTS);
  float* bts = (float*)(smem_raw + SO_BTS);
  float* rat = (float*)(smem_raw + SO_RAT);
  const uint32_t ab = base + SO_A;
  const uint32_t wb0 = base + SO_B0, wb1 = base + SO_B1;
  const uint32_t mb0 = base + SO_MB, mb1 = base + SO_MB + 8;
  const int tid = threadIdx.x;
  const int lane = tid & 31, w = tid >> 5;
  const int mg = w >> 1, ng = w & 1;   // mg 0..2 (16 rows), ng 0..1
  const int R0 = blockIdx.x * 48;

  if (tid < 48) rat[tid] = ts[R0 + tid];
  if (tid < 128) {
    wts[tid] = w_t[tid];
    bts[tid] = b_t[tid];
    b3s[tid] = b3[tid];
  }
  for (int i = tid; i < 256; i += 192) { b1s[i] = b1[i]; b2s[i] = b2[i]; }
  if (tid == 0) { MBAR_INIT(mb0, 1); MBAR_INIT(mb1, 1); }
  for (int p = tid; p < 48 * 64; p += 192) {
    int r = p >> 6, k2 = (p & 63) * 2;
    float2 zz = *(const float2*)(z + ((R0 + r) & 63) * Z_D + k2);
    *(float2*)(g_y + (size_t)(R0 + r) * Z_D + k2) = zz;
  }
  __syncthreads();
  if (tid == 0) {                        // bootstrap: blocks 0,1
    MBAR_EXPECT(mb0, 32768);
    BULK_LOAD(wb0, (const void*)(g_wh + 0), 32768, mb0);
    MBAR_EXPECT(mb1, 32768);
    BULK_LOAD(wb1, (const void*)(g_wh + 16384), 32768, mb1);
  }

  int blk = 0, ph0 = 0, ph1 = 0;
  for (int step = 0; step < N_STEPS; step++) {
    float s0 = step * DT_F;
    for (int st = 0; st < 6; st++) {
      float tst = s0 + cC[st] * DT_F;
      // ---- build stage input into fp16 A (48 x 128) ----
      for (int p = tid; p < 48 * 64; p += 192) {
        int r = p >> 6, k2 = (p & 63) * 2;
        size_t gi = (size_t)(R0 + r) * Z_D + k2;
        float2 v = *(const float2*)(g_y + gi);
        #pragma unroll 1
        for (int j = 0; j < st; j++) {
          uint32_t kp = *(const uint32_t*)(&g_k[j][gi]);
          float2 kk = __half22float2(*reinterpret_cast<__half2*>(&kp));
          float cj = DT_F * cA[st][j];
          v.x += cj * kk.x; v.y += cj * kk.y;
        }
        float tr = tst * rat[r];
        v.x += __cosf(fmaf(tr, wts[k2], bts[k2]));
        v.y += __cosf(fmaf(tr, wts[k2 + 1], bts[k2 + 1]));
        uint32_t hp; CVT_H2(hp, v.x, v.y);
        uint32_t off = (uint32_t)((r << 9) + ((((k2 >> 3) ^ (r & 7))) << 4) + ((k2 & 7) << 1));
        asm volatile("st.shared.b32 [%0], %1;" :: "r"(ab + off), "r"(hp) : "memory");
      }
      __syncthreads();                   // A ready
      {   // layer 1: K=128 (blocks 0,1) -> N=256, tanh
        uint32_t c[16][2];
        init_bias_frag<16>(c, b1s, ng * 128, lane);
        DO_BLOCK(16, 4, 7, 0,  ng * 128, c);
        DO_BLOCK(16, 4, 7, 64, ng * 128, c);
        epi_tanh<16>(c, ab, ng * 128, mg, lane);
      }
      __syncthreads();                   // A rewritten
      {   // layer 2: K=256 (blocks 2..5) -> N=256, tanh
        uint32_t c[16][2];
        init_bias_frag<16>(c, b2s, ng * 128, lane);
        DO_BLOCK(16, 4, 7, 0,   ng * 128, c);
        DO_BLOCK(16, 4, 7, 64,  ng * 128, c);
        DO_BLOCK(16, 4, 7, 128, ng * 128, c);
        DO_BLOCK(16, 4, 7, 192, ng * 128, c);
        epi_tanh<16>(c, ab, ng * 128, mg, lane);
      }
      __syncthreads();                   // A rewritten
      {   // layer 3: K=256 (blocks 6,7) -> N=128, * ratio -> g_k[st] (fp16)
        uint32_t c[8][2];
        init_bias_frag<8>(c, b3s, ng * 64, lane);
        DO_BLOCK(8, 8, 8, 0,   ng * 64, c);
        DO_BLOCK(8, 8, 8, 128, ng * 64, c);
        int row = 16 * mg + (lane >> 2);
        #pragma unroll
        for (int nt = 0; nt < 8; nt++) {
          int col = ng * 64 + nt * 8 + (lane & 3) * 2;
          #pragma unroll
          for (int h = 0; h < 2; h++) {
            int rr = row + 8 * h;
            float sc = rat[rr];
            uint32_t scp; CVT_H2(scp, sc, sc);
            __half2 prod = __hmul2(*reinterpret_cast<__half2*>(&c[nt][h]),
                                   *reinterpret_cast<__half2*>(&scp));
            *(uint32_t*)(&g_k[st][(size_t)(R0 + rr) * Z_D + col]) =
                *reinterpret_cast<uint32_t*>(&prod);
          }
        }
      }
      __syncthreads();                   // g_k visible
    }
    // ---- y += dt * sum bw_j k_j ----
    for (int p = tid; p < 48 * 64; p += 192) {
      int r = p >> 6, k2 = (p & 63) * 2;
      size_t gi = (size_t)(R0 + r) * Z_D + k2;
      float2 y = *(float2*)(g_y + gi);
      const float cw[6] = {35.f/384.f, 0.f, 500.f/1113.f, 125.f/192.f,
                           -2187.f/6784.f, 11.f/84.f};
      #pragma unroll
      for (int j = 0; j < 6; j++) {
        if (j == 1) continue;
        uint32_t kp = *(const uint32_t*)(&g_k[j][gi]);
        float2 kk = __half22float2(*reinterpret_cast<__half2*>(&kp));
        y.x += DT_F * cw[j] * kk.x;
        y.y += DT_F * cw[j] * kk.y;
      }
      *(float2*)(g_y + gi) = y;
    }
    __syncthreads();
  }
}

// ---------------- decode_fc: 64 rows/block ----------------
__global__ void __launch_bounds__(256) dec_kernel(
    const float* __restrict__ x, const float* __restrict__ Wd, const float* __restrict__ bd) {
  __shared__ float xs[172];
  __shared__ float ys[64 * 128];
  const int tid = threadIdx.x;
  const int b = blockIdx.x, R0 = b * 64;
  for (int i = tid; i < 172; i += 256) xs[i] = x[(size_t)b * 172 + i];
  for (int i = tid; i < 64 * 128; i += 256) ys[i] = g_y[(size_t)R0 * 128 + i];
  __syncthreads();
  float acc0 = bd[tid];
  #pragma unroll 4
  for (int k = 0; k < 172; k++) acc0 = fmaf(xs[k], Wd[(size_t)k * 256 + tid], acc0);
  float acc[64];
  #pragma unroll
  for (int r = 0; r < 64; r++) acc[r] = acc0;
  #pragma unroll 2
  for (int k = 0; k < 128; k++) {
    float w = Wd[(size_t)(172 + k) * 256 + tid];
    #pragma unroll
    for (int r = 0; r < 64; r++) acc[r] = fmaf(ys[r * 128 + k], w, acc[r]);
  }
  #pragma unroll
  for (int r = 0; r < 64; r++) g_h[(size_t)(R0 + r) * 256 + tid] = acc[r];
}

// ---------------- src/dst fc: 32 rows/block ----------------
__global__ void __launch_bounds__(256) sd_kernel(
    const float* __restrict__ Ws, const float* __restrict__ bs,
    const float* __restrict__ Wdst, const float* __restrict__ bdst) {
  __shared__ float hs[32 * 256];
  const int tid = threadIdx.x;
  const int R0 = blockIdx.x * 32;
  const float* W = (R0 < 4096) ? Ws : Wdst;
  const float* bb = (R0 < 4096) ? bs : bdst;
  for (int i = tid; i < 32 * 256; i += 256) hs[i] = g_h[(size_t)R0 * 256 + i];
  __syncthreads();
  float acc[32];
  float b0 = bb[tid];
  #pragma unroll
  for (int r = 0; r < 32; r++) acc[r] = b0;
  #pragma unroll 2
  for (int k = 0; k < 256; k++) {
    float w = W[(size_t)k * 256 + tid];
    #pragma unroll
    for (int r = 0; r < 32; r++) acc[r] = fmaf(hs[r * 256 + k], w, acc[r]);
  }
  #pragma unroll
  for (int r = 0; r < 32; r++) g_s[(size_t)(R0 + r) * 256 + tid] = acc[r];
}

// ---------------- edge out + mean over L ----------------
__global__ void __launch_bounds__(256) edge_kernel(
    const float* __restrict__ Wo, const float* __restrict__ bo, float* __restrict__ out) {
  __shared__ float red[8];
  const int tid = threadIdx.x;
  const int o = blockIdx.x;
  const int b = (o < 64) ? o : (o - 64);
  const size_t off2 = (o < 64) ? (size_t)4096 * H_D : (size_t)8192 * H_D;
  const float wcol = Wo[tid];
  float sum = 0.f;
  for (int l = 0; l < 64; l++) {
    size_t r1 = (size_t)(b * 64 + l) * H_D + tid;
    float v = g_s[r1] + g_s[off2 + r1];
    sum += fmaxf(v, 0.f) * wcol;
  }
  #pragma unroll
  for (int d = 16; d > 0; d >>= 1) sum += __shfl_xor_sync(0xFFFFFFFFu, sum, d);
  if ((tid & 31) == 0) red[tid >> 5] = sum;
  __syncthreads();
  if (tid == 0) {
    float t = 0.f;
    #pragma unroll
    for (int w = 0; w < 8; w++) t += red[w];
    out[o] = t * (1.f / 64.f) + bo[0];
  }
}

extern "C" void kernel_launch(void* const* d_in, const int* in_sizes, int n_in,
                              void* d_out, int out_size) {
  const float* x    = (const float*)d_in[0];
  const float* z    = (const float*)d_in[1];
  const float* ts   = (const float*)d_in[2];
  const float* w_t  = (const float*)d_in[3];
  const float* b_t  = (const float*)d_in[4];
  const float* W1   = (const float*)d_in[5];
  const float* b1   = (const float*)d_in[6];
  const float* W2   = (const float*)d_in[7];
  const float* b2   = (const float*)d_in[8];
  const float* W3   = (const float*)d_in[9];
  const float* b3   = (const float*)d_in[10];
  const float* Wd   = (const float*)d_in[11];
  const float* bd   = (const float*)d_in[12];
  const float* Ws   = (const float*)d_in[13];
  const float* bs   = (const float*)d_in[14];
  const float* Wdst = (const float*)d_in[15];
  const float* bdst = (const float*)d_in[16];
  const float* Wo   = (const float*)d_in[17];
  const float* bo   = (const float*)d_in[18];
  float* out = (float*)d_out;

  cudaFuncSetAttribute(ode_kernel, cudaFuncAttributeMaxDynamicSharedMemorySize, SM_ODE);

  prep_kernel<<<512, 256>>>(W1, W2, W3);
  ode_kernel<<<256, 192, SM_ODE>>>(z, ts, w_t, b_t, b1, b2, b3);
  dec_kernel<<<192, 256>>>(x, Wd, bd);
  sd_kernel<<<384, 256>>>(Ws, bs, Wdst, bdst);
  edge_kernel<<<128, 256>>>(Wo, bo, out);
}

// round 13
// speedup vs baseline: 5.3072x; 1.1451x over previous
#include <cuda_runtime.h>
#include <cuda_fp16.h>
#include <cstdint>

#define N_ROWS 12288
#define Z_D 128
#define H_D 256
#define N_STEPS 8
#define DT_F 0.125f

__device__ __half g_k[6][N_ROWS * Z_D];
__device__ float g_y[N_ROWS * Z_D];
__device__ float g_h[N_ROWS * H_D];
__device__ float g_s[N_ROWS * H_D];
// 8 sequential 32KB blocks (16384 halves each):
// B0=W1[k0:64] B1=W1[k64:128] B2..B5=W2[k*64 quarters] B6=W3[k0:128] B7=W3[k128:256]
__device__ __half g_wh[131072];

__constant__ float cA[6][5] = {
  {0.f,0.f,0.f,0.f,0.f},
  {0.2f,0.f,0.f,0.f,0.f},
  {3.f/40.f,9.f/40.f,0.f,0.f,0.f},
  {44.f/45.f,-56.f/15.f,32.f/9.f,0.f,0.f},
  {19372.f/6561.f,-25360.f/2187.f,64448.f/6561.f,-212.f/729.f,0.f},
  {9017.f/3168.f,-355.f/33.f,46732.f/5247.f,49.f/176.f,-5103.f/18656.f}
};
__constant__ float cC[6] = {0.f,0.2f,0.3f,0.8f,8.f/9.f,1.f};

// ---------------- helpers ----------------
__device__ __forceinline__ uint32_t smem_u32(const void* p) {
  uint32_t a;
  asm("{ .reg .u64 t; cvta.to.shared.u64 t, %1; cvt.u32.u64 %0, t; }" : "=r"(a) : "l"(p));
  return a;
}
#define CVT_H2(res, lo, hi) \
  asm("cvt.rn.f16x2.f32 %0, %1, %2;" : "=r"(res) : "f"(hi), "f"(lo))

__device__ __forceinline__ void mma_f16h(uint32_t* c, const uint32_t* a, const uint32_t* b) {
  asm volatile(
    "mma.sync.aligned.m16n8k16.row.col.f16.f16.f16.f16 "
    "{%0,%1}, {%2,%3,%4,%5}, {%6,%7}, {%0,%1};"
    : "+r"(c[0]), "+r"(c[1])
    : "r"(a[0]), "r"(a[1]), "r"(a[2]), "r"(a[3]), "r"(b[0]), "r"(b[1]));
}
__device__ __forceinline__ void ldm4(uint32_t* r, uint32_t addr) {
  asm volatile("ldmatrix.sync.aligned.m8n8.x4.shared.b16 {%0,%1,%2,%3}, [%4];"
    : "=r"(r[0]), "=r"(r[1]), "=r"(r[2]), "=r"(r[3]) : "r"(addr));
}

#define MBAR_INIT(mbar, cnt) \
  asm volatile("mbarrier.init.shared.b64 [%0], %1;" :: "r"(mbar), "r"(cnt) : "memory")
#define MBAR_EXPECT(mbar, bytes) \
  asm volatile("mbarrier.arrive.expect_tx.shared.b64 _, [%0], %1;" :: "r"(mbar), "r"(bytes) : "memory")
#define MBAR_ARRIVE(mbar) \
  asm volatile("mbarrier.arrive.shared.b64 _, [%0];" :: "r"(mbar) : "memory")
#define MBAR_WAIT(mbar, par) do { \
  uint32_t _m = (mbar), _p = (par), _d; \
  asm volatile("{\n\t.reg .pred p;\n\tmbarrier.try_wait.parity.acquire.cta.shared::cta.b64 p, [%1], %2;\n\tselp.b32 %0, 1, 0, p;\n\t}" \
    : "=r"(_d) : "r"(_m), "r"(_p) : "memory"); \
  if (!_d) { \
    asm volatile("{\n\t.reg .pred P1;\n\tWL_%=:\n\tmbarrier.try_wait.parity.acquire.cta.shared::cta.b64 P1, [%0], %1, 0x989680;\n\t@P1 bra.uni WD_%=;\n\tbra.uni WL_%=;\n\tWD_%=:\n\t}" \
      :: "r"(_m), "r"(_p) : "memory"); \
  } \
} while (0)
#define BULK_LOAD(dst, src, bytes, mbar) \
  asm volatile("cp.async.bulk.shared::cluster.global.mbarrier::complete_tx::bytes [%0], [%1], %2, [%3];" \
    :: "r"(dst), "l"(src), "r"(bytes), "r"(mbar) : "memory")
#define PAIR_BAR(mgid) \
  asm volatile("bar.sync %0, 64;" :: "r"(1 + (mgid)) : "memory")

// ---- smem layout (bytes), per 48-row CTA ----
#define SO_A    0
#define SO_B0   24576
#define SO_B1   57344
#define SO_B1S  90112
#define SO_B2S  91136
#define SO_B3S  92160
#define SO_WTS  92672
#define SO_BTS  93184
#define SO_RAT  93696
#define SO_MB   93952
#define SM_ODE  94208

// ---------------- weight prep: fp32 -> fp16, 32KB-block layout + XOR-granule swizzle ----------------
__global__ void prep_kernel(const float* __restrict__ W1, const float* __restrict__ W2,
                            const float* __restrict__ W3) {
  int i = blockIdx.x * 256 + threadIdx.x;
  if (i < 32768) {                       // W1 [N=256][K=128] -> blocks 0,1 (row 64 halves)
    int n = i >> 7, k = i & 127;
    int blk = k >> 6, kl = k & 63;
    int dst = blk * 16384 + n * 64 + (((kl >> 3) ^ (n & 7)) << 3) + (kl & 7);
    g_wh[dst] = __float2half_rn(W1[k * 256 + n]);
  } else if (i < 98304) {                // W2 [N=256][K=256] -> blocks 2..5
    int e = i - 32768; int n = e >> 8, k = e & 255;
    int blk = 2 + (k >> 6), kl = k & 63;
    int dst = blk * 16384 + n * 64 + (((kl >> 3) ^ (n & 7)) << 3) + (kl & 7);
    g_wh[dst] = __float2half_rn(W2[k * 256 + n]);
  } else {                               // W3 [N=128][K=256] -> blocks 6,7 (row 128 halves)
    int e = i - 98304; int n = e >> 8, k = e & 255;
    int blk = 6 + (k >> 7), kl = k & 127;
    int dst = blk * 16384 + n * 128 + (((kl >> 3) ^ (n & 7)) << 3) + (kl & 7);
    g_wh[dst] = __float2half_rn(W3[k * 128 + n]);
  }
}

// ---------------- MMA span over a resident 32KB B block ----------------
template<int NT, int NKS, int RBS>
__device__ __forceinline__ void mma_span(
    uint32_t ab, uint32_t bb, int kbaseA,
    int ncb, int mg, int lane, uint32_t (*c)[2]) {
  int m = lane >> 3;
  int row = 16 * mg + (m & 1) * 8 + (lane & 7);
  int g = lane >> 3, rr = lane & 7;
  #pragma unroll
  for (int ks = 0; ks < NKS; ks++) {
    int kcolA = kbaseA + ks * 16 + (m >> 1) * 8;
    uint32_t aoff = (uint32_t)((row << 9) + ((((kcolA >> 3) ^ (row & 7))) << 4));
    uint32_t af[4];
    ldm4(af, ab + aoff);
    int kcolB = ks * 16 + (g & 1) * 8;
    #pragma unroll
    for (int nt2 = 0; nt2 < NT / 2; nt2++) {
      int n = ncb + nt2 * 16 + (g >> 1) * 8 + rr;
      uint32_t boff = (uint32_t)((n << RBS) + ((((kcolB >> 3) ^ (n & 7))) << 4));
      uint32_t rb[4];
      ldm4(rb, bb + boff);
      mma_f16h(c[nt2 * 2],     af, rb);
      mma_f16h(c[nt2 * 2 + 1], af, rb + 2);
    }
  }
}

template<int NT>
__device__ __forceinline__ void init_bias_frag(uint32_t (*c)[2], const float* bias, int ncb, int lane) {
  #pragma unroll
  for (int nt = 0; nt < NT; nt++) {
    int cc = ncb + nt * 8 + (lane & 3) * 2;
    uint32_t hp; CVT_H2(hp, bias[cc], bias[cc + 1]);
    c[nt][0] = hp; c[nt][1] = hp;
  }
}

// tanh epilogue: warp-private rows/cols
template<int NT>
__device__ __forceinline__ void epi_tanh(uint32_t (*c)[2], uint32_t ab,
                                         int ncb, int mg, int lane) {
  int row = 16 * mg + (lane >> 2);
  #pragma unroll
  for (int nt = 0; nt < NT; nt++) {
    int col = ncb + nt * 8 + (lane & 3) * 2;
    #pragma unroll
    for (int h = 0; h < 2; h++) {
      int rh = row + 8 * h;
      uint32_t t;
      asm("tanh.approx.f16x2 %0, %1;" : "=r"(t) : "r"(c[nt][h]));
      uint32_t off = (uint32_t)((rh << 9) + ((((col >> 3) ^ (rh & 7))) << 4) + ((col & 7) << 1));
      asm volatile("st.shared.b32 [%0], %1;" :: "r"(ab + off), "r"(t) : "memory");
    }
  }
}

extern __shared__ char smem_raw[];

// pipelined weight block: full-wait, MMA, per-warp empty-arrive; warp0 waits empty + reissues.
#define DO_BLOCK(NT_, NKS_, RBS_, KBASE_, NCB_, CARR_) do { \
  uint32_t bb_ = (blk & 1) ? wb1 : wb0; \
  if (blk & 1) { MBAR_WAIT(mb1, ph1); ph1 ^= 1; } \
  else         { MBAR_WAIT(mb0, ph0); ph0 ^= 1; } \
  mma_span<NT_, NKS_, RBS_>(ab, bb_, KBASE_, NCB_, mg, lane, CARR_); \
  if (lane == 0) MBAR_ARRIVE((blk & 1) ? me1 : me0); \
  if (w == 0 && blk + 2 < 384) { \
    if (blk & 1) { MBAR_WAIT(me1, qe1); qe1 ^= 1; } \
    else         { MBAR_WAIT(me0, qe0); qe0 ^= 1; } \
    if (lane == 0) { \
      uint32_t mbf_ = (blk & 1) ? mb1 : mb0; \
      MBAR_EXPECT(mbf_, 32768); \
      BULK_LOAD(bb_, (const void*)(g_wh + (((blk + 2) & 7) * 16384)), 32768, mbf_); \
    } \
  } \
  blk++; \
} while (0)

__global__ void __launch_bounds__(192, 2) ode_kernel(
    const float* __restrict__ z, const float* __restrict__ ts,
    const float* __restrict__ w_t, const float* __restrict__ b_t,
    const float* __restrict__ b1, const float* __restrict__ b2, const float* __restrict__ b3) {
  const uint32_t base = smem_u32(smem_raw);
  float* b1s = (float*)(smem_raw + SO_B1S);
  float* b2s = (float*)(smem_raw + SO_B2S);
  float* b3s = (float*)(smem_raw + SO_B3S);
  float* wts = (float*)(smem_raw + SO_WTS);
  float* bts = (float*)(smem_raw + SO_BTS);
  float* rat = (float*)(smem_raw + SO_RAT);
  const uint32_t ab = base + SO_A;
  const uint32_t wb0 = base + SO_B0, wb1 = base + SO_B1;
  const uint32_t mb0 = base + SO_MB, mb1 = base + SO_MB + 8;
  const uint32_t me0 = base + SO_MB + 16, me1 = base + SO_MB + 24;
  const int tid = threadIdx.x;
  const int lane = tid & 31, w = tid >> 5;
  const int mg = w >> 1, ng = w & 1;   // mg 0..2 (16 rows), ng 0..1 (col half)
  const int R0 = blockIdx.x * 48;

  if (tid < 48) rat[tid] = ts[R0 + tid];
  if (tid < 128) {
    wts[tid] = w_t[tid];
    bts[tid] = b_t[tid];
    b3s[tid] = b3[tid];
  }
  for (int i = tid; i < 256; i += 192) { b1s[i] = b1[i]; b2s[i] = b2[i]; }
  if (tid == 0) {
    MBAR_INIT(mb0, 1); MBAR_INIT(mb1, 1);
    MBAR_INIT(me0, 6); MBAR_INIT(me1, 6);
  }
  for (int p = tid; p < 48 * 64; p += 192) {
    int r = p >> 6, k2 = (p & 63) * 2;
    float2 zz = *(const float2*)(z + ((R0 + r) & 63) * Z_D + k2);
    *(float2*)(g_y + (size_t)(R0 + r) * Z_D + k2) = zz;
  }
  __syncthreads();
  if (tid == 0) {                        // bootstrap: blocks 0,1
    MBAR_EXPECT(mb0, 32768);
    BULK_LOAD(wb0, (const void*)(g_wh + 0), 32768, mb0);
    MBAR_EXPECT(mb1, 32768);
    BULK_LOAD(wb1, (const void*)(g_wh + 16384), 32768, mb1);
  }

  int blk = 0, ph0 = 0, ph1 = 0, qe0 = 0, qe1 = 0;
  for (int step = 0; step < N_STEPS; step++) {
    float s0 = step * DT_F;
    for (int st = 0; st < 6; st++) {
      float tst = s0 + cC[st] * DT_F;
      // ---- warp-private build: own 16 rows, own 64-col half ----
      for (int q = lane; q < 16 * 32; q += 32) {
        int r = 16 * mg + (q >> 5);
        int k2 = ng * 64 + (q & 31) * 2;
        size_t gi = (size_t)(R0 + r) * Z_D + k2;
        float2 v = *(const float2*)(g_y + gi);
        #pragma unroll 1
        for (int j = 0; j < st; j++) {
          uint32_t kp = *(const uint32_t*)(&g_k[j][gi]);
          float2 kk = __half22float2(*reinterpret_cast<__half2*>(&kp));
          float cj = DT_F * cA[st][j];
          v.x += cj * kk.x; v.y += cj * kk.y;
        }
        float tr = tst * rat[r];
        v.x += __cosf(fmaf(tr, wts[k2], bts[k2]));
        v.y += __cosf(fmaf(tr, wts[k2 + 1], bts[k2 + 1]));
        uint32_t hp; CVT_H2(hp, v.x, v.y);
        uint32_t off = (uint32_t)((r << 9) + ((((k2 >> 3) ^ (r & 7))) << 4) + ((k2 & 7) << 1));
        asm volatile("st.shared.b32 [%0], %1;" :: "r"(ab + off), "r"(hp) : "memory");
      }
      PAIR_BAR(mg);                      // A cols 0..127 visible within pair
      {   // layer 1: K=128 (blocks 0,1) -> N=256, tanh
        uint32_t c[16][2];
        init_bias_frag<16>(c, b1s, ng * 128, lane);
        DO_BLOCK(16, 4, 7, 0,  ng * 128, c);
        DO_BLOCK(16, 4, 7, 64, ng * 128, c);
        PAIR_BAR(mg);                    // partner's layer1 A reads done
        epi_tanh<16>(c, ab, ng * 128, mg, lane);
      }
      PAIR_BAR(mg);                      // epi1 visible
      {   // layer 2: K=256 (blocks 2..5) -> N=256, tanh
        uint32_t c[16][2];
        init_bias_frag<16>(c, b2s, ng * 128, lane);
        DO_BLOCK(16, 4, 7, 0,   ng * 128, c);
        DO_BLOCK(16, 4, 7, 64,  ng * 128, c);
        DO_BLOCK(16, 4, 7, 128, ng * 128, c);
        DO_BLOCK(16, 4, 7, 192, ng * 128, c);
        PAIR_BAR(mg);                    // partner's layer2 A reads done
        epi_tanh<16>(c, ab, ng * 128, mg, lane);
      }
      PAIR_BAR(mg);                      // epi2 visible
      {   // layer 3: K=256 (blocks 6,7) -> N=128, * ratio -> g_k[st] (fp16, own cells)
        uint32_t c[8][2];
        init_bias_frag<8>(c, b3s, ng * 64, lane);
        DO_BLOCK(8, 8, 8, 0,   ng * 64, c);
        DO_BLOCK(8, 8, 8, 128, ng * 64, c);
        int row = 16 * mg + (lane >> 2);
        #pragma unroll
        for (int nt = 0; nt < 8; nt++) {
          int col = ng * 64 + nt * 8 + (lane & 3) * 2;
          #pragma unroll
          for (int h = 0; h < 2; h++) {
            int rr = row + 8 * h;
            float sc = rat[rr];
            uint32_t scp; CVT_H2(scp, sc, sc);
            __half2 prod = __hmul2(*reinterpret_cast<__half2*>(&c[nt][h]),
                                   *reinterpret_cast<__half2*>(&scp));
            *(uint32_t*)(&g_k[st][(size_t)(R0 + rr) * Z_D + col]) =
                *reinterpret_cast<uint32_t*>(&prod);
          }
        }
      }
      PAIR_BAR(mg);                      // partner's layer3 A reads done (A rewritten next build)
    }
    // ---- y += dt * sum bw_j k_j (warp-private cells) ----
    for (int q = lane; q < 16 * 32; q += 32) {
      int r = 16 * mg + (q >> 5);
      int k2 = ng * 64 + (q & 31) * 2;
      size_t gi = (size_t)(R0 + r) * Z_D + k2;
      float2 y = *(float2*)(g_y + gi);
      const float cw[6] = {35.f/384.f, 0.f, 500.f/1113.f, 125.f/192.f,
                           -2187.f/6784.f, 11.f/84.f};
      #pragma unroll
      for (int j = 0; j < 6; j++) {
        if (j == 1) continue;
        uint32_t kp = *(const uint32_t*)(&g_k[j][gi]);
        float2 kk = __half22float2(*reinterpret_cast<__half2*>(&kp));
        y.x += DT_F * cw[j] * kk.x;
        y.y += DT_F * cw[j] * kk.y;
      }
      *(float2*)(g_y + gi) = y;
    }
  }
}

// ---------------- decode_fc: 64 rows/block, float4 smem reads ----------------
__global__ void __launch_bounds__(256) dec_kernel(
    const float* __restrict__ x, const float* __restrict__ Wd, const float* __restrict__ bd) {
  __shared__ float xs[172];
  __shared__ float ys[64 * 128];
  const int tid = threadIdx.x;
  const int b = blockIdx.x, R0 = b * 64;
  for (int i = tid; i < 172; i += 256) xs[i] = x[(size_t)b * 172 + i];
  for (int i = tid; i < 64 * 128; i += 256) ys[i] = g_y[(size_t)R0 * 128 + i];
  __syncthreads();
  float acc0 = bd[tid];
  #pragma unroll 4
  for (int k = 0; k < 172; k++) acc0 = fmaf(xs[k], Wd[(size_t)k * 256 + tid], acc0);
  float acc[64];
  #pragma unroll
  for (int r = 0; r < 64; r++) acc[r] = acc0;
  #pragma unroll 1
  for (int k = 0; k < 128; k += 4) {
    float w0 = Wd[(size_t)(172 + k) * 256 + tid];
    float w1 = Wd[(size_t)(173 + k) * 256 + tid];
    float w2 = Wd[(size_t)(174 + k) * 256 + tid];
    float w3 = Wd[(size_t)(175 + k) * 256 + tid];
    #pragma unroll
    for (int r = 0; r < 64; r++) {
      float4 h4 = *(const float4*)(&ys[r * 128 + k]);
      acc[r] = fmaf(h4.x, w0, acc[r]);
      acc[r] = fmaf(h4.y, w1, acc[r]);
      acc[r] = fmaf(h4.z, w2, acc[r]);
      acc[r] = fmaf(h4.w, w3, acc[r]);
    }
  }
  #pragma unroll
  for (int r = 0; r < 64; r++) g_h[(size_t)(R0 + r) * 256 + tid] = acc[r];
}

// ---------------- src/dst fc: 32 rows/block, float4 smem reads ----------------
__global__ void __launch_bounds__(256) sd_kernel(
    const float* __restrict__ Ws, const float* __restrict__ bs,
    const float* __restrict__ Wdst, const float* __restrict__ bdst) {
  __shared__ float hs[32 * 256];
  const int tid = threadIdx.x;
  const int R0 = blockIdx.x * 32;
  const float* W = (R0 < 4096) ? Ws : Wdst;
  const float* bb = (R0 < 4096) ? bs : bdst;
  for (int i = tid; i < 32 * 256; i += 256) hs[i] = g_h[(size_t)R0 * 256 + i];
  __syncthreads();
  float acc[32];
  float b0 = bb[tid];
  #pragma unroll
  for (int r = 0; r < 32; r++) acc[r] = b0;
  #pragma unroll 1
  for (int k = 0; k < 256; k += 4) {
    float w0 = W[(size_t)(k + 0) * 256 + tid];
    float w1 = W[(size_t)(k + 1) * 256 + tid];
    float w2 = W[(size_t)(k + 2) * 256 + tid];
    float w3 = W[(size_t)(k + 3) * 256 + tid];
    #pragma unroll
    for (int r = 0; r < 32; r++) {
      float4 h4 = *(const float4*)(&hs[r * 256 + k]);
      acc[r] = fmaf(h4.x, w0, acc[r]);
      acc[r] = fmaf(h4.y, w1, acc[r]);
      acc[r] = fmaf(h4.z, w2, acc[r]);
      acc[r] = fmaf(h4.w, w3, acc[r]);
    }
  }
  #pragma unroll
  for (int r = 0; r < 32; r++) g_s[(size_t)(R0 + r) * 256 + tid] = acc[r];
}

// ---------------- edge out + mean over L ----------------
__global__ void __launch_bounds__(256) edge_kernel(
    const float* __restrict__ Wo, const float* __restrict__ bo, float* __restrict__ out) {
  __shared__ float red[8];
  const int tid = threadIdx.x;
  const int o = blockIdx.x;
  const int b = (o < 64) ? o : (o - 64);
  const size_t off2 = (o < 64) ? (size_t)4096 * H_D : (size_t)8192 * H_D;
  const float wcol = Wo[tid];
  float sum = 0.f;
  for (int l = 0; l < 64; l++) {
    size_t r1 = (size_t)(b * 64 + l) * H_D + tid;
    float v = g_s[r1] + g_s[off2 + r1];
    sum += fmaxf(v, 0.f) * wcol;
  }
  #pragma unroll
  for (int d = 16; d > 0; d >>= 1) sum += __shfl_xor_sync(0xFFFFFFFFu, sum, d);
  if ((tid & 31) == 0) red[tid >> 5] = sum;
  __syncthreads();
  if (tid == 0) {
    float t = 0.f;
    #pragma unroll
    for (int w = 0; w < 8; w++) t += red[w];
    out[o] = t * (1.f / 64.f) + bo[0];
  }
}

extern "C" void kernel_launch(void* const* d_in, const int* in_sizes, int n_in,
                              void* d_out, int out_size) {
  const float* x    = (const float*)d_in[0];
  const float* z    = (const float*)d_in[1];
  const float* ts   = (const float*)d_in[2];
  const float* w_t  = (const float*)d_in[3];
  const float* b_t  = (const float*)d_in[4];
  const float* W1   = (const float*)d_in[5];
  const float* b1   = (const float*)d_in[6];
  const float* W2   = (const float*)d_in[7];
  const float* b2   = (const float*)d_in[8];
  const float* W3   = (const float*)d_in[9];
  const float* b3   = (const float*)d_in[10];
  const float* Wd   = (const float*)d_in[11];
  const float* bd   = (const float*)d_in[12];
  const float* Ws   = (const float*)d_in[13];
  const float* bs   = (const float*)d_in[14];
  const float* Wdst = (const float*)d_in[15];
  const float* bdst = (const float*)d_in[16];
  const float* Wo   = (const float*)d_in[17];
  const float* bo   = (const float*)d_in[18];
  float* out = (float*)d_out;

  cudaFuncSetAttribute(ode_kernel, cudaFuncAttributeMaxDynamicSharedMemorySize, SM_ODE);

  prep_kernel<<<512, 256>>>(W1, W2, W3);
  ode_kernel<<<256, 192, SM_ODE>>>(z, ts, w_t, b_t, b1, b2, b3);
  dec_kernel<<<192, 256>>>(x, Wd, bd);
  sd_kernel<<<384, 256>>>(Ws, bs, Wdst, bdst);
  edge_kernel<<<128, 256>>>(Wo, bo, out);
}

// round 14
// speedup vs baseline: 7.2257x; 1.3615x over previous
#include <cuda_runtime.h>
#include <cuda_fp16.h>
#include <cstdint>

#define N_ROWS 12288
#define Z_D 128
#define H_D 256
#define N_STEPS 8
#define DT_F 0.125f

__device__ __half g_k[6][N_ROWS * Z_D];
__device__ float g_y[N_ROWS * Z_D];
__device__ float g_h[N_ROWS * H_D];
__device__ float g_s[N_ROWS * H_D];
// 8 sequential 32KB blocks (16384 halves each):
// B0=W1[k0:64] B1=W1[k64:128] B2..B5=W2[k*64 quarters] B6=W3[k0:128] B7=W3[k128:256]
__device__ __half g_wh[131072];
// fp16 decode weights
__device__ __half g_wdh[76800];    // Wd [300][256]
__device__ __half g_wsh[65536];    // Ws [256][256]
__device__ __half g_wdsth[65536];  // Wdst [256][256]

__constant__ float cA[6][5] = {
  {0.f,0.f,0.f,0.f,0.f},
  {0.2f,0.f,0.f,0.f,0.f},
  {3.f/40.f,9.f/40.f,0.f,0.f,0.f},
  {44.f/45.f,-56.f/15.f,32.f/9.f,0.f,0.f},
  {19372.f/6561.f,-25360.f/2187.f,64448.f/6561.f,-212.f/729.f,0.f},
  {9017.f/3168.f,-355.f/33.f,46732.f/5247.f,49.f/176.f,-5103.f/18656.f}
};
__constant__ float cC[6] = {0.f,0.2f,0.3f,0.8f,8.f/9.f,1.f};

// ---------------- helpers ----------------
__device__ __forceinline__ uint32_t smem_u32(const void* p) {
  uint32_t a;
  asm("{ .reg .u64 t; cvta.to.shared.u64 t, %1; cvt.u32.u64 %0, t; }" : "=r"(a) : "l"(p));
  return a;
}
#define CVT_H2(res, lo, hi) \
  asm("cvt.rn.f16x2.f32 %0, %1, %2;" : "=r"(res) : "f"(hi), "f"(lo))

__device__ __forceinline__ void mma_f16h(uint32_t* c, const uint32_t* a, const uint32_t* b) {
  asm volatile(
    "mma.sync.aligned.m16n8k16.row.col.f16.f16.f16.f16 "
    "{%0,%1}, {%2,%3,%4,%5}, {%6,%7}, {%0,%1};"
    : "+r"(c[0]), "+r"(c[1])
    : "r"(a[0]), "r"(a[1]), "r"(a[2]), "r"(a[3]), "r"(b[0]), "r"(b[1]));
}
__device__ __forceinline__ void ldm4(uint32_t* r, uint32_t addr) {
  asm volatile("ldmatrix.sync.aligned.m8n8.x4.shared.b16 {%0,%1,%2,%3}, [%4];"
    : "=r"(r[0]), "=r"(r[1]), "=r"(r[2]), "=r"(r[3]) : "r"(addr));
}

#define MBAR_INIT(mbar, cnt) \
  asm volatile("mbarrier.init.shared.b64 [%0], %1;" :: "r"(mbar), "r"(cnt) : "memory")
#define MBAR_EXPECT(mbar, bytes) \
  asm volatile("mbarrier.arrive.expect_tx.shared.b64 _, [%0], %1;" :: "r"(mbar), "r"(bytes) : "memory")
#define MBAR_ARRIVE(mbar) \
  asm volatile("mbarrier.arrive.shared.b64 _, [%0];" :: "r"(mbar) : "memory")
#define MBAR_WAIT(mbar, par) do { \
  uint32_t _m = (mbar), _p = (par), _d; \
  asm volatile("{\n\t.reg .pred p;\n\tmbarrier.try_wait.parity.acquire.cta.shared::cta.b64 p, [%1], %2;\n\tselp.b32 %0, 1, 0, p;\n\t}" \
    : "=r"(_d) : "r"(_m), "r"(_p) : "memory"); \
  if (!_d) { \
    asm volatile("{\n\t.reg .pred P1;\n\tWL_%=:\n\tmbarrier.try_wait.parity.acquire.cta.shared::cta.b64 P1, [%0], %1, 0x989680;\n\t@P1 bra.uni WD_%=;\n\tbra.uni WL_%=;\n\tWD_%=:\n\t}" \
      :: "r"(_m), "r"(_p) : "memory"); \
  } \
} while (0)
#define BULK_LOAD(dst, src, bytes, mbar) \
  asm volatile("cp.async.bulk.shared::cluster.global.mbarrier::complete_tx::bytes [%0], [%1], %2, [%3];" \
    :: "r"(dst), "l"(src), "r"(bytes), "r"(mbar) : "memory")
#define PAIR_BAR(mgid) \
  asm volatile("bar.sync %0, 64;" :: "r"(1 + (mgid)) : "memory")

// ---- smem layout (bytes), per 48-row CTA ----
#define SO_A    0
#define SO_B0   24576
#define SO_B1   57344
#define SO_B1S  90112
#define SO_B2S  91136
#define SO_B3S  92160
#define SO_WTS  92672
#define SO_BTS  93184
#define SO_RAT  93696
#define SO_MB   93952
#define SM_ODE  94208

// ---------------- weight prep: fp32 -> fp16, 32KB-block layout + XOR-granule swizzle ----------------
__global__ void prep_kernel(const float* __restrict__ W1, const float* __restrict__ W2,
                            const float* __restrict__ W3) {
  int i = blockIdx.x * 256 + threadIdx.x;
  if (i < 32768) {                       // W1 [N=256][K=128] -> blocks 0,1 (row 64 halves)
    int n = i >> 7, k = i & 127;
    int blk = k >> 6, kl = k & 63;
    int dst = blk * 16384 + n * 64 + (((kl >> 3) ^ (n & 7)) << 3) + (kl & 7);
    g_wh[dst] = __float2half_rn(W1[k * 256 + n]);
  } else if (i < 98304) {                // W2 [N=256][K=256] -> blocks 2..5
    int e = i - 32768; int n = e >> 8, k = e & 255;
    int blk = 2 + (k >> 6), kl = k & 63;
    int dst = blk * 16384 + n * 64 + (((kl >> 3) ^ (n & 7)) << 3) + (kl & 7);
    g_wh[dst] = __float2half_rn(W2[k * 256 + n]);
  } else {                               // W3 [N=128][K=256] -> blocks 6,7 (row 128 halves)
    int e = i - 98304; int n = e >> 8, k = e & 255;
    int blk = 6 + (k >> 7), kl = k & 127;
    int dst = blk * 16384 + n * 128 + (((kl >> 3) ^ (n & 7)) << 3) + (kl & 7);
    g_wh[dst] = __float2half_rn(W3[k * 128 + n]);
  }
}

// ---------------- decode weight prep: fp32 -> fp16 straight copy ----------------
__global__ void prep2_kernel(const float* __restrict__ Wd, const float* __restrict__ Ws,
                             const float* __restrict__ Wdst) {
  int i = blockIdx.x * 256 + threadIdx.x;
  if (i < 76800)        g_wdh[i] = __float2half_rn(Wd[i]);
  else if (i < 142336)  g_wsh[i - 76800] = __float2half_rn(Ws[i - 76800]);
  else if (i < 207872)  g_wdsth[i - 142336] = __float2half_rn(Wdst[i - 142336]);
}

// ---------------- MMA span over a resident 32KB B block ----------------
template<int NT, int NKS, int RBS>
__device__ __forceinline__ void mma_span(
    uint32_t ab, uint32_t bb, int kbaseA,
    int ncb, int mg, int lane, uint32_t (*c)[2]) {
  int m = lane >> 3;
  int row = 16 * mg + (m & 1) * 8 + (lane & 7);
  int g = lane >> 3, rr = lane & 7;
  #pragma unroll
  for (int ks = 0; ks < NKS; ks++) {
    int kcolA = kbaseA + ks * 16 + (m >> 1) * 8;
    uint32_t aoff = (uint32_t)((row << 9) + ((((kcolA >> 3) ^ (row & 7))) << 4));
    uint32_t af[4];
    ldm4(af, ab + aoff);
    int kcolB = ks * 16 + (g & 1) * 8;
    #pragma unroll
    for (int nt2 = 0; nt2 < NT / 2; nt2++) {
      int n = ncb + nt2 * 16 + (g >> 1) * 8 + rr;
      uint32_t boff = (uint32_t)((n << RBS) + ((((kcolB >> 3) ^ (n & 7))) << 4));
      uint32_t rb[4];
      ldm4(rb, bb + boff);
      mma_f16h(c[nt2 * 2],     af, rb);
      mma_f16h(c[nt2 * 2 + 1], af, rb + 2);
    }
  }
}

template<int NT>
__device__ __forceinline__ void init_bias_frag(uint32_t (*c)[2], const float* bias, int ncb, int lane) {
  #pragma unroll
  for (int nt = 0; nt < NT; nt++) {
    int cc = ncb + nt * 8 + (lane & 3) * 2;
    uint32_t hp; CVT_H2(hp, bias[cc], bias[cc + 1]);
    c[nt][0] = hp; c[nt][1] = hp;
  }
}

// tanh epilogue: warp-private rows/cols
template<int NT>
__device__ __forceinline__ void epi_tanh(uint32_t (*c)[2], uint32_t ab,
                                         int ncb, int mg, int lane) {
  int row = 16 * mg + (lane >> 2);
  #pragma unroll
  for (int nt = 0; nt < NT; nt++) {
    int col = ncb + nt * 8 + (lane & 3) * 2;
    #pragma unroll
    for (int h = 0; h < 2; h++) {
      int rh = row + 8 * h;
      uint32_t t;
      asm("tanh.approx.f16x2 %0, %1;" : "=r"(t) : "r"(c[nt][h]));
      uint32_t off = (uint32_t)((rh << 9) + ((((col >> 3) ^ (rh & 7))) << 4) + ((col & 7) << 1));
      asm volatile("st.shared.b32 [%0], %1;" :: "r"(ab + off), "r"(t) : "memory");
    }
  }
}

// ---------------- templated warp-private stage build (unrolled j-loop) ----------------
template<int ST>
__device__ __forceinline__ void build_stage(
    float tst, const float* rat, const float* wts, const float* bts,
    uint32_t ab, int R0, int mg, int ng, int lane) {
  #pragma unroll
  for (int qi = 0; qi < 16; qi++) {
    int q = lane + qi * 32;
    int r = 16 * mg + (q >> 5);
    int k2 = ng * 64 + (q & 31) * 2;
    size_t gi = (size_t)(R0 + r) * Z_D + k2;
    float2 v = *(const float2*)(g_y + gi);
    #pragma unroll
    for (int j = 0; j < ST; j++) {
      uint32_t kp = *(const uint32_t*)(&g_k[j][gi]);
      float2 kk = __half22float2(*reinterpret_cast<__half2*>(&kp));
      float cj = DT_F * cA[ST][j];
      v.x += cj * kk.x; v.y += cj * kk.y;
    }
    float tr = tst * rat[r];
    v.x += __cosf(fmaf(tr, wts[k2], bts[k2]));
    v.y += __cosf(fmaf(tr, wts[k2 + 1], bts[k2 + 1]));
    uint32_t hp; CVT_H2(hp, v.x, v.y);
    uint32_t off = (uint32_t)((r << 9) + ((((k2 >> 3) ^ (r & 7))) << 4) + ((k2 & 7) << 1));
    asm volatile("st.shared.b32 [%0], %1;" :: "r"(ab + off), "r"(hp) : "memory");
  }
}

extern __shared__ char smem_raw[];

// pipelined weight block: full-wait, MMA, per-warp empty-arrive; warp0 waits empty + reissues.
#define DO_BLOCK(NT_, NKS_, RBS_, KBASE_, NCB_, CARR_) do { \
  uint32_t bb_ = (blk & 1) ? wb1 : wb0; \
  if (blk & 1) { MBAR_WAIT(mb1, ph1); ph1 ^= 1; } \
  else         { MBAR_WAIT(mb0, ph0); ph0 ^= 1; } \
  mma_span<NT_, NKS_, RBS_>(ab, bb_, KBASE_, NCB_, mg, lane, CARR_); \
  if (lane == 0) MBAR_ARRIVE((blk & 1) ? me1 : me0); \
  if (w == 0 && blk + 2 < 384) { \
    if (blk & 1) { MBAR_WAIT(me1, qe1); qe1 ^= 1; } \
    else         { MBAR_WAIT(me0, qe0); qe0 ^= 1; } \
    if (lane == 0) { \
      uint32_t mbf_ = (blk & 1) ? mb1 : mb0; \
      MBAR_EXPECT(mbf_, 32768); \
      BULK_LOAD(bb_, (const void*)(g_wh + (((blk + 2) & 7) * 16384)), 32768, mbf_); \
    } \
  } \
  blk++; \
} while (0)

__global__ void __launch_bounds__(192, 2) ode_kernel(
    const float* __restrict__ z, const float* __restrict__ ts,
    const float* __restrict__ w_t, const float* __restrict__ b_t,
    const float* __restrict__ b1, const float* __restrict__ b2, const float* __restrict__ b3) {
  const uint32_t base = smem_u32(smem_raw);
  float* b1s = (float*)(smem_raw + SO_B1S);
  float* b2s = (float*)(smem_raw + SO_B2S);
  float* b3s = (float*)(smem_raw + SO_B3S);
  float* wts = (float*)(smem_raw + SO_WTS);
  float* bts = (float*)(smem_raw + SO_BTS);
  float* rat = (float*)(smem_raw + SO_RAT);
  const uint32_t ab = base + SO_A;
  const uint32_t wb0 = base + SO_B0, wb1 = base + SO_B1;
  const uint32_t mb0 = base + SO_MB, mb1 = base + SO_MB + 8;
  const uint32_t me0 = base + SO_MB + 16, me1 = base + SO_MB + 24;
  const int tid = threadIdx.x;
  const int lane = tid & 31, w = tid >> 5;
  const int mg = w >> 1, ng = w & 1;   // mg 0..2 (16 rows), ng 0..1 (col half)
  const int R0 = blockIdx.x * 48;

  if (tid < 48) rat[tid] = ts[R0 + tid];
  if (tid < 128) {
    wts[tid] = w_t[tid];
    bts[tid] = b_t[tid];
    b3s[tid] = b3[tid];
  }
  for (int i = tid; i < 256; i += 192) { b1s[i] = b1[i]; b2s[i] = b2[i]; }
  if (tid == 0) {
    MBAR_INIT(mb0, 1); MBAR_INIT(mb1, 1);
    MBAR_INIT(me0, 6); MBAR_INIT(me1, 6);
  }
  for (int p = tid; p < 48 * 64; p += 192) {
    int r = p >> 6, k2 = (p & 63) * 2;
    float2 zz = *(const float2*)(z + ((R0 + r) & 63) * Z_D + k2);
    *(float2*)(g_y + (size_t)(R0 + r) * Z_D + k2) = zz;
  }
  __syncthreads();
  if (tid == 0) {                        // bootstrap: blocks 0,1
    MBAR_EXPECT(mb0, 32768);
    BULK_LOAD(wb0, (const void*)(g_wh + 0), 32768, mb0);
    MBAR_EXPECT(mb1, 32768);
    BULK_LOAD(wb1, (const void*)(g_wh + 16384), 32768, mb1);
  }

  int blk = 0, ph0 = 0, ph1 = 0, qe0 = 0, qe1 = 0;
  for (int step = 0; step < N_STEPS; step++) {
    float s0 = step * DT_F;
    for (int st = 0; st < 6; st++) {
      float tst = s0 + cC[st] * DT_F;
      switch (st) {
        case 0: build_stage<0>(tst, rat, wts, bts, ab, R0, mg, ng, lane); break;
        case 1: build_stage<1>(tst, rat, wts, bts, ab, R0, mg, ng, lane); break;
        case 2: build_stage<2>(tst, rat, wts, bts, ab, R0, mg, ng, lane); break;
        case 3: build_stage<3>(tst, rat, wts, bts, ab, R0, mg, ng, lane); break;
        case 4: build_stage<4>(tst, rat, wts, bts, ab, R0, mg, ng, lane); break;
        default: build_stage<5>(tst, rat, wts, bts, ab, R0, mg, ng, lane); break;
      }
      PAIR_BAR(mg);                      // A cols 0..127 visible within pair
      {   // layer 1: K=128 (blocks 0,1) -> N=256, tanh
        uint32_t c[16][2];
        init_bias_frag<16>(c, b1s, ng * 128, lane);
        DO_BLOCK(16, 4, 7, 0,  ng * 128, c);
        DO_BLOCK(16, 4, 7, 64, ng * 128, c);
        PAIR_BAR(mg);                    // partner's layer1 A reads done
        epi_tanh<16>(c, ab, ng * 128, mg, lane);
      }
      PAIR_BAR(mg);                      // epi1 visible
      {   // layer 2: K=256 (blocks 2..5) -> N=256, tanh
        uint32_t c[16][2];
        init_bias_frag<16>(c, b2s, ng * 128, lane);
        DO_BLOCK(16, 4, 7, 0,   ng * 128, c);
        DO_BLOCK(16, 4, 7, 64,  ng * 128, c);
        DO_BLOCK(16, 4, 7, 128, ng * 128, c);
        DO_BLOCK(16, 4, 7, 192, ng * 128, c);
        PAIR_BAR(mg);                    // partner's layer2 A reads done
        epi_tanh<16>(c, ab, ng * 128, mg, lane);
      }
      PAIR_BAR(mg);                      // epi2 visible
      {   // layer 3: K=256 (blocks 6,7) -> N=128, * ratio -> g_k[st] (fp16, own cells)
        uint32_t c[8][2];
        init_bias_frag<8>(c, b3s, ng * 64, lane);
        DO_BLOCK(8, 8, 8, 0,   ng * 64, c);
        DO_BLOCK(8, 8, 8, 128, ng * 64, c);
        int row = 16 * mg + (lane >> 2);
        #pragma unroll
        for (int nt = 0; nt < 8; nt++) {
          int col = ng * 64 + nt * 8 + (lane & 3) * 2;
          #pragma unroll
          for (int h = 0; h < 2; h++) {
            int rr = row + 8 * h;
            float sc = rat[rr];
            uint32_t scp; CVT_H2(scp, sc, sc);
            __half2 prod = __hmul2(*reinterpret_cast<__half2*>(&c[nt][h]),
                                   *reinterpret_cast<__half2*>(&scp));
            *(uint32_t*)(&g_k[st][(size_t)(R0 + rr) * Z_D + col]) =
                *reinterpret_cast<uint32_t*>(&prod);
          }
        }
      }
      PAIR_BAR(mg);                      // partner's layer3 A reads done (A rewritten next build)
    }
    // ---- y += dt * sum bw_j k_j (warp-private cells) ----
    for (int q = lane; q < 16 * 32; q += 32) {
      int r = 16 * mg + (q >> 5);
      int k2 = ng * 64 + (q & 31) * 2;
      size_t gi = (size_t)(R0 + r) * Z_D + k2;
      float2 y = *(float2*)(g_y + gi);
      const float cw[6] = {35.f/384.f, 0.f, 500.f/1113.f, 125.f/192.f,
                           -2187.f/6784.f, 11.f/84.f};
      #pragma unroll
      for (int j = 0; j < 6; j++) {
        if (j == 1) continue;
        uint32_t kp = *(const uint32_t*)(&g_k[j][gi]);
        float2 kk = __half22float2(*reinterpret_cast<__half2*>(&kp));
        y.x += DT_F * cw[j] * kk.x;
        y.y += DT_F * cw[j] * kk.y;
      }
      *(float2*)(g_y + gi) = y;
    }
  }
}

// ---------------- decode_fc: 64 rows/block, fp16 weights ----------------
__global__ void __launch_bounds__(256) dec_kernel(
    const float* __restrict__ x, const float* __restrict__ bd) {
  __shared__ float xs[172];
  __shared__ float ys[64 * 128];
  const int tid = threadIdx.x;
  const int b = blockIdx.x, R0 = b * 64;
  for (int i = tid; i < 172; i += 256) xs[i] = x[(size_t)b * 172 + i];
  for (int i = tid; i < 64 * 128; i += 256) ys[i] = g_y[(size_t)R0 * 128 + i];
  __syncthreads();
  float acc0 = bd[tid];
  #pragma unroll 4
  for (int k = 0; k < 172; k++)
    acc0 = fmaf(xs[k], __half2float(g_wdh[(size_t)k * 256 + tid]), acc0);
  float acc[64];
  #pragma unroll
  for (int r = 0; r < 64; r++) acc[r] = acc0;
  #pragma unroll 1
  for (int k = 0; k < 128; k += 4) {
    float w0 = __half2float(g_wdh[(size_t)(172 + k) * 256 + tid]);
    float w1 = __half2float(g_wdh[(size_t)(173 + k) * 256 + tid]);
    float w2 = __half2float(g_wdh[(size_t)(174 + k) * 256 + tid]);
    float w3 = __half2float(g_wdh[(size_t)(175 + k) * 256 + tid]);
    #pragma unroll
    for (int r = 0; r < 64; r++) {
      float4 h4 = *(const float4*)(&ys[r * 128 + k]);
      acc[r] = fmaf(h4.x, w0, acc[r]);
      acc[r] = fmaf(h4.y, w1, acc[r]);
      acc[r] = fmaf(h4.z, w2, acc[r]);
      acc[r] = fmaf(h4.w, w3, acc[r]);
    }
  }
  #pragma unroll
  for (int r = 0; r < 64; r++) g_h[(size_t)(R0 + r) * 256 + tid] = acc[r];
}

// ---------------- src/dst fc: 32 rows/block, fp16 weights ----------------
__global__ void __launch_bounds__(256) sd_kernel(
    const float* __restrict__ bs, const float* __restrict__ bdst) {
  __shared__ float hs[32 * 256];
  const int tid = threadIdx.x;
  const int R0 = blockIdx.x * 32;
  const __half* W = (R0 < 4096) ? g_wsh : g_wdsth;
  const float* bb = (R0 < 4096) ? bs : bdst;
  for (int i = tid; i < 32 * 256; i += 256) hs[i] = g_h[(size_t)R0 * 256 + i];
  __syncthreads();
  float acc[32];
  float b0 = bb[tid];
  #pragma unroll
  for (int r = 0; r < 32; r++) acc[r] = b0;
  #pragma unroll 1
  for (int k = 0; k < 256; k += 4) {
    float w0 = __half2float(W[(size_t)(k + 0) * 256 + tid]);
    float w1 = __half2float(W[(size_t)(k + 1) * 256 + tid]);
    float w2 = __half2float(W[(size_t)(k + 2) * 256 + tid]);
    float w3 = __half2float(W[(size_t)(k + 3) * 256 + tid]);
    #pragma unroll
    for (int r = 0; r < 32; r++) {
      float4 h4 = *(const float4*)(&hs[r * 256 + k]);
      acc[r] = fmaf(h4.x, w0, acc[r]);
      acc[r] = fmaf(h4.y, w1, acc[r]);
      acc[r] = fmaf(h4.z, w2, acc[r]);
      acc[r] = fmaf(h4.w, w3, acc[r]);
    }
  }
  #pragma unroll
  for (int r = 0; r < 32; r++) g_s[(size_t)(R0 + r) * 256 + tid] = acc[r];
}

// ---------------- edge out + mean over L ----------------
__global__ void __launch_bounds__(256) edge_kernel(
    const float* __restrict__ Wo, const float* __restrict__ bo, float* __restrict__ out) {
  __shared__ float red[8];
  const int tid = threadIdx.x;
  const int o = blockIdx.x;
  const int b = (o < 64) ? o : (o - 64);
  const size_t off2 = (o < 64) ? (size_t)4096 * H_D : (size_t)8192 * H_D;
  const float wcol = Wo[tid];
  float sum = 0.f;
  for (int l = 0; l < 64; l++) {
    size_t r1 = (size_t)(b * 64 + l) * H_D + tid;
    float v = g_s[r1] + g_s[off2 + r1];
    sum += fmaxf(v, 0.f) * wcol;
  }
  #pragma unroll
  for (int d = 16; d > 0; d >>= 1) sum += __shfl_xor_sync(0xFFFFFFFFu, sum, d);
  if ((tid & 31) == 0) red[tid >> 5] = sum;
  __syncthreads();
  if (tid == 0) {
    float t = 0.f;
    #pragma unroll
    for (int w = 0; w < 8; w++) t += red[w];
    out[o] = t * (1.f / 64.f) + bo[0];
  }
}

extern "C" void kernel_launch(void* const* d_in, const int* in_sizes, int n_in,
                              void* d_out, int out_size) {
  const float* x    = (const float*)d_in[0];
  const float* z    = (const float*)d_in[1];
  const float* ts   = (const float*)d_in[2];
  const float* w_t  = (const float*)d_in[3];
  const float* b_t  = (const float*)d_in[4];
  const float* W1   = (const float*)d_in[5];
  const float* b1   = (const float*)d_in[6];
  const float* W2   = (const float*)d_in[7];
  const float* b2   = (const float*)d_in[8];
  const float* W3   = (const float*)d_in[9];
  const float* b3   = (const float*)d_in[10];
  const float* Wd   = (const float*)d_in[11];
  const float* bd   = (const float*)d_in[12];
  const float* Ws   = (const float*)d_in[13];
  const float* bs   = (const float*)d_in[14];
  const float* Wdst = (const float*)d_in[15];
  const float* bdst = (const float*)d_in[16];
  const float* Wo   = (const float*)d_in[17];
  const float* bo   = (const float*)d_in[18];
  float* out = (float*)d_out;

  cudaFuncSetAttribute(ode_kernel, cudaFuncAttributeMaxDynamicSharedMemorySize, SM_ODE);

  prep_kernel<<<512, 256>>>(W1, W2, W3);
  prep2_kernel<<<812, 256>>>(Wd, Ws, Wdst);
  ode_kernel<<<256, 192, SM_ODE>>>(z, ts, w_t, b_t, b1, b2, b3);
  dec_kernel<<<192, 256>>>(x, bd);
  sd_kernel<<<384, 256>>>(bs, bdst);
  edge_kernel<<<128, 256>>>(Wo, bo, out);
}

// round 15
// speedup vs baseline: 7.3540x; 1.0178x over previous
#include <cuda_runtime.h>
#include <cuda_fp16.h>
#include <cstdint>

#define N_ROWS 12288
#define Z_D 128
#define H_D 256
#define N_STEPS 8
#define DT_F 0.125f

__device__ __half g_k[6][N_ROWS * Z_D];
__device__ float g_y[N_ROWS * Z_D];
__device__ float g_s[N_ROWS * H_D];
// 8 sequential 32KB blocks (16384 halves each):
// B0=W1[k0:64] B1=W1[k64:128] B2..B5=W2[k*64 quarters] B6=W3[k0:128] B7=W3[k128:256]
__device__ __half g_wh[131072];
// fp16 decode weights
__device__ __half g_wdh[76800];    // Wd [300][256]
__device__ __half g_wsh[65536];    // Ws [256][256]
__device__ __half g_wdsth[65536];  // Wdst [256][256]

__constant__ float cA[6][5] = {
  {0.f,0.f,0.f,0.f,0.f},
  {0.2f,0.f,0.f,0.f,0.f},
  {3.f/40.f,9.f/40.f,0.f,0.f,0.f},
  {44.f/45.f,-56.f/15.f,32.f/9.f,0.f,0.f},
  {19372.f/6561.f,-25360.f/2187.f,64448.f/6561.f,-212.f/729.f,0.f},
  {9017.f/3168.f,-355.f/33.f,46732.f/5247.f,49.f/176.f,-5103.f/18656.f}
};
__constant__ float cC[6] = {0.f,0.2f,0.3f,0.8f,8.f/9.f,1.f};

// ---------------- helpers ----------------
__device__ __forceinline__ uint32_t smem_u32(const void* p) {
  uint32_t a;
  asm("{ .reg .u64 t; cvta.to.shared.u64 t, %1; cvt.u32.u64 %0, t; }" : "=r"(a) : "l"(p));
  return a;
}
#define CVT_H2(res, lo, hi) \
  asm("cvt.rn.f16x2.f32 %0, %1, %2;" : "=r"(res) : "f"(hi), "f"(lo))

__device__ __forceinline__ void mma_f16h(uint32_t* c, const uint32_t* a, const uint32_t* b) {
  asm volatile(
    "mma.sync.aligned.m16n8k16.row.col.f16.f16.f16.f16 "
    "{%0,%1}, {%2,%3,%4,%5}, {%6,%7}, {%0,%1};"
    : "+r"(c[0]), "+r"(c[1])
    : "r"(a[0]), "r"(a[1]), "r"(a[2]), "r"(a[3]), "r"(b[0]), "r"(b[1]));
}
__device__ __forceinline__ void ldm4(uint32_t* r, uint32_t addr) {
  asm volatile("ldmatrix.sync.aligned.m8n8.x4.shared.b16 {%0,%1,%2,%3}, [%4];"
    : "=r"(r[0]), "=r"(r[1]), "=r"(r[2]), "=r"(r[3]) : "r"(addr));
}

#define MBAR_INIT(mbar, cnt) \
  asm volatile("mbarrier.init.shared.b64 [%0], %1;" :: "r"(mbar), "r"(cnt) : "memory")
#define MBAR_EXPECT(mbar, bytes) \
  asm volatile("mbarrier.arrive.expect_tx.shared.b64 _, [%0], %1;" :: "r"(mbar), "r"(bytes) : "memory")
#define MBAR_ARRIVE(mbar) \
  asm volatile("mbarrier.arrive.shared.b64 _, [%0];" :: "r"(mbar) : "memory")
#define MBAR_WAIT(mbar, par) do { \
  uint32_t _m = (mbar), _p = (par), _d; \
  asm volatile("{\n\t.reg .pred p;\n\tmbarrier.try_wait.parity.acquire.cta.shared::cta.b64 p, [%1], %2;\n\tselp.b32 %0, 1, 0, p;\n\t}" \
    : "=r"(_d) : "r"(_m), "r"(_p) : "memory"); \
  if (!_d) { \
    asm volatile("{\n\t.reg .pred P1;\n\tWL_%=:\n\tmbarrier.try_wait.parity.acquire.cta.shared::cta.b64 P1, [%0], %1, 0x989680;\n\t@P1 bra.uni WD_%=;\n\tbra.uni WL_%=;\n\tWD_%=:\n\t}" \
      :: "r"(_m), "r"(_p) : "memory"); \
  } \
} while (0)
#define BULK_LOAD(dst, src, bytes, mbar) \
  asm volatile("cp.async.bulk.shared::cluster.global.mbarrier::complete_tx::bytes [%0], [%1], %2, [%3];" \
    :: "r"(dst), "l"(src), "r"(bytes), "r"(mbar) : "memory")
#define PAIR_BAR(mgid) \
  asm volatile("bar.sync %0, 64;" :: "r"(1 + (mgid)) : "memory")

// ---- smem layout (bytes), per 48-row CTA ----
#define SO_A    0
#define SO_B0   24576
#define SO_B1   57344
#define SO_B1S  90112
#define SO_B2S  91136
#define SO_B3S  92160
#define SO_WTS  92672
#define SO_BTS  93184
#define SO_RAT  93696
#define SO_MB   93952
#define SM_ODE  94208

// ---------------- weight prep: fp32 -> fp16, 32KB-block layout + XOR-granule swizzle ----------------
__global__ void prep_kernel(const float* __restrict__ W1, const float* __restrict__ W2,
                            const float* __restrict__ W3) {
  int i = blockIdx.x * 256 + threadIdx.x;
  if (i < 32768) {                       // W1 [N=256][K=128] -> blocks 0,1 (row 64 halves)
    int n = i >> 7, k = i & 127;
    int blk = k >> 6, kl = k & 63;
    int dst = blk * 16384 + n * 64 + (((kl >> 3) ^ (n & 7)) << 3) + (kl & 7);
    g_wh[dst] = __float2half_rn(W1[k * 256 + n]);
  } else if (i < 98304) {                // W2 [N=256][K=256] -> blocks 2..5
    int e = i - 32768; int n = e >> 8, k = e & 255;
    int blk = 2 + (k >> 6), kl = k & 63;
    int dst = blk * 16384 + n * 64 + (((kl >> 3) ^ (n & 7)) << 3) + (kl & 7);
    g_wh[dst] = __float2half_rn(W2[k * 256 + n]);
  } else {                               // W3 [N=128][K=256] -> blocks 6,7 (row 128 halves)
    int e = i - 98304; int n = e >> 8, k = e & 255;
    int blk = 6 + (k >> 7), kl = k & 127;
    int dst = blk * 16384 + n * 128 + (((kl >> 3) ^ (n & 7)) << 3) + (kl & 7);
    g_wh[dst] = __float2half_rn(W3[k * 128 + n]);
  }
}

// ---------------- decode weight prep: fp32 -> fp16 straight copy ----------------
__global__ void prep2_kernel(const float* __restrict__ Wd, const float* __restrict__ Ws,
                             const float* __restrict__ Wdst) {
  int i = blockIdx.x * 256 + threadIdx.x;
  if (i < 76800)        g_wdh[i] = __float2half_rn(Wd[i]);
  else if (i < 142336)  g_wsh[i - 76800] = __float2half_rn(Ws[i - 76800]);
  else if (i < 207872)  g_wdsth[i - 142336] = __float2half_rn(Wdst[i - 142336]);
}

// ---------------- MMA span over a resident 32KB B block ----------------
template<int NT, int NKS, int RBS>
__device__ __forceinline__ void mma_span(
    uint32_t ab, uint32_t bb, int kbaseA,
    int ncb, int mg, int lane, uint32_t (*c)[2]) {
  int m = lane >> 3;
  int row = 16 * mg + (m & 1) * 8 + (lane & 7);
  int g = lane >> 3, rr = lane & 7;
  #pragma unroll
  for (int ks = 0; ks < NKS; ks++) {
    int kcolA = kbaseA + ks * 16 + (m >> 1) * 8;
    uint32_t aoff = (uint32_t)((row << 9) + ((((kcolA >> 3) ^ (row & 7))) << 4));
    uint32_t af[4];
    ldm4(af, ab + aoff);
    int kcolB = ks * 16 + (g & 1) * 8;
    #pragma unroll
    for (int nt2 = 0; nt2 < NT / 2; nt2++) {
      int n = ncb + nt2 * 16 + (g >> 1) * 8 + rr;
      uint32_t boff = (uint32_t)((n << RBS) + ((((kcolB >> 3) ^ (n & 7))) << 4));
      uint32_t rb[4];
      ldm4(rb, bb + boff);
      mma_f16h(c[nt2 * 2],     af, rb);
      mma_f16h(c[nt2 * 2 + 1], af, rb + 2);
    }
  }
}

template<int NT>
__device__ __forceinline__ void init_bias_frag(uint32_t (*c)[2], const float* bias, int ncb, int lane) {
  #pragma unroll
  for (int nt = 0; nt < NT; nt++) {
    int cc = ncb + nt * 8 + (lane & 3) * 2;
    uint32_t hp; CVT_H2(hp, bias[cc], bias[cc + 1]);
    c[nt][0] = hp; c[nt][1] = hp;
  }
}

// tanh epilogue: warp-private rows/cols
template<int NT>
__device__ __forceinline__ void epi_tanh(uint32_t (*c)[2], uint32_t ab,
                                         int ncb, int mg, int lane) {
  int row = 16 * mg + (lane >> 2);
  #pragma unroll
  for (int nt = 0; nt < NT; nt++) {
    int col = ncb + nt * 8 + (lane & 3) * 2;
    #pragma unroll
    for (int h = 0; h < 2; h++) {
      int rh = row + 8 * h;
      uint32_t t;
      asm("tanh.approx.f16x2 %0, %1;" : "=r"(t) : "r"(c[nt][h]));
      uint32_t off = (uint32_t)((rh << 9) + ((((col >> 3) ^ (rh & 7))) << 4) + ((col & 7) << 1));
      asm volatile("st.shared.b32 [%0], %1;" :: "r"(ab + off), "r"(t) : "memory");
    }
  }
}

// ---------------- templated warp-private stage build (unrolled j-loop) ----------------
template<int ST>
__device__ __forceinline__ void build_stage(
    float tst, const float* rat, const float* wts, const float* bts,
    uint32_t ab, int R0, int mg, int ng, int lane) {
  #pragma unroll
  for (int qi = 0; qi < 16; qi++) {
    int q = lane + qi * 32;
    int r = 16 * mg + (q >> 5);
    int k2 = ng * 64 + (q & 31) * 2;
    size_t gi = (size_t)(R0 + r) * Z_D + k2;
    float2 v = *(const float2*)(g_y + gi);
    #pragma unroll
    for (int j = 0; j < ST; j++) {
      uint32_t kp = *(const uint32_t*)(&g_k[j][gi]);
      float2 kk = __half22float2(*reinterpret_cast<__half2*>(&kp));
      float cj = DT_F * cA[ST][j];
      v.x += cj * kk.x; v.y += cj * kk.y;
    }
    float tr = tst * rat[r];
    v.x += __cosf(fmaf(tr, wts[k2], bts[k2]));
    v.y += __cosf(fmaf(tr, wts[k2 + 1], bts[k2 + 1]));
    uint32_t hp; CVT_H2(hp, v.x, v.y);
    uint32_t off = (uint32_t)((r << 9) + ((((k2 >> 3) ^ (r & 7))) << 4) + ((k2 & 7) << 1));
    asm volatile("st.shared.b32 [%0], %1;" :: "r"(ab + off), "r"(hp) : "memory");
  }
}

extern __shared__ char smem_raw[];

// pipelined weight block: full-wait, MMA, per-warp empty-arrive; warp0 waits empty + reissues.
#define DO_BLOCK(NT_, NKS_, RBS_, KBASE_, NCB_, CARR_) do { \
  uint32_t bb_ = (blk & 1) ? wb1 : wb0; \
  if (blk & 1) { MBAR_WAIT(mb1, ph1); ph1 ^= 1; } \
  else         { MBAR_WAIT(mb0, ph0); ph0 ^= 1; } \
  mma_span<NT_, NKS_, RBS_>(ab, bb_, KBASE_, NCB_, mg, lane, CARR_); \
  if (lane == 0) MBAR_ARRIVE((blk & 1) ? me1 : me0); \
  if (w == 0 && blk + 2 < 384) { \
    if (blk & 1) { MBAR_WAIT(me1, qe1); qe1 ^= 1; } \
    else         { MBAR_WAIT(me0, qe0); qe0 ^= 1; } \
    if (lane == 0) { \
      uint32_t mbf_ = (blk & 1) ? mb1 : mb0; \
      MBAR_EXPECT(mbf_, 32768); \
      BULK_LOAD(bb_, (const void*)(g_wh + (((blk + 2) & 7) * 16384)), 32768, mbf_); \
    } \
  } \
  blk++; \
} while (0)

__global__ void __launch_bounds__(192, 2) ode_kernel(
    const float* __restrict__ z, const float* __restrict__ ts,
    const float* __restrict__ w_t, const float* __restrict__ b_t,
    const float* __restrict__ b1, const float* __restrict__ b2, const float* __restrict__ b3) {
  const uint32_t base = smem_u32(smem_raw);
  float* b1s = (float*)(smem_raw + SO_B1S);
  float* b2s = (float*)(smem_raw + SO_B2S);
  float* b3s = (float*)(smem_raw + SO_B3S);
  float* wts = (float*)(smem_raw + SO_WTS);
  float* bts = (float*)(smem_raw + SO_BTS);
  float* rat = (float*)(smem_raw + SO_RAT);
  const uint32_t ab = base + SO_A;
  const uint32_t wb0 = base + SO_B0, wb1 = base + SO_B1;
  const uint32_t mb0 = base + SO_MB, mb1 = base + SO_MB + 8;
  const uint32_t me0 = base + SO_MB + 16, me1 = base + SO_MB + 24;
  const int tid = threadIdx.x;
  const int lane = tid & 31, w = tid >> 5;
  const int mg = w >> 1, ng = w & 1;   // mg 0..2 (16 rows), ng 0..1 (col half)
  const int R0 = blockIdx.x * 48;

  if (tid < 48) rat[tid] = ts[R0 + tid];
  if (tid < 128) {
    wts[tid] = w_t[tid];
    bts[tid] = b_t[tid];
    b3s[tid] = b3[tid];
  }
  for (int i = tid; i < 256; i += 192) { b1s[i] = b1[i]; b2s[i] = b2[i]; }
  if (tid == 0) {
    MBAR_INIT(mb0, 1); MBAR_INIT(mb1, 1);
    MBAR_INIT(me0, 6); MBAR_INIT(me1, 6);
  }
  for (int p = tid; p < 48 * 64; p += 192) {
    int r = p >> 6, k2 = (p & 63) * 2;
    float2 zz = *(const float2*)(z + ((R0 + r) & 63) * Z_D + k2);
    *(float2*)(g_y + (size_t)(R0 + r) * Z_D + k2) = zz;
  }
  __syncthreads();
  if (tid == 0) {                        // bootstrap: blocks 0,1
    MBAR_EXPECT(mb0, 32768);
    BULK_LOAD(wb0, (const void*)(g_wh + 0), 32768, mb0);
    MBAR_EXPECT(mb1, 32768);
    BULK_LOAD(wb1, (const void*)(g_wh + 16384), 32768, mb1);
  }

  int blk = 0, ph0 = 0, ph1 = 0, qe0 = 0, qe1 = 0;
  for (int step = 0; step < N_STEPS; step++) {
    float s0 = step * DT_F;
    for (int st = 0; st < 6; st++) {
      float tst = s0 + cC[st] * DT_F;
      switch (st) {
        case 0: build_stage<0>(tst, rat, wts, bts, ab, R0, mg, ng, lane); break;
        case 1: build_stage<1>(tst, rat, wts, bts, ab, R0, mg, ng, lane); break;
        case 2: build_stage<2>(tst, rat, wts, bts, ab, R0, mg, ng, lane); break;
        case 3: build_stage<3>(tst, rat, wts, bts, ab, R0, mg, ng, lane); break;
        case 4: build_stage<4>(tst, rat, wts, bts, ab, R0, mg, ng, lane); break;
        default: build_stage<5>(tst, rat, wts, bts, ab, R0, mg, ng, lane); break;
      }
      PAIR_BAR(mg);                      // A cols 0..127 visible within pair
      {   // layer 1: K=128 (blocks 0,1) -> N=256, tanh
        uint32_t c[16][2];
        init_bias_frag<16>(c, b1s, ng * 128, lane);
        DO_BLOCK(16, 4, 7, 0,  ng * 128, c);
        DO_BLOCK(16, 4, 7, 64, ng * 128, c);
        PAIR_BAR(mg);                    // partner's layer1 A reads done
        epi_tanh<16>(c, ab, ng * 128, mg, lane);
      }
      PAIR_BAR(mg);                      // epi1 visible
      {   // layer 2: K=256 (blocks 2..5) -> N=256, tanh
        uint32_t c[16][2];
        init_bias_frag<16>(c, b2s, ng * 128, lane);
        DO_BLOCK(16, 4, 7, 0,   ng * 128, c);
        DO_BLOCK(16, 4, 7, 64,  ng * 128, c);
        DO_BLOCK(16, 4, 7, 128, ng * 128, c);
        DO_BLOCK(16, 4, 7, 192, ng * 128, c);
        PAIR_BAR(mg);                    // partner's layer2 A reads done
        epi_tanh<16>(c, ab, ng * 128, mg, lane);
      }
      PAIR_BAR(mg);                      // epi2 visible
      {   // layer 3: K=256 (blocks 6,7) -> N=128, * ratio -> g_k[st] (fp16, own cells)
        uint32_t c[8][2];
        init_bias_frag<8>(c, b3s, ng * 64, lane);
        DO_BLOCK(8, 8, 8, 0,   ng * 64, c);
        DO_BLOCK(8, 8, 8, 128, ng * 64, c);
        int row = 16 * mg + (lane >> 2);
        #pragma unroll
        for (int nt = 0; nt < 8; nt++) {
          int col = ng * 64 + nt * 8 + (lane & 3) * 2;
          #pragma unroll
          for (int h = 0; h < 2; h++) {
            int rr = row + 8 * h;
            float sc = rat[rr];
            uint32_t scp; CVT_H2(scp, sc, sc);
            __half2 prod = __hmul2(*reinterpret_cast<__half2*>(&c[nt][h]),
                                   *reinterpret_cast<__half2*>(&scp));
            *(uint32_t*)(&g_k[st][(size_t)(R0 + rr) * Z_D + col]) =
                *reinterpret_cast<uint32_t*>(&prod);
          }
        }
      }
      PAIR_BAR(mg);                      // partner's layer3 A reads done (A rewritten next build)
    }
    // ---- y += dt * sum bw_j k_j (warp-private cells) ----
    for (int q = lane; q < 16 * 32; q += 32) {
      int r = 16 * mg + (q >> 5);
      int k2 = ng * 64 + (q & 31) * 2;
      size_t gi = (size_t)(R0 + r) * Z_D + k2;
      float2 y = *(float2*)(g_y + gi);
      const float cw[6] = {35.f/384.f, 0.f, 500.f/1113.f, 125.f/192.f,
                           -2187.f/6784.f, 11.f/84.f};
      #pragma unroll
      for (int j = 0; j < 6; j++) {
        if (j == 1) continue;
        uint32_t kp = *(const uint32_t*)(&g_k[j][gi]);
        float2 kk = __half22float2(*reinterpret_cast<__half2*>(&kp));
        y.x += DT_F * cw[j] * kk.x;
        y.y += DT_F * cw[j] * kk.y;
      }
      *(float2*)(g_y + gi) = y;
    }
  }
}

// ---------------- fused decode: h = [x|y]@Wd+bd ; s = h@W{s,dst}+b ----------------
// 32 rows/block; smem buffer reused: phase1 ys[32][128]+xs[172], phase2 hs[32][256].
__global__ void __launch_bounds__(256) ds_kernel(
    const float* __restrict__ x, const float* __restrict__ bd,
    const float* __restrict__ bs, const float* __restrict__ bdst) {
  __shared__ float buf[32 * 256];   // 32 KB
  float* ys = buf;                  // [32][128]
  float* xs = buf + 32 * 128;       // [172]
  const int tid = threadIdx.x;
  const int R0 = blockIdx.x * 32;
  const int b = R0 >> 6;

  for (int i = tid; i < 172; i += 256) xs[i] = x[(size_t)b * 172 + i];
  for (int i = tid; i < 32 * 128; i += 256) ys[i] = g_y[(size_t)R0 * 128 + i];
  __syncthreads();

  // phase 1: h
  float acc0 = bd[tid];
  #pragma unroll 4
  for (int k = 0; k < 172; k++)
    acc0 = fmaf(xs[k], __half2float(g_wdh[(size_t)k * 256 + tid]), acc0);
  float acc[32];
  #pragma unroll
  for (int r = 0; r < 32; r++) acc[r] = acc0;
  #pragma unroll 1
  for (int k = 0; k < 128; k += 4) {
    float w0 = __half2float(g_wdh[(size_t)(172 + k) * 256 + tid]);
    float w1 = __half2float(g_wdh[(size_t)(173 + k) * 256 + tid]);
    float w2 = __half2float(g_wdh[(size_t)(174 + k) * 256 + tid]);
    float w3 = __half2float(g_wdh[(size_t)(175 + k) * 256 + tid]);
    #pragma unroll
    for (int r = 0; r < 32; r++) {
      float4 h4 = *(const float4*)(&ys[r * 128 + k]);
      acc[r] = fmaf(h4.x, w0, acc[r]);
      acc[r] = fmaf(h4.y, w1, acc[r]);
      acc[r] = fmaf(h4.z, w2, acc[r]);
      acc[r] = fmaf(h4.w, w3, acc[r]);
    }
  }
  __syncthreads();                  // all ys/xs reads done
  #pragma unroll
  for (int r = 0; r < 32; r++) buf[r * 256 + tid] = acc[r];   // hs[32][256]
  __syncthreads();

  // phase 2: s
  const __half* W = (R0 < 4096) ? g_wsh : g_wdsth;
  const float* bb = (R0 < 4096) ? bs : bdst;
  float b0 = bb[tid];
  float acc2[32];
  #pragma unroll
  for (int r = 0; r < 32; r++) acc2[r] = b0;
  #pragma unroll 1
  for (int k = 0; k < 256; k += 4) {
    float w0 = __half2float(W[(size_t)(k + 0) * 256 + tid]);
    float w1 = __half2float(W[(size_t)(k + 1) * 256 + tid]);
    float w2 = __half2float(W[(size_t)(k + 2) * 256 + tid]);
    float w3 = __half2float(W[(size_t)(k + 3) * 256 + tid]);
    #pragma unroll
    for (int r = 0; r < 32; r++) {
      float4 h4 = *(const float4*)(&buf[r * 256 + k]);
      acc2[r] = fmaf(h4.x, w0, acc2[r]);
      acc2[r] = fmaf(h4.y, w1, acc2[r]);
      acc2[r] = fmaf(h4.z, w2, acc2[r]);
      acc2[r] = fmaf(h4.w, w3, acc2[r]);
    }
  }
  #pragma unroll
  for (int r = 0; r < 32; r++) g_s[(size_t)(R0 + r) * 256 + tid] = acc2[r];
}

// ---------------- edge out + mean over L ----------------
__global__ void __launch_bounds__(256) edge_kernel(
    const float* __restrict__ Wo, const float* __restrict__ bo, float* __restrict__ out) {
  __shared__ float red[8];
  const int tid = threadIdx.x;
  const int o = blockIdx.x;
  const int b = (o < 64) ? o : (o - 64);
  const size_t off2 = (o < 64) ? (size_t)4096 * H_D : (size_t)8192 * H_D;
  const float wcol = Wo[tid];
  float sum = 0.f;
  for (int l = 0; l < 64; l++) {
    size_t r1 = (size_t)(b * 64 + l) * H_D + tid;
    float v = g_s[r1] + g_s[off2 + r1];
    sum += fmaxf(v, 0.f) * wcol;
  }
  #pragma unroll
  for (int d = 16; d > 0; d >>= 1) sum += __shfl_xor_sync(0xFFFFFFFFu, sum, d);
  if ((tid & 31) == 0) red[tid >> 5] = sum;
  __syncthreads();
  if (tid == 0) {
    float t = 0.f;
    #pragma unroll
    for (int w = 0; w < 8; w++) t += red[w];
    out[o] = t * (1.f / 64.f) + bo[0];
  }
}

extern "C" void kernel_launch(void* const* d_in, const int* in_sizes, int n_in,
                              void* d_out, int out_size) {
  const float* x    = (const float*)d_in[0];
  const float* z    = (const float*)d_in[1];
  const float* ts   = (const float*)d_in[2];
  const float* w_t  = (const float*)d_in[3];
  const float* b_t  = (const float*)d_in[4];
  const float* W1   = (const float*)d_in[5];
  const float* b1   = (const float*)d_in[6];
  const float* W2   = (const float*)d_in[7];
  const float* b2   = (const float*)d_in[8];
  const float* W3   = (const float*)d_in[9];
  const float* b3   = (const float*)d_in[10];
  const float* Wd   = (const float*)d_in[11];
  const float* bd   = (const float*)d_in[12];
  const float* Ws   = (const float*)d_in[13];
  const float* bs   = (const float*)d_in[14];
  const float* Wdst = (const float*)d_in[15];
  const float* bdst = (const float*)d_in[16];
  const float* Wo   = (const float*)d_in[17];
  const float* bo   = (const float*)d_in[18];
  float* out = (float*)d_out;

  cudaFuncSetAttribute(ode_kernel, cudaFuncAttributeMaxDynamicSharedMemorySize, SM_ODE);

  prep_kernel<<<512, 256>>>(W1, W2, W3);
  prep2_kernel<<<812, 256>>>(Wd, Ws, Wdst);
  ode_kernel<<<256, 192, SM_ODE>>>(z, ts, w_t, b_t, b1, b2, b3);
  ds_kernel<<<384, 256>>>(x, bd, bs, bdst);
  edge_kernel<<<128, 256>>>(Wo, bo, out);
}

// round 16
// speedup vs baseline: 8.2258x; 1.1185x over previous
#include <cuda_runtime.h>
#include <cuda_fp16.h>
#include <cstdint>

#define N_ROWS 12288
#define Z_D 128
#define H_D 256
#define N_STEPS 8
#define DT_F 0.125f

__device__ __half g_k[6][N_ROWS * Z_D];
__device__ float g_y[N_ROWS * Z_D];
__device__ float g_s[N_ROWS * H_D];
// ODE weights: 8 sequential 32KB blocks (16384 halves each)
__device__ __half g_wh[131072];
// decode weights
__device__ __half g_wd1[44032];    // Wd rows 0..171, linear [k][n]
__device__ __half g_wd2[32768];    // Wd rows 172..299 -> 2 swizzled 64-K blocks
__device__ __half g_wsB[65536];    // Ws -> 4 swizzled 64-K blocks
__device__ __half g_wdstB[65536];  // Wdst -> 4 swizzled 64-K blocks

__constant__ float cA[6][5] = {
  {0.f,0.f,0.f,0.f,0.f},
  {0.2f,0.f,0.f,0.f,0.f},
  {3.f/40.f,9.f/40.f,0.f,0.f,0.f},
  {44.f/45.f,-56.f/15.f,32.f/9.f,0.f,0.f},
  {19372.f/6561.f,-25360.f/2187.f,64448.f/6561.f,-212.f/729.f,0.f},
  {9017.f/3168.f,-355.f/33.f,46732.f/5247.f,49.f/176.f,-5103.f/18656.f}
};
__constant__ float cC[6] = {0.f,0.2f,0.3f,0.8f,8.f/9.f,1.f};

// ---------------- helpers ----------------
__device__ __forceinline__ uint32_t smem_u32(const void* p) {
  uint32_t a;
  asm("{ .reg .u64 t; cvta.to.shared.u64 t, %1; cvt.u32.u64 %0, t; }" : "=r"(a) : "l"(p));
  return a;
}
#define CVT_H2(res, lo, hi) \
  asm("cvt.rn.f16x2.f32 %0, %1, %2;" : "=r"(res) : "f"(hi), "f"(lo))

__device__ __forceinline__ void mma_f16h(uint32_t* c, const uint32_t* a, const uint32_t* b) {
  asm volatile(
    "mma.sync.aligned.m16n8k16.row.col.f16.f16.f16.f16 "
    "{%0,%1}, {%2,%3,%4,%5}, {%6,%7}, {%0,%1};"
    : "+r"(c[0]), "+r"(c[1])
    : "r"(a[0]), "r"(a[1]), "r"(a[2]), "r"(a[3]), "r"(b[0]), "r"(b[1]));
}
__device__ __forceinline__ void ldm4(uint32_t* r, uint32_t addr) {
  asm volatile("ldmatrix.sync.aligned.m8n8.x4.shared.b16 {%0,%1,%2,%3}, [%4];"
    : "=r"(r[0]), "=r"(r[1]), "=r"(r[2]), "=r"(r[3]) : "r"(addr));
}

#define MBAR_INIT(mbar, cnt) \
  asm volatile("mbarrier.init.shared.b64 [%0], %1;" :: "r"(mbar), "r"(cnt) : "memory")
#define MBAR_EXPECT(mbar, bytes) \
  asm volatile("mbarrier.arrive.expect_tx.shared.b64 _, [%0], %1;" :: "r"(mbar), "r"(bytes) : "memory")
#define MBAR_ARRIVE(mbar) \
  asm volatile("mbarrier.arrive.shared.b64 _, [%0];" :: "r"(mbar) : "memory")
#define MBAR_WAIT(mbar, par) do { \
  uint32_t _m = (mbar), _p = (par), _d; \
  asm volatile("{\n\t.reg .pred p;\n\tmbarrier.try_wait.parity.acquire.cta.shared::cta.b64 p, [%1], %2;\n\tselp.b32 %0, 1, 0, p;\n\t}" \
    : "=r"(_d) : "r"(_m), "r"(_p) : "memory"); \
  if (!_d) { \
    asm volatile("{\n\t.reg .pred P1;\n\tWL_%=:\n\tmbarrier.try_wait.parity.acquire.cta.shared::cta.b64 P1, [%0], %1, 0x989680;\n\t@P1 bra.uni WD_%=;\n\tbra.uni WL_%=;\n\tWD_%=:\n\t}" \
      :: "r"(_m), "r"(_p) : "memory"); \
  } \
} while (0)
#define BULK_LOAD(dst, src, bytes, mbar) \
  asm volatile("cp.async.bulk.shared::cluster.global.mbarrier::complete_tx::bytes [%0], [%1], %2, [%3];" \
    :: "r"(dst), "l"(src), "r"(bytes), "r"(mbar) : "memory")
#define PAIR_BAR(mgid) \
  asm volatile("bar.sync %0, 64;" :: "r"(1 + (mgid)) : "memory")

// ---- ODE smem layout (bytes), per 48-row CTA ----
#define SO_A    0
#define SO_B0   24576
#define SO_B1   57344
#define SO_B1S  90112
#define SO_B2S  91136
#define SO_B3S  92160
#define SO_WTS  92672
#define SO_BTS  93184
#define SO_RAT  93696
#define SO_MB   93952
#define SM_ODE  94208

// ---- ds smem layout (bytes), per 64-row CTA ----
#define DSO_A    0
#define DSO_B0   32768
#define DSO_B1   65536
#define DSO_XACC 98304
#define DSO_XS   99328
#define DSO_BB   100096
#define DSO_MB   101120
#define SM_DS    101376

// ---------------- ODE weight prep ----------------
__global__ void prep_kernel(const float* __restrict__ W1, const float* __restrict__ W2,
                            const float* __restrict__ W3) {
  int i = blockIdx.x * 256 + threadIdx.x;
  if (i < 32768) {
    int n = i >> 7, k = i & 127;
    int blk = k >> 6, kl = k & 63;
    int dst = blk * 16384 + n * 64 + (((kl >> 3) ^ (n & 7)) << 3) + (kl & 7);
    g_wh[dst] = __float2half_rn(W1[k * 256 + n]);
  } else if (i < 98304) {
    int e = i - 32768; int n = e >> 8, k = e & 255;
    int blk = 2 + (k >> 6), kl = k & 63;
    int dst = blk * 16384 + n * 64 + (((kl >> 3) ^ (n & 7)) << 3) + (kl & 7);
    g_wh[dst] = __float2half_rn(W2[k * 256 + n]);
  } else {
    int e = i - 98304; int n = e >> 8, k = e & 255;
    int blk = 6 + (k >> 7), kl = k & 127;
    int dst = blk * 16384 + n * 128 + (((kl >> 3) ^ (n & 7)) << 3) + (kl & 7);
    g_wh[dst] = __float2half_rn(W3[k * 128 + n]);
  }
}

// ---------------- decode weight prep: linear Wd1 + swizzled 64-K blocks ----------------
__global__ void prep2_kernel(const float* __restrict__ Wd, const float* __restrict__ Ws,
                             const float* __restrict__ Wdst) {
  int i = blockIdx.x * 256 + threadIdx.x;
  if (i < 76800) {                       // Wd [300][256]
    int k = i >> 8, n = i & 255;
    float v = Wd[i];
    if (k < 172) g_wd1[i] = __float2half_rn(v);
    else {
      int kl = k - 172;
      int blk = kl >> 6, klo = kl & 63;
      g_wd2[blk * 16384 + n * 64 + (((klo >> 3) ^ (n & 7)) << 3) + (klo & 7)] = __float2half_rn(v);
    }
  } else if (i < 142336) {               // Ws [256][256]
    int e = i - 76800; int k = e >> 8, n = e & 255;
    int blk = k >> 6, klo = k & 63;
    g_wsB[blk * 16384 + n * 64 + (((klo >> 3) ^ (n & 7)) << 3) + (klo & 7)] = __float2half_rn(Ws[e]);
  } else if (i < 207872) {               // Wdst [256][256]
    int e = i - 142336; int k = e >> 8, n = e & 255;
    int blk = k >> 6, klo = k & 63;
    g_wdstB[blk * 16384 + n * 64 + (((klo >> 3) ^ (n & 7)) << 3) + (klo & 7)] = __float2half_rn(Wdst[e]);
  }
}

// ---------------- MMA span over a resident 32KB B block ----------------
template<int NT, int NKS, int RBS>
__device__ __forceinline__ void mma_span(
    uint32_t ab, uint32_t bb, int kbaseA,
    int ncb, int mg, int lane, uint32_t (*c)[2]) {
  int m = lane >> 3;
  int row = 16 * mg + (m & 1) * 8 + (lane & 7);
  int g = lane >> 3, rr = lane & 7;
  #pragma unroll
  for (int ks = 0; ks < NKS; ks++) {
    int kcolA = kbaseA + ks * 16 + (m >> 1) * 8;
    uint32_t aoff = (uint32_t)((row << 9) + ((((kcolA >> 3) ^ (row & 7))) << 4));
    uint32_t af[4];
    ldm4(af, ab + aoff);
    int kcolB = ks * 16 + (g & 1) * 8;
    #pragma unroll
    for (int nt2 = 0; nt2 < NT / 2; nt2++) {
      int n = ncb + nt2 * 16 + (g >> 1) * 8 + rr;
      uint32_t boff = (uint32_t)((n << RBS) + ((((kcolB >> 3) ^ (n & 7))) << 4));
      uint32_t rb[4];
      ldm4(rb, bb + boff);
      mma_f16h(c[nt2 * 2],     af, rb);
      mma_f16h(c[nt2 * 2 + 1], af, rb + 2);
    }
  }
}

template<int NT>
__device__ __forceinline__ void init_bias_frag(uint32_t (*c)[2], const float* bias, int ncb, int lane) {
  #pragma unroll
  for (int nt = 0; nt < NT; nt++) {
    int cc = ncb + nt * 8 + (lane & 3) * 2;
    uint32_t hp; CVT_H2(hp, bias[cc], bias[cc + 1]);
    c[nt][0] = hp; c[nt][1] = hp;
  }
}

template<int NT>
__device__ __forceinline__ void epi_tanh(uint32_t (*c)[2], uint32_t ab,
                                         int ncb, int mg, int lane) {
  int row = 16 * mg + (lane >> 2);
  #pragma unroll
  for (int nt = 0; nt < NT; nt++) {
    int col = ncb + nt * 8 + (lane & 3) * 2;
    #pragma unroll
    for (int h = 0; h < 2; h++) {
      int rh = row + 8 * h;
      uint32_t t;
      asm("tanh.approx.f16x2 %0, %1;" : "=r"(t) : "r"(c[nt][h]));
      uint32_t off = (uint32_t)((rh << 9) + ((((col >> 3) ^ (rh & 7))) << 4) + ((col & 7) << 1));
      asm volatile("st.shared.b32 [%0], %1;" :: "r"(ab + off), "r"(t) : "memory");
    }
  }
}

// ---------------- templated warp-private stage build ----------------
template<int ST>
__device__ __forceinline__ void build_stage(
    float tst, const float* rat, const float* wts, const float* bts,
    uint32_t ab, int R0, int mg, int ng, int lane) {
  #pragma unroll
  for (int qi = 0; qi < 16; qi++) {
    int q = lane + qi * 32;
    int r = 16 * mg + (q >> 5);
    int k2 = ng * 64 + (q & 31) * 2;
    size_t gi = (size_t)(R0 + r) * Z_D + k2;
    float2 v = *(const float2*)(g_y + gi);
    #pragma unroll
    for (int j = 0; j < ST; j++) {
      uint32_t kp = *(const uint32_t*)(&g_k[j][gi]);
      float2 kk = __half22float2(*reinterpret_cast<__half2*>(&kp));
      float cj = DT_F * cA[ST][j];
      v.x += cj * kk.x; v.y += cj * kk.y;
    }
    float tr = tst * rat[r];
    v.x += __cosf(fmaf(tr, wts[k2], bts[k2]));
    v.y += __cosf(fmaf(tr, wts[k2 + 1], bts[k2 + 1]));
    uint32_t hp; CVT_H2(hp, v.x, v.y);
    uint32_t off = (uint32_t)((r << 9) + ((((k2 >> 3) ^ (r & 7))) << 4) + ((k2 & 7) << 1));
    asm volatile("st.shared.b32 [%0], %1;" :: "r"(ab + off), "r"(hp) : "memory");
  }
}

extern __shared__ char smem_raw[];

#define DO_BLOCK(NT_, NKS_, RBS_, KBASE_, NCB_, CARR_) do { \
  uint32_t bb_ = (blk & 1) ? wb1 : wb0; \
  if (blk & 1) { MBAR_WAIT(mb1, ph1); ph1 ^= 1; } \
  else         { MBAR_WAIT(mb0, ph0); ph0 ^= 1; } \
  mma_span<NT_, NKS_, RBS_>(ab, bb_, KBASE_, NCB_, mg, lane, CARR_); \
  if (lane == 0) MBAR_ARRIVE((blk & 1) ? me1 : me0); \
  if (w == 0 && blk + 2 < 384) { \
    if (blk & 1) { MBAR_WAIT(me1, qe1); qe1 ^= 1; } \
    else         { MBAR_WAIT(me0, qe0); qe0 ^= 1; } \
    if (lane == 0) { \
      uint32_t mbf_ = (blk & 1) ? mb1 : mb0; \
      MBAR_EXPECT(mbf_, 32768); \
      BULK_LOAD(bb_, (const void*)(g_wh + (((blk + 2) & 7) * 16384)), 32768, mbf_); \
    } \
  } \
  blk++; \
} while (0)

__global__ void __launch_bounds__(192, 2) ode_kernel(
    const float* __restrict__ z, const float* __restrict__ ts,
    const float* __restrict__ w_t, const float* __restrict__ b_t,
    const float* __restrict__ b1, const float* __restrict__ b2, const float* __restrict__ b3) {
  const uint32_t base = smem_u32(smem_raw);
  float* b1s = (float*)(smem_raw + SO_B1S);
  float* b2s = (float*)(smem_raw + SO_B2S);
  float* b3s = (float*)(smem_raw + SO_B3S);
  float* wts = (float*)(smem_raw + SO_WTS);
  float* bts = (float*)(smem_raw + SO_BTS);
  float* rat = (float*)(smem_raw + SO_RAT);
  const uint32_t ab = base + SO_A;
  const uint32_t wb0 = base + SO_B0, wb1 = base + SO_B1;
  const uint32_t mb0 = base + SO_MB, mb1 = base + SO_MB + 8;
  const uint32_t me0 = base + SO_MB + 16, me1 = base + SO_MB + 24;
  const int tid = threadIdx.x;
  const int lane = tid & 31, w = tid >> 5;
  const int mg = w >> 1, ng = w & 1;
  const int R0 = blockIdx.x * 48;

  if (tid < 48) rat[tid] = ts[R0 + tid];
  if (tid < 128) {
    wts[tid] = w_t[tid];
    bts[tid] = b_t[tid];
    b3s[tid] = b3[tid];
  }
  for (int i = tid; i < 256; i += 192) { b1s[i] = b1[i]; b2s[i] = b2[i]; }
  if (tid == 0) {
    MBAR_INIT(mb0, 1); MBAR_INIT(mb1, 1);
    MBAR_INIT(me0, 6); MBAR_INIT(me1, 6);
  }
  for (int p = tid; p < 48 * 64; p += 192) {
    int r = p >> 6, k2 = (p & 63) * 2;
    float2 zz = *(const float2*)(z + ((R0 + r) & 63) * Z_D + k2);
    *(float2*)(g_y + (size_t)(R0 + r) * Z_D + k2) = zz;
  }
  __syncthreads();
  if (tid == 0) {
    MBAR_EXPECT(mb0, 32768);
    BULK_LOAD(wb0, (const void*)(g_wh + 0), 32768, mb0);
    MBAR_EXPECT(mb1, 32768);
    BULK_LOAD(wb1, (const void*)(g_wh + 16384), 32768, mb1);
  }

  int blk = 0, ph0 = 0, ph1 = 0, qe0 = 0, qe1 = 0;
  for (int step = 0; step < N_STEPS; step++) {
    float s0 = step * DT_F;
    for (int st = 0; st < 6; st++) {
      float tst = s0 + cC[st] * DT_F;
      switch (st) {
        case 0: build_stage<0>(tst, rat, wts, bts, ab, R0, mg, ng, lane); break;
        case 1: build_stage<1>(tst, rat, wts, bts, ab, R0, mg, ng, lane); break;
        case 2: build_stage<2>(tst, rat, wts, bts, ab, R0, mg, ng, lane); break;
        case 3: build_stage<3>(tst, rat, wts, bts, ab, R0, mg, ng, lane); break;
        case 4: build_stage<4>(tst, rat, wts, bts, ab, R0, mg, ng, lane); break;
        default: build_stage<5>(tst, rat, wts, bts, ab, R0, mg, ng, lane); break;
      }
      PAIR_BAR(mg);
      {
        uint32_t c[16][2];
        init_bias_frag<16>(c, b1s, ng * 128, lane);
        DO_BLOCK(16, 4, 7, 0,  ng * 128, c);
        DO_BLOCK(16, 4, 7, 64, ng * 128, c);
        PAIR_BAR(mg);
        epi_tanh<16>(c, ab, ng * 128, mg, lane);
      }
      PAIR_BAR(mg);
      {
        uint32_t c[16][2];
        init_bias_frag<16>(c, b2s, ng * 128, lane);
        DO_BLOCK(16, 4, 7, 0,   ng * 128, c);
        DO_BLOCK(16, 4, 7, 64,  ng * 128, c);
        DO_BLOCK(16, 4, 7, 128, ng * 128, c);
        DO_BLOCK(16, 4, 7, 192, ng * 128, c);
        PAIR_BAR(mg);
        epi_tanh<16>(c, ab, ng * 128, mg, lane);
      }
      PAIR_BAR(mg);
      {
        uint32_t c[8][2];
        init_bias_frag<8>(c, b3s, ng * 64, lane);
        DO_BLOCK(8, 8, 8, 0,   ng * 64, c);
        DO_BLOCK(8, 8, 8, 128, ng * 64, c);
        int row = 16 * mg + (lane >> 2);
        #pragma unroll
        for (int nt = 0; nt < 8; nt++) {
          int col = ng * 64 + nt * 8 + (lane & 3) * 2;
          #pragma unroll
          for (int h = 0; h < 2; h++) {
            int rr = row + 8 * h;
            float sc = rat[rr];
            uint32_t scp; CVT_H2(scp, sc, sc);
            __half2 prod = __hmul2(*reinterpret_cast<__half2*>(&c[nt][h]),
                                   *reinterpret_cast<__half2*>(&scp));
            *(uint32_t*)(&g_k[st][(size_t)(R0 + rr) * Z_D + col]) =
                *reinterpret_cast<uint32_t*>(&prod);
          }
        }
      }
      PAIR_BAR(mg);
    }
    for (int q = lane; q < 16 * 32; q += 32) {
      int r = 16 * mg + (q >> 5);
      int k2 = ng * 64 + (q & 31) * 2;
      size_t gi = (size_t)(R0 + r) * Z_D + k2;
      float2 y = *(float2*)(g_y + gi);
      const float cw[6] = {35.f/384.f, 0.f, 500.f/1113.f, 125.f/192.f,
                           -2187.f/6784.f, 11.f/84.f};
      #pragma unroll
      for (int j = 0; j < 6; j++) {
        if (j == 1) continue;
        uint32_t kp = *(const uint32_t*)(&g_k[j][gi]);
        float2 kk = __half22float2(*reinterpret_cast<__half2*>(&kp));
        y.x += DT_F * cw[j] * kk.x;
        y.y += DT_F * cw[j] * kk.y;
      }
      *(float2*)(g_y + gi) = y;
    }
  }
}

// ---------------- fused HMMA decode: 64 rows/CTA, x-part broadcast ----------------
__global__ void __launch_bounds__(256, 2) ds_kernel(
    const float* __restrict__ x, const float* __restrict__ bd,
    const float* __restrict__ bs, const float* __restrict__ bdst) {
  const uint32_t base = smem_u32(smem_raw);
  float* xacc = (float*)(smem_raw + DSO_XACC);
  float* xs   = (float*)(smem_raw + DSO_XS);
  float* bbs  = (float*)(smem_raw + DSO_BB);
  const uint32_t ab = base + DSO_A;
  const uint32_t wb0 = base + DSO_B0, wb1 = base + DSO_B1;
  const uint32_t mb0 = base + DSO_MB, mb1 = base + DSO_MB + 8;
  const uint32_t me0 = base + DSO_MB + 16, me1 = base + DSO_MB + 24;
  const int tid = threadIdx.x;
  const int lane = tid & 31, w = tid >> 5;
  const int mg = w >> 1, ng = w & 1;   // mg 0..3 (16 rows), ng 0..1 (128 cols)
  const int R0 = blockIdx.x * 64;
  const int b = R0 >> 6;
  const __half* WB = (R0 < 4096) ? g_wsB : g_wdstB;
  const __half* bsrc[6] = {g_wd2, g_wd2 + 16384, WB, WB + 16384, WB + 32768, WB + 49152};

  for (int i = tid; i < 172; i += 256) xs[i] = x[(size_t)b * 172 + i];
  bbs[tid] = (R0 < 4096) ? bs[tid] : bdst[tid];
  if (tid == 0) {
    MBAR_INIT(mb0, 1); MBAR_INIT(mb1, 1);
    MBAR_INIT(me0, 8); MBAR_INIT(me1, 8);
  }
  // y -> A fp16 swizzled (64 rows x 128 cols)
  for (int p = tid; p < 64 * 64; p += 256) {
    int r = p >> 6, k2 = (p & 63) * 2;
    float2 yy = *(const float2*)(g_y + (size_t)(R0 + r) * Z_D + k2);
    uint32_t hp; CVT_H2(hp, yy.x, yy.y);
    uint32_t off = (uint32_t)((r << 9) + ((((k2 >> 3) ^ (r & 7))) << 4) + ((k2 & 7) << 1));
    asm volatile("st.shared.b32 [%0], %1;" :: "r"(ab + off), "r"(hp) : "memory");
  }
  __syncthreads();
  if (tid == 0) {
    MBAR_EXPECT(mb0, 32768);
    BULK_LOAD(wb0, (const void*)bsrc[0], 32768, mb0);
    MBAR_EXPECT(mb1, 32768);
    BULK_LOAD(wb1, (const void*)bsrc[1], 32768, mb1);
  }
  // broadcast x-part: xacc[n] = bd[n] + sum_k x[k]*Wd[k][n]
  {
    float a0 = bd[tid];
    #pragma unroll 4
    for (int k = 0; k < 172; k++)
      a0 = fmaf(xs[k], __half2float(g_wd1[(size_t)k * 256 + tid]), a0);
    xacc[tid] = a0;
  }
  __syncthreads();

  int blk = 0, ph0 = 0, ph1 = 0, qe0 = 0, qe1 = 0;
  #define DS_BLOCK(KBASE_, CARR_) do { \
    uint32_t bb_ = (blk & 1) ? wb1 : wb0; \
    if (blk & 1) { MBAR_WAIT(mb1, ph1); ph1 ^= 1; } \
    else         { MBAR_WAIT(mb0, ph0); ph0 ^= 1; } \
    mma_span<16, 4, 7>(ab, bb_, KBASE_, ng * 128, mg, lane, CARR_); \
    if (lane == 0) MBAR_ARRIVE((blk & 1) ? me1 : me0); \
    if (w == 0 && blk + 2 < 6) { \
      if (blk & 1) { MBAR_WAIT(me1, qe1); qe1 ^= 1; } \
      else         { MBAR_WAIT(me0, qe0); qe0 ^= 1; } \
      if (lane == 0) { \
        uint32_t mbf_ = (blk & 1) ? mb1 : mb0; \
        MBAR_EXPECT(mbf_, 32768); \
        BULK_LOAD(bb_, (const void*)bsrc[blk + 2], 32768, mbf_); \
      } \
    } \
    blk++; \
  } while (0)

  // GEMM1: h = y @ Wd2 (K=128, blocks 0,1), then += xacc, store to A
  {
    uint32_t c[16][2];
    #pragma unroll
    for (int nt = 0; nt < 16; nt++) { c[nt][0] = 0u; c[nt][1] = 0u; }
    DS_BLOCK(0,  c);
    DS_BLOCK(64, c);
    __syncthreads();               // all warps' A reads done before overwrite
    int row = 16 * mg + (lane >> 2);
    #pragma unroll
    for (int nt = 0; nt < 16; nt++) {
      int col = ng * 128 + nt * 8 + (lane & 3) * 2;
      float2 xa = *(const float2*)(&xacc[col]);
      #pragma unroll
      for (int h = 0; h < 2; h++) {
        int rh = row + 8 * h;
        float2 f = __half22float2(*reinterpret_cast<__half2*>(&c[nt][h]));
        f.x += xa.x; f.y += xa.y;
        uint32_t hp; CVT_H2(hp, f.x, f.y);
        uint32_t off = (uint32_t)((rh << 9) + ((((col >> 3) ^ (rh & 7))) << 4) + ((col & 7) << 1));
        asm volatile("st.shared.b32 [%0], %1;" :: "r"(ab + off), "r"(hp) : "memory");
      }
    }
    __syncthreads();
  }
  // GEMM2: s = h @ W (K=256, blocks 2..5) + bias -> g_s fp32
  {
    uint32_t c[16][2];
    init_bias_frag<16>(c, bbs, ng * 128, lane);
    DS_BLOCK(0,   c);
    DS_BLOCK(64,  c);
    DS_BLOCK(128, c);
    DS_BLOCK(192, c);
    int row = 16 * mg + (lane >> 2);
    #pragma unroll
    for (int nt = 0; nt < 16; nt++) {
      int col = ng * 128 + nt * 8 + (lane & 3) * 2;
      #pragma unroll
      for (int h = 0; h < 2; h++) {
        int rh = row + 8 * h;
        float2 f = __half22float2(*reinterpret_cast<__half2*>(&c[nt][h]));
        *(float2*)(&g_s[(size_t)(R0 + rh) * H_D + col]) = f;
      }
    }
  }
  #undef DS_BLOCK
}

// ---------------- edge out + mean over L ----------------
__global__ void __launch_bounds__(256) edge_kernel(
    const float* __restrict__ Wo, const float* __restrict__ bo, float* __restrict__ out) {
  __shared__ float red[8];
  const int tid = threadIdx.x;
  const int o = blockIdx.x;
  const int b = (o < 64) ? o : (o - 64);
  const size_t off2 = (o < 64) ? (size_t)4096 * H_D : (size_t)8192 * H_D;
  const float wcol = Wo[tid];
  float sum = 0.f;
  for (int l = 0; l < 64; l++) {
    size_t r1 = (size_t)(b * 64 + l) * H_D + tid;
    float v = g_s[r1] + g_s[off2 + r1];
    sum += fmaxf(v, 0.f) * wcol;
  }
  #pragma unroll
  for (int d = 16; d > 0; d >>= 1) sum += __shfl_xor_sync(0xFFFFFFFFu, sum, d);
  if ((tid & 31) == 0) red[tid >> 5] = sum;
  __syncthreads();
  if (tid == 0) {
    float t = 0.f;
    #pragma unroll
    for (int w = 0; w < 8; w++) t += red[w];
    out[o] = t * (1.f / 64.f) + bo[0];
  }
}

extern "C" void kernel_launch(void* const* d_in, const int* in_sizes, int n_in,
                              void* d_out, int out_size) {
  const float* x    = (const float*)d_in[0];
  const float* z    = (const float*)d_in[1];
  const float* ts   = (const float*)d_in[2];
  const float* w_t  = (const float*)d_in[3];
  const float* b_t  = (const float*)d_in[4];
  const float* W1   = (const float*)d_in[5];
  const float* b1   = (const float*)d_in[6];
  const float* W2   = (const float*)d_in[7];
  const float* b2   = (const float*)d_in[8];
  const float* W3   = (const float*)d_in[9];
  const float* b3   = (const float*)d_in[10];
  const float* Wd   = (const float*)d_in[11];
  const float* bd   = (const float*)d_in[12];
  const float* Ws   = (const float*)d_in[13];
  const float* bs   = (const float*)d_in[14];
  const float* Wdst = (const float*)d_in[15];
  const float* bdst = (const float*)d_in[16];
  const float* Wo   = (const float*)d_in[17];
  const float* bo   = (const float*)d_in[18];
  float* out = (float*)d_out;

  cudaFuncSetAttribute(ode_kernel, cudaFuncAttributeMaxDynamicSharedMemorySize, SM_ODE);
  cudaFuncSetAttribute(ds_kernel,  cudaFuncAttributeMaxDynamicSharedMemorySize, SM_DS);

  prep_kernel<<<512, 256>>>(W1, W2, W3);
  prep2_kernel<<<812, 256>>>(Wd, Ws, Wdst);
  ode_kernel<<<256, 192, SM_ODE>>>(z, ts, w_t, b_t, b1, b2, b3);
  ds_kernel<<<192, 256, SM_DS>>>(x, bd, bs, bdst);
  edge_kernel<<<128, 256>>>(Wo, bo, out);
}